// round 4
// baseline (speedup 1.0000x reference)
#include <cuda_runtime.h>
#include <cstdint>
#include <cstddef>

// ---------------- problem constants ----------------
#define BATCH   8
#define T_ENC   1024
#define T_DEC   100
#define DMODEL  512
#define NHEAD   8
#define DHEAD   64
#define DFF     2048
#define M_ENC   (BATCH * T_ENC)   // 8192
#define M_DEC   (BATCH * T_DEC)   // 800
#define BHT     (BATCH * NHEAD)   // 64

// ---------------- scratch (device globals; no allocation allowed) ----------------
__device__ float g_q   [M_ENC * DMODEL];
__device__ float g_k   [M_ENC * DMODEL];
__device__ float g_v   [M_ENC * DMODEL];
__device__ float g_att [M_ENC * DMODEL];
__device__ float g_x1  [M_ENC * DMODEL];
__device__ float g_x   [M_ENC * DMODEL];
__device__ float g_h   [M_ENC * DFF];
__device__ float g_y1  [M_DEC * DMODEL];
__device__ float g_y2  [M_DEC * DMODEL];
__device__ float g_y   [M_DEC * DMODEL];

__device__ __forceinline__ uint32_t f2tf32(float x) {
    uint32_t t;
    asm("cvt.rna.tf32.f32 %0, %1;" : "=r"(t) : "f"(x));
    return t;
}

__device__ __forceinline__ void mma8(float* c, const uint32_t* a, uint32_t b0, uint32_t b1) {
    asm volatile(
        "mma.sync.aligned.m16n8k8.row.col.f32.tf32.tf32.f32 "
        "{%0,%1,%2,%3}, {%4,%5,%6,%7}, {%8,%9}, {%0,%1,%2,%3};"
        : "+f"(c[0]), "+f"(c[1]), "+f"(c[2]), "+f"(c[3])
        : "r"(a[0]), "r"(a[1]), "r"(a[2]), "r"(a[3]), "r"(b0), "r"(b1));
}

__device__ __forceinline__ void cpasync16(uint32_t smem_dst, const void* gsrc, int bytes) {
    asm volatile("cp.async.ca.shared.global [%0], [%1], 16, %2;"
                 :: "r"(smem_dst), "l"(gsrc), "r"(bytes));
}

// ================= 3-stage cp.async tf32 GEMM =================
// C = A(MxK) @ B(KxN) (+bias) (+relu).  BM=BN=128, BK=32, 256 thr, 8 warps.
// N,K multiples of 128/32; only M may be ragged.
#define GA_STRIDE 36     // 32 + 4
#define GB_STRIDE 132    // 128 + 4
#define GA_STAGE  (128 * GA_STRIDE)
#define GB_STAGE  (32 * GB_STRIDE)
#define GEMM_SMEM ((3 * GA_STAGE + 3 * GB_STAGE) * 4)

template<int RELU>
__global__ __launch_bounds__(256)
void mma_gemm(const float* __restrict__ A, const float* __restrict__ B,
              const float* __restrict__ bias, float* __restrict__ C,
              int M, int N, int K)
{
    extern __shared__ float gsm[];
    float* Asf = gsm;
    float* Bsf = gsm + 3 * GA_STAGE;

    const int tid  = threadIdx.x;
    const int wid  = tid >> 5, lane = tid & 31;
    const int wm   = wid & 1, wn = wid >> 1;
    const int g    = lane >> 2, tig = lane & 3;
    const int m0   = blockIdx.y * 128, n0 = blockIdx.x * 128;

    const uint32_t aBase = (uint32_t)__cvta_generic_to_shared(Asf);
    const uint32_t bBase = (uint32_t)__cvta_generic_to_shared(Bsf);

    float acc[4][4][4];
    #pragma unroll
    for (int i = 0; i < 4; i++)
        #pragma unroll
        for (int j = 0; j < 4; j++)
            #pragma unroll
            for (int c = 0; c < 4; c++) acc[i][j][c] = 0.f;

    auto issue = [&](int s, int k0) {
        #pragma unroll
        for (int i = 0; i < 4; i++) {
            int idx = tid + (i << 8);
            int r = idx >> 3, kk4 = (idx & 7) << 2;
            int m = m0 + r;
            const float* src = A + (size_t)(m < M ? m : 0) * K + k0 + kk4;
            cpasync16(aBase + (s * GA_STAGE + r * GA_STRIDE + kk4) * 4, src, (m < M) ? 16 : 0);
        }
        #pragma unroll
        for (int i = 0; i < 4; i++) {
            int idx = tid + (i << 8);
            int kk = idx >> 5, n4 = (idx & 31) << 2;
            const float* src = B + (size_t)(k0 + kk) * N + n0 + n4;
            cpasync16(bBase + (s * GB_STAGE + kk * GB_STRIDE + n4) * 4, src, 16);
        }
        asm volatile("cp.async.commit_group;");
    };

    const int nk = K >> 5;
    issue(0, 0);
    if (nk > 1) issue(1, 32);

    int s = 0;
    for (int kt = 0; kt < nk; kt++) {
        if (kt + 2 < nk) {
            int s2 = s + 2; if (s2 >= 3) s2 -= 3;
            issue(s2, (kt + 2) << 5);
            asm volatile("cp.async.wait_group 2;");
        } else if (kt + 1 < nk) {
            asm volatile("cp.async.wait_group 1;");
        } else {
            asm volatile("cp.async.wait_group 0;");
        }
        __syncthreads();

        const float* As = Asf + s * GA_STAGE;
        const float* Bs = Bsf + s * GB_STAGE;
        #pragma unroll
        for (int ks = 0; ks < 32; ks += 8) {
            uint32_t af[4][4];
            #pragma unroll
            for (int mi = 0; mi < 4; mi++) {
                int mr = wm * 64 + mi * 16;
                af[mi][0] = f2tf32(As[(mr + g    ) * GA_STRIDE + ks + tig    ]);
                af[mi][1] = f2tf32(As[(mr + g + 8) * GA_STRIDE + ks + tig    ]);
                af[mi][2] = f2tf32(As[(mr + g    ) * GA_STRIDE + ks + tig + 4]);
                af[mi][3] = f2tf32(As[(mr + g + 8) * GA_STRIDE + ks + tig + 4]);
            }
            uint32_t bf[4][2];
            #pragma unroll
            for (int ni = 0; ni < 4; ni++) {
                int nc = wn * 32 + ni * 8 + g;
                bf[ni][0] = f2tf32(Bs[(ks + tig    ) * GB_STRIDE + nc]);
                bf[ni][1] = f2tf32(Bs[(ks + tig + 4) * GB_STRIDE + nc]);
            }
            #pragma unroll
            for (int mi = 0; mi < 4; mi++)
                #pragma unroll
                for (int ni = 0; ni < 4; ni++)
                    mma8(acc[mi][ni], af[mi], bf[ni][0], bf[ni][1]);
        }
        __syncthreads();
        if (++s >= 3) s -= 3;
    }

    #pragma unroll
    for (int mi = 0; mi < 4; mi++) {
        int mb = m0 + wm * 64 + mi * 16;
        #pragma unroll
        for (int ni = 0; ni < 4; ni++) {
            int nb = n0 + wn * 32 + ni * 8 + 2 * tig;
            #pragma unroll
            for (int half = 0; half < 2; half++) {
                int m = mb + g + half * 8;
                if (m < M) {
                    float v0 = acc[mi][ni][half * 2    ];
                    float v1 = acc[mi][ni][half * 2 + 1];
                    if (bias) { v0 += bias[nb]; v1 += bias[nb + 1]; }
                    if (RELU) { v0 = fmaxf(v0, 0.f); v1 = fmaxf(v1, 0.f); }
                    *(float2*)(C + (size_t)m * N + nb) = make_float2(v0, v1);
                }
            }
        }
    }
}

// ================= fused flash attention (non-causal, exact) =================
// Per CTA: 128 q-rows x full head. 256 threads = 8 warps, 16 q-rows/warp.
// cp.async double-buffered 64-row KV tiles (raw fp32; tf32 cvt at fragment load).
// scale folded into Q at load (0.125 = exact pow2, bit-identical). Tk % 64 == 0.
#define FQ_STRIDE 68
#define FKV_STAGE (64 * FQ_STRIDE)
#define FLASH_SMEM ((128 * FQ_STRIDE + 4 * FKV_STAGE + 128 * FQ_STRIDE) * 4)

__global__ __launch_bounds__(256)
void flash_attn(const float* __restrict__ Qg, const float* __restrict__ Kg,
                const float* __restrict__ Vg, float* __restrict__ Og,
                int Tq, int Tk, float scale)
{
    extern __shared__ float fsm[];
    uint32_t* Qs = (uint32_t*)fsm;                 // [128][68] tf32
    float* Kraw  = fsm + 128 * FQ_STRIDE;          // 2 stages x [64][68] raw fp32
    float* Vraw  = Kraw + 2 * FKV_STAGE;           // 2 stages x [64][68]
    uint32_t* Ps = (uint32_t*)(Vraw + 2 * FKV_STAGE);  // [128][68] tf32

    const int bh = blockIdx.y;
    const int b = bh >> 3, h = bh & 7;
    const int q0 = blockIdx.x * 128;
    const int tid = threadIdx.x;
    const int wid = tid >> 5, lane = tid & 31;
    const int g = lane >> 2, tig = lane & 3;
    const int mr = wid * 16;

    const float* qp = Qg + (size_t)b * Tq * DMODEL + h * DHEAD;
    const float* kp = Kg + (size_t)b * Tk * DMODEL + h * DHEAD;
    const float* vp = Vg + (size_t)b * Tk * DMODEL + h * DHEAD;

    const uint32_t kBase = (uint32_t)__cvta_generic_to_shared(Kraw);
    const uint32_t vBase = (uint32_t)__cvta_generic_to_shared(Vraw);

    auto issueKV = [&](int s, int kt) {
        #pragma unroll
        for (int i = 0; i < 4; i++) {
            int idx = tid + (i << 8);
            int r = idx >> 4, d4 = (idx & 15) << 2;
            cpasync16(kBase + (s * FKV_STAGE + r * FQ_STRIDE + d4) * 4,
                      kp + (size_t)(kt + r) * DMODEL + d4, 16);
            cpasync16(vBase + (s * FKV_STAGE + r * FQ_STRIDE + d4) * 4,
                      vp + (size_t)(kt + r) * DMODEL + d4, 16);
        }
        asm volatile("cp.async.commit_group;");
    };

    // prefetch tile 0, then load+scale+convert Q
    issueKV(0, 0);
    #pragma unroll
    for (int i = 0; i < 8; i++) {
        int idx = tid + (i << 8);
        int r = idx >> 4, d4 = (idx & 15) << 2;
        int q = q0 + r;
        float4 v = (q < Tq) ? *(const float4*)(qp + (size_t)q * DMODEL + d4)
                            : make_float4(0.f, 0.f, 0.f, 0.f);
        uint32_t* dst = &Qs[r * FQ_STRIDE + d4];
        dst[0] = f2tf32(v.x * scale); dst[1] = f2tf32(v.y * scale);
        dst[2] = f2tf32(v.z * scale); dst[3] = f2tf32(v.w * scale);
    }

    float o[8][4];
    #pragma unroll
    for (int ni = 0; ni < 8; ni++)
        #pragma unroll
        for (int c = 0; c < 4; c++) o[ni][c] = 0.f;
    float m0 = -1e30f, m1 = -1e30f, l0 = 0.f, l1 = 0.f;

    const int nt = Tk >> 6;
    for (int kt = 0; kt < nt; kt++) {
        const int s = kt & 1;
        if (kt + 1 < nt) {
            issueKV(s ^ 1, (kt + 1) << 6);
            asm volatile("cp.async.wait_group 1;");
        } else {
            asm volatile("cp.async.wait_group 0;");
        }
        __syncthreads();

        const float* Ks = Kraw + s * FKV_STAGE;
        const float* Vs = Vraw + s * FKV_STAGE;

        // ---- S = (scale*Q) @ K^T ----
        float sfr[8][4];
        #pragma unroll
        for (int ni = 0; ni < 8; ni++)
            #pragma unroll
            for (int c = 0; c < 4; c++) sfr[ni][c] = 0.f;
        #pragma unroll
        for (int ks = 0; ks < 64; ks += 8) {
            uint32_t af[4];
            af[0] = Qs[(mr + g    ) * FQ_STRIDE + ks + tig    ];
            af[1] = Qs[(mr + g + 8) * FQ_STRIDE + ks + tig    ];
            af[2] = Qs[(mr + g    ) * FQ_STRIDE + ks + tig + 4];
            af[3] = Qs[(mr + g + 8) * FQ_STRIDE + ks + tig + 4];
            #pragma unroll
            for (int ni = 0; ni < 8; ni++) {
                uint32_t b0 = f2tf32(Ks[(ni * 8 + g) * FQ_STRIDE + ks + tig    ]);
                uint32_t b1 = f2tf32(Ks[(ni * 8 + g) * FQ_STRIDE + ks + tig + 4]);
                mma8(sfr[ni], af, b0, b1);
            }
        }

        // ---- online softmax ----
        float tmax0 = -1e30f, tmax1 = -1e30f;
        #pragma unroll
        for (int ni = 0; ni < 8; ni++) {
            tmax0 = fmaxf(tmax0, fmaxf(sfr[ni][0], sfr[ni][1]));
            tmax1 = fmaxf(tmax1, fmaxf(sfr[ni][2], sfr[ni][3]));
        }
        #pragma unroll
        for (int off = 1; off <= 2; off <<= 1) {
            tmax0 = fmaxf(tmax0, __shfl_xor_sync(0xffffffffu, tmax0, off));
            tmax1 = fmaxf(tmax1, __shfl_xor_sync(0xffffffffu, tmax1, off));
        }
        const float mn0 = fmaxf(m0, tmax0), mn1 = fmaxf(m1, tmax1);
        const float a0 = __expf(m0 - mn0), a1 = __expf(m1 - mn1);
        float rs0 = 0.f, rs1 = 0.f;
        #pragma unroll
        for (int ni = 0; ni < 8; ni++) {
            float p0 = __expf(sfr[ni][0] - mn0);
            float p1 = __expf(sfr[ni][1] - mn0);
            float p2 = __expf(sfr[ni][2] - mn1);
            float p3 = __expf(sfr[ni][3] - mn1);
            rs0 += p0 + p1; rs1 += p2 + p3;
            int col = ni * 8 + 2 * tig;
            Ps[(mr + g    ) * FQ_STRIDE + col    ] = f2tf32(p0);
            Ps[(mr + g    ) * FQ_STRIDE + col + 1] = f2tf32(p1);
            Ps[(mr + g + 8) * FQ_STRIDE + col    ] = f2tf32(p2);
            Ps[(mr + g + 8) * FQ_STRIDE + col + 1] = f2tf32(p3);
        }
        #pragma unroll
        for (int off = 1; off <= 2; off <<= 1) {
            rs0 += __shfl_xor_sync(0xffffffffu, rs0, off);
            rs1 += __shfl_xor_sync(0xffffffffu, rs1, off);
        }
        l0 = l0 * a0 + rs0; l1 = l1 * a1 + rs1;
        m0 = mn0; m1 = mn1;
        #pragma unroll
        for (int ni = 0; ni < 8; ni++) {
            o[ni][0] *= a0; o[ni][1] *= a0;
            o[ni][2] *= a1; o[ni][3] *= a1;
        }
        __syncwarp();

        // ---- O += P @ V ----
        #pragma unroll
        for (int ks = 0; ks < 64; ks += 8) {
            uint32_t af[4];
            af[0] = Ps[(mr + g    ) * FQ_STRIDE + ks + tig    ];
            af[1] = Ps[(mr + g + 8) * FQ_STRIDE + ks + tig    ];
            af[2] = Ps[(mr + g    ) * FQ_STRIDE + ks + tig + 4];
            af[3] = Ps[(mr + g + 8) * FQ_STRIDE + ks + tig + 4];
            #pragma unroll
            for (int ni = 0; ni < 8; ni++) {
                uint32_t b0 = f2tf32(Vs[(ks + tig    ) * FQ_STRIDE + ni * 8 + g]);
                uint32_t b1 = f2tf32(Vs[(ks + tig + 4) * FQ_STRIDE + ni * 8 + g]);
                mma8(o[ni], af, b0, b1);
            }
        }
        __syncthreads();
    }

    // ---- epilogue: normalize + store (float2) ----
    const float i0 = 1.f / l0, i1 = 1.f / l1;
    #pragma unroll
    for (int ni = 0; ni < 8; ni++) {
        int col = h * DHEAD + ni * 8 + 2 * tig;
        int r0 = q0 + mr + g, r1 = r0 + 8;
        if (r0 < Tq)
            *(float2*)(Og + (size_t)(b * Tq + r0) * DMODEL + col) =
                make_float2(o[ni][0] * i0, o[ni][1] * i0);
        if (r1 < Tq)
            *(float2*)(Og + (size_t)(b * Tq + r1) * DMODEL + col) =
                make_float2(o[ni][2] * i1, o[ni][3] * i1);
    }
}

// ================= fused decoder self-attention (exact fp32) =================
// One CTA per (b,h). Q/K/V (100x64) + S (100x100) in smem. Full-row softmax
// first, THEN causal fill of -1e10 (faithful to reference), then P@V.
#define DS_STRIDE 68
#define DS_SSTRIDE 104
#define DEC_SMEM ((3 * T_DEC * DS_STRIDE + T_DEC * DS_SSTRIDE) * 4)

__global__ __launch_bounds__(256)
void dec_self_attn(const float* __restrict__ Qg, const float* __restrict__ Kg,
                   const float* __restrict__ Vg, float* __restrict__ Og)
{
    extern __shared__ float dsm[];
    float* Qd = dsm;
    float* Kd = Qd + T_DEC * DS_STRIDE;
    float* Vd = Kd + T_DEC * DS_STRIDE;
    float* Sd = Vd + T_DEC * DS_STRIDE;

    const int bh = blockIdx.x;
    const int b = bh >> 3, h = bh & 7;
    const int tid = threadIdx.x;
    const int wid = tid >> 5, lane = tid & 31;

    const float* qp = Qg + (size_t)b * T_DEC * DMODEL + h * DHEAD;
    const float* kp = Kg + (size_t)b * T_DEC * DMODEL + h * DHEAD;
    const float* vp = Vg + (size_t)b * T_DEC * DMODEL + h * DHEAD;

    // load Q, K, V (100 x 64) as float4
    for (int idx = tid; idx < T_DEC * 16; idx += 256) {
        int r = idx >> 4, d4 = (idx & 15) << 2;
        *(float4*)&Qd[r * DS_STRIDE + d4] = *(const float4*)(qp + (size_t)r * DMODEL + d4);
        *(float4*)&Kd[r * DS_STRIDE + d4] = *(const float4*)(kp + (size_t)r * DMODEL + d4);
        *(float4*)&Vd[r * DS_STRIDE + d4] = *(const float4*)(vp + (size_t)r * DMODEL + d4);
    }
    __syncthreads();

    // S = scale * Q @ K^T
    for (int e = tid; e < T_DEC * T_DEC; e += 256) {
        int q = e / T_DEC, kk = e - q * T_DEC;
        const float* qr = &Qd[q * DS_STRIDE];
        const float* kr = &Kd[kk * DS_STRIDE];
        float acc = 0.f;
        #pragma unroll
        for (int d = 0; d < 64; d++) acc += qr[d] * kr[d];
        Sd[q * DS_SSTRIDE + kk] = acc * 0.125f;
    }
    __syncthreads();

    // per-row softmax over all 100 cols, then fill k>q with -1e10
    for (int q = wid; q < T_DEC; q += 8) {
        float* row = &Sd[q * DS_SSTRIDE];
        float r0 = (lane      < T_DEC) ? row[lane]      : -1e30f;
        float r1 = (lane + 32 < T_DEC) ? row[lane + 32] : -1e30f;
        float r2 = (lane + 64 < T_DEC) ? row[lane + 64] : -1e30f;
        float r3 = (lane + 96 < T_DEC) ? row[lane + 96] : -1e30f;
        float m = fmaxf(fmaxf(r0, r1), fmaxf(r2, r3));
        #pragma unroll
        for (int off = 16; off; off >>= 1) m = fmaxf(m, __shfl_xor_sync(0xffffffffu, m, off));
        float e0 = expf(r0 - m), e1 = expf(r1 - m), e2 = expf(r2 - m), e3 = expf(r3 - m);
        if (lane      >= T_DEC) e0 = 0.f;
        if (lane + 32 >= T_DEC) e1 = 0.f;
        if (lane + 64 >= T_DEC) e2 = 0.f;
        if (lane + 96 >= T_DEC) e3 = 0.f;
        float s = e0 + e1 + e2 + e3;
        #pragma unroll
        for (int off = 16; off; off >>= 1) s += __shfl_xor_sync(0xffffffffu, s, off);
        const float inv = 1.f / s;
        if (lane      < T_DEC) row[lane]      = (lane      > q) ? -1e10f : e0 * inv;
        if (lane + 32 < T_DEC) row[lane + 32] = (lane + 32 > q) ? -1e10f : e1 * inv;
        if (lane + 64 < T_DEC) row[lane + 64] = (lane + 64 > q) ? -1e10f : e2 * inv;
        if (lane + 96 < T_DEC) row[lane + 96] = (lane + 96 > q) ? -1e10f : e3 * inv;
    }
    __syncthreads();

    // O = P @ V
    for (int e = tid; e < T_DEC * 64; e += 256) {
        int q = e >> 6, d = e & 63;
        const float* pr = &Sd[q * DS_SSTRIDE];
        float acc = 0.f;
        #pragma unroll 4
        for (int kk = 0; kk < T_DEC; kk++) acc += pr[kk] * Vd[kk * DS_STRIDE + d];
        Og[(size_t)(b * T_DEC + q) * DMODEL + h * DHEAD + d] = acc;
    }
}

// ---------------- fused residual + LayerNorm over D=512 ----------------
__global__ void ln_res_kernel(const float* __restrict__ A, const float* __restrict__ Bv,
                              const float* __restrict__ g, const float* __restrict__ be,
                              float* __restrict__ O) {
    const int row = blockIdx.x;
    const float* a = A + (size_t)row * DMODEL;
    const float* b = Bv + (size_t)row * DMODEL;
    __shared__ float red[256];
    const int tid = threadIdx.x;

    float v0 = a[tid] + b[tid];
    float v1 = a[tid + 256] + b[tid + 256];

    red[tid] = v0 + v1; __syncthreads();
    for (int s = 128; s > 0; s >>= 1) { if (tid < s) red[tid] += red[tid + s]; __syncthreads(); }
    const float mean = red[0] * (1.f / DMODEL); __syncthreads();

    float d0 = v0 - mean, d1 = v1 - mean;
    red[tid] = d0 * d0 + d1 * d1; __syncthreads();
    for (int s = 128; s > 0; s >>= 1) { if (tid < s) red[tid] += red[tid + s]; __syncthreads(); }
    const float inv = rsqrtf(red[0] * (1.f / DMODEL) + 1e-5f);

    O[(size_t)row * DMODEL + tid]       = d0 * inv * g[tid]       + be[tid];
    O[(size_t)row * DMODEL + tid + 256] = d1 * inv * g[tid + 256] + be[tid + 256];
}

// ---------------- host orchestration ----------------
static inline void mgemm(const float* A, const float* B, const float* bias, float* C,
                         int M, int N, int K, int relu) {
    dim3 grid(N / 128, (M + 127) / 128);
    if (relu)
        mma_gemm<1><<<grid, 256, GEMM_SMEM>>>(A, B, bias, C, M, N, K);
    else
        mma_gemm<0><<<grid, 256, GEMM_SMEM>>>(A, B, bias, C, M, N, K);
}

template <typename T>
static inline float* sym(T& s) {
    void* p = nullptr;
    cudaGetSymbolAddress(&p, s);
    return (float*)p;
}

extern "C" void kernel_launch(void* const* d_in, const int* in_sizes, int n_in,
                              void* d_out, int out_size) {
    (void)in_sizes; (void)n_in; (void)out_size;

    cudaFuncSetAttribute(mma_gemm<0>, cudaFuncAttributeMaxDynamicSharedMemorySize, GEMM_SMEM);
    cudaFuncSetAttribute(mma_gemm<1>, cudaFuncAttributeMaxDynamicSharedMemorySize, GEMM_SMEM);
    cudaFuncSetAttribute(flash_attn, cudaFuncAttributeMaxDynamicSharedMemorySize, FLASH_SMEM);
    cudaFuncSetAttribute(dec_self_attn, cudaFuncAttributeMaxDynamicSharedMemorySize, DEC_SMEM);

    const float* x_in      = (const float*)d_in[0];
    const float* y_in      = (const float*)d_in[1];
    const float* enc_Wq    = (const float*)d_in[2];
    const float* enc_Wk    = (const float*)d_in[3];
    const float* enc_Wv    = (const float*)d_in[4];
    const float* enc_ff_w1 = (const float*)d_in[5];
    const float* enc_ff_b1 = (const float*)d_in[6];
    const float* enc_ff_w2 = (const float*)d_in[7];
    const float* enc_ff_b2 = (const float*)d_in[8];
    const float* enc_ln1_g = (const float*)d_in[9];
    const float* enc_ln1_b = (const float*)d_in[10];
    const float* enc_ln2_g = (const float*)d_in[11];
    const float* enc_ln2_b = (const float*)d_in[12];
    const float* dec_Wq1   = (const float*)d_in[13];
    const float* dec_Wk1   = (const float*)d_in[14];
    const float* dec_Wv1   = (const float*)d_in[15];
    const float* dec_Wq2   = (const float*)d_in[16];
    const float* dec_Wk2   = (const float*)d_in[17];
    const float* dec_Wv2   = (const float*)d_in[18];
    const float* dec_ff_w1 = (const float*)d_in[19];
    const float* dec_ff_b1 = (const float*)d_in[20];
    const float* dec_ff_w2 = (const float*)d_in[21];
    const float* dec_ff_b2 = (const float*)d_in[22];
    const float* dec_ln1_g = (const float*)d_in[23];
    const float* dec_ln1_b = (const float*)d_in[24];
    const float* dec_ln2_g = (const float*)d_in[25];
    const float* dec_ln2_b = (const float*)d_in[26];
    const float* dec_ln3_g = (const float*)d_in[27];
    const float* dec_ln3_b = (const float*)d_in[28];

    float* q   = sym(g_q);
    float* k   = sym(g_k);
    float* v   = sym(g_v);
    float* att = sym(g_att);
    float* x1  = sym(g_x1);
    float* gx  = sym(g_x);
    float* h   = sym(g_h);
    float* y1  = sym(g_y1);
    float* y2  = sym(g_y2);
    float* gy  = sym(g_y);

    const float scale = 0.125f;  // 1/sqrt(64), exact power of 2
    const long long WO = DMODEL * DMODEL;
    const long long FO1 = DMODEL * DFF;
    const long long FO2 = DFF * DMODEL;

    // -------- encoder --------
    const float* xc = x_in;
    for (int i = 0; i < 2; i++) {
        mgemm(xc, enc_Wq + i * WO, nullptr, q, M_ENC, DMODEL, DMODEL, 0);
        mgemm(xc, enc_Wk + i * WO, nullptr, k, M_ENC, DMODEL, DMODEL, 0);
        mgemm(xc, enc_Wv + i * WO, nullptr, v, M_ENC, DMODEL, DMODEL, 0);
        flash_attn<<<dim3(T_ENC / 128, BHT), 256, FLASH_SMEM>>>(q, k, v, att, T_ENC, T_ENC, scale);
        ln_res_kernel<<<M_ENC, 256>>>(xc, att, enc_ln1_g + i * DMODEL, enc_ln1_b + i * DMODEL, x1);
        mgemm(x1, enc_ff_w1 + i * FO1, enc_ff_b1 + i * DFF, h, M_ENC, DFF, DMODEL, 1);
        mgemm(h, enc_ff_w2 + i * FO2, enc_ff_b2 + i * DMODEL, att, M_ENC, DMODEL, DFF, 0);
        ln_res_kernel<<<M_ENC, 256>>>(x1, att, enc_ln2_g + i * DMODEL, enc_ln2_b + i * DMODEL, gx);
        xc = gx;
    }

    // -------- decoder --------
    const float* yc = y_in;
    for (int i = 0; i < 2; i++) {
        // masked self-attention: exact fp32 fused path (post-softmax -1e10 fill)
        mgemm(yc, dec_Wq1 + i * WO, nullptr, q, M_DEC, DMODEL, DMODEL, 0);
        mgemm(yc, dec_Wk1 + i * WO, nullptr, k, M_DEC, DMODEL, DMODEL, 0);
        mgemm(yc, dec_Wv1 + i * WO, nullptr, v, M_DEC, DMODEL, DMODEL, 0);
        dec_self_attn<<<BHT, 256, DEC_SMEM>>>(q, k, v, att);
        ln_res_kernel<<<M_DEC, 256>>>(yc, att, dec_ln1_g + i * DMODEL, dec_ln1_b + i * DMODEL, y1);

        // cross-attention (non-causal -> flash)
        mgemm(y1, dec_Wq2 + i * WO, nullptr, q, M_DEC, DMODEL, DMODEL, 0);
        mgemm(xc, dec_Wk2 + i * WO, nullptr, k, M_ENC, DMODEL, DMODEL, 0);
        mgemm(xc, dec_Wv2 + i * WO, nullptr, v, M_ENC, DMODEL, DMODEL, 0);
        flash_attn<<<dim3(1, BHT), 256, FLASH_SMEM>>>(q, k, v, att, T_DEC, T_ENC, scale);
        ln_res_kernel<<<M_DEC, 256>>>(y1, att, dec_ln2_g + i * DMODEL, dec_ln2_b + i * DMODEL, y2);

        // feed-forward
        mgemm(y2, dec_ff_w1 + i * FO1, dec_ff_b1 + i * DFF, h, M_DEC, DFF, DMODEL, 1);
        mgemm(h, dec_ff_w2 + i * FO2, dec_ff_b2 + i * DMODEL, att, M_DEC, DMODEL, DFF, 0);
        float* outp = (i == 1) ? (float*)d_out : gy;
        ln_res_kernel<<<M_DEC, 256>>>(y2, att, dec_ln3_g + i * DMODEL, dec_ln3_b + i * DMODEL, outp);
        yc = gy;
    }
}

// round 5
// speedup vs baseline: 1.1363x; 1.1363x over previous
#include <cuda_runtime.h>
#include <cstdint>
#include <cstddef>

// ---------------- problem constants ----------------
#define BATCH   8
#define T_ENC   1024
#define T_DEC   100
#define DMODEL  512
#define NHEAD   8
#define DHEAD   64
#define DFF     2048
#define M_ENC   (BATCH * T_ENC)   // 8192
#define M_DEC   (BATCH * T_DEC)   // 800
#define BHT     (BATCH * NHEAD)   // 64

// ---------------- scratch (device globals; no allocation allowed) ----------------
__device__ float g_q   [M_ENC * DMODEL];
__device__ float g_k   [M_ENC * DMODEL];
__device__ float g_v   [M_ENC * DMODEL];
__device__ float g_att [M_ENC * DMODEL];
__device__ float g_x1  [M_ENC * DMODEL];
__device__ float g_x   [M_ENC * DMODEL];
__device__ float g_h   [M_ENC * DFF];
__device__ float g_y1  [M_DEC * DMODEL];
__device__ float g_y2  [M_DEC * DMODEL];
__device__ float g_y   [M_DEC * DMODEL];

__device__ __forceinline__ uint32_t f2tf32(float x) {
    uint32_t t;
    asm("cvt.rna.tf32.f32 %0, %1;" : "=r"(t) : "f"(x));
    return t;
}

__device__ __forceinline__ void mma8(float* c, const uint32_t* a, uint32_t b0, uint32_t b1) {
    asm volatile(
        "mma.sync.aligned.m16n8k8.row.col.f32.tf32.tf32.f32 "
        "{%0,%1,%2,%3}, {%4,%5,%6,%7}, {%8,%9}, {%0,%1,%2,%3};"
        : "+f"(c[0]), "+f"(c[1]), "+f"(c[2]), "+f"(c[3])
        : "r"(a[0]), "r"(a[1]), "r"(a[2]), "r"(a[3]), "r"(b0), "r"(b1));
}

__device__ __forceinline__ void cpasync16(uint32_t smem_dst, const void* gsrc, int bytes) {
    asm volatile("cp.async.ca.shared.global [%0], [%1], 16, %2;"
                 :: "r"(smem_dst), "l"(gsrc), "r"(bytes));
}

// ================= 2-stage cp.async tf32 GEMM (3 CTAs/SM) =================
// C = A(MxK) @ B(KxN) (+bias) (+relu).  BM=BN=128, BK=32, 256 thr, 8 warps.
// N,K multiples of 128/32; only M may be ragged.
#define GA_STRIDE 36     // 32 + 4
#define GB_STRIDE 132    // 128 + 4
#define GA_STAGE  (128 * GA_STRIDE)
#define GB_STAGE  (32 * GB_STRIDE)
#define GEMM_SMEM ((2 * GA_STAGE + 2 * GB_STAGE) * 4)

template<int RELU>
__global__ __launch_bounds__(256)
void mma_gemm(const float* __restrict__ A, const float* __restrict__ B,
              const float* __restrict__ bias, float* __restrict__ C,
              int M, int N, int K)
{
    extern __shared__ float gsm[];
    float* Asf = gsm;
    float* Bsf = gsm + 2 * GA_STAGE;

    const int tid  = threadIdx.x;
    const int wid  = tid >> 5, lane = tid & 31;
    const int wm   = wid & 1, wn = wid >> 1;
    const int g    = lane >> 2, tig = lane & 3;
    const int m0   = blockIdx.y * 128, n0 = blockIdx.x * 128;

    const uint32_t aBase = (uint32_t)__cvta_generic_to_shared(Asf);
    const uint32_t bBase = (uint32_t)__cvta_generic_to_shared(Bsf);

    float acc[4][4][4];
    #pragma unroll
    for (int i = 0; i < 4; i++)
        #pragma unroll
        for (int j = 0; j < 4; j++)
            #pragma unroll
            for (int c = 0; c < 4; c++) acc[i][j][c] = 0.f;

    auto issue = [&](int s, int k0) {
        #pragma unroll
        for (int i = 0; i < 4; i++) {
            int idx = tid + (i << 8);
            int r = idx >> 3, kk4 = (idx & 7) << 2;
            int m = m0 + r;
            const float* src = A + (size_t)(m < M ? m : 0) * K + k0 + kk4;
            cpasync16(aBase + (s * GA_STAGE + r * GA_STRIDE + kk4) * 4, src, (m < M) ? 16 : 0);
        }
        #pragma unroll
        for (int i = 0; i < 4; i++) {
            int idx = tid + (i << 8);
            int kk = idx >> 5, n4 = (idx & 31) << 2;
            const float* src = B + (size_t)(k0 + kk) * N + n0 + n4;
            cpasync16(bBase + (s * GB_STAGE + kk * GB_STRIDE + n4) * 4, src, 16);
        }
        asm volatile("cp.async.commit_group;");
    };

    const int nk = K >> 5;
    issue(0, 0);

    for (int kt = 0; kt < nk; kt++) {
        const int s = kt & 1;
        if (kt + 1 < nk) {
            issue(s ^ 1, (kt + 1) << 5);
            asm volatile("cp.async.wait_group 1;");
        } else {
            asm volatile("cp.async.wait_group 0;");
        }
        __syncthreads();

        const float* As = Asf + s * GA_STAGE;
        const float* Bs = Bsf + s * GB_STAGE;
        #pragma unroll
        for (int ks = 0; ks < 32; ks += 8) {
            uint32_t af[4][4];
            #pragma unroll
            for (int mi = 0; mi < 4; mi++) {
                int mr = wm * 64 + mi * 16;
                af[mi][0] = f2tf32(As[(mr + g    ) * GA_STRIDE + ks + tig    ]);
                af[mi][1] = f2tf32(As[(mr + g + 8) * GA_STRIDE + ks + tig    ]);
                af[mi][2] = f2tf32(As[(mr + g    ) * GA_STRIDE + ks + tig + 4]);
                af[mi][3] = f2tf32(As[(mr + g + 8) * GA_STRIDE + ks + tig + 4]);
            }
            uint32_t bf[4][2];
            #pragma unroll
            for (int ni = 0; ni < 4; ni++) {
                int nc = wn * 32 + ni * 8 + g;
                bf[ni][0] = f2tf32(Bs[(ks + tig    ) * GB_STRIDE + nc]);
                bf[ni][1] = f2tf32(Bs[(ks + tig + 4) * GB_STRIDE + nc]);
            }
            #pragma unroll
            for (int mi = 0; mi < 4; mi++)
                #pragma unroll
                for (int ni = 0; ni < 4; ni++)
                    mma8(acc[mi][ni], af[mi], bf[ni][0], bf[ni][1]);
        }
        __syncthreads();
    }

    #pragma unroll
    for (int mi = 0; mi < 4; mi++) {
        int mb = m0 + wm * 64 + mi * 16;
        #pragma unroll
        for (int ni = 0; ni < 4; ni++) {
            int nb = n0 + wn * 32 + ni * 8 + 2 * tig;
            #pragma unroll
            for (int half = 0; half < 2; half++) {
                int m = mb + g + half * 8;
                if (m < M) {
                    float v0 = acc[mi][ni][half * 2    ];
                    float v1 = acc[mi][ni][half * 2 + 1];
                    if (bias) { v0 += bias[nb]; v1 += bias[nb + 1]; }
                    if (RELU) { v0 = fmaxf(v0, 0.f); v1 = fmaxf(v1, 0.f); }
                    *(float2*)(C + (size_t)m * N + nb) = make_float2(v0, v1);
                }
            }
        }
    }
}

// ================= fused flash attention (non-causal, exact) =================
// Per CTA: 128 q-rows x full head. 256 threads = 8 warps, 16 q-rows/warp.
// cp.async double-buffered 64-row KV tiles; P kept in registers and moved to
// the mma A-fragment layout via quad shuffles (no P smem buffer -> 102KB smem,
// 2 CTAs/SM with full double buffering). Tk % 64 == 0.
#define FQ_STRIDE 68
#define FKV_STAGE (64 * FQ_STRIDE)
#define FLASH_SMEM ((128 * FQ_STRIDE + 4 * FKV_STAGE) * 4)

__global__ __launch_bounds__(256, 2)
void flash_attn(const float* __restrict__ Qg, const float* __restrict__ Kg,
                const float* __restrict__ Vg, float* __restrict__ Og,
                int Tq, int Tk, float scale)
{
    extern __shared__ float fsm[];
    uint32_t* Qs = (uint32_t*)fsm;                 // [128][68] tf32
    float* Kraw  = fsm + 128 * FQ_STRIDE;          // 2 stages x [64][68] raw fp32
    float* Vraw  = Kraw + 2 * FKV_STAGE;           // 2 stages x [64][68]

    const int bh = blockIdx.y;
    const int b = bh >> 3, h = bh & 7;
    const int q0 = blockIdx.x * 128;
    const int tid = threadIdx.x;
    const int wid = tid >> 5, lane = tid & 31;
    const int g = lane >> 2, tig = lane & 3;
    const int mr = wid * 16;

    const float* qp = Qg + (size_t)b * Tq * DMODEL + h * DHEAD;
    const float* kp = Kg + (size_t)b * Tk * DMODEL + h * DHEAD;
    const float* vp = Vg + (size_t)b * Tk * DMODEL + h * DHEAD;

    const uint32_t kBase = (uint32_t)__cvta_generic_to_shared(Kraw);
    const uint32_t vBase = (uint32_t)__cvta_generic_to_shared(Vraw);

    auto issueKV = [&](int s, int kt) {
        #pragma unroll
        for (int i = 0; i < 4; i++) {
            int idx = tid + (i << 8);
            int r = idx >> 4, d4 = (idx & 15) << 2;
            cpasync16(kBase + (s * FKV_STAGE + r * FQ_STRIDE + d4) * 4,
                      kp + (size_t)(kt + r) * DMODEL + d4, 16);
            cpasync16(vBase + (s * FKV_STAGE + r * FQ_STRIDE + d4) * 4,
                      vp + (size_t)(kt + r) * DMODEL + d4, 16);
        }
        asm volatile("cp.async.commit_group;");
    };

    // prefetch tile 0, then load+scale+convert Q
    issueKV(0, 0);
    #pragma unroll
    for (int i = 0; i < 8; i++) {
        int idx = tid + (i << 8);
        int r = idx >> 4, d4 = (idx & 15) << 2;
        int q = q0 + r;
        float4 v = (q < Tq) ? *(const float4*)(qp + (size_t)q * DMODEL + d4)
                            : make_float4(0.f, 0.f, 0.f, 0.f);
        uint32_t* dst = &Qs[r * FQ_STRIDE + d4];
        dst[0] = f2tf32(v.x * scale); dst[1] = f2tf32(v.y * scale);
        dst[2] = f2tf32(v.z * scale); dst[3] = f2tf32(v.w * scale);
    }

    float o[8][4];
    #pragma unroll
    for (int ni = 0; ni < 8; ni++)
        #pragma unroll
        for (int c = 0; c < 4; c++) o[ni][c] = 0.f;
    float m0 = -1e30f, m1 = -1e30f, l0 = 0.f, l1 = 0.f;

    const int srcA = (lane & ~3) | (tig >> 1);   // quad-local source for col tig
    const int srcB = srcA + 2;                   // quad-local source for col tig+4
    const bool odd = tig & 1;

    const int nt = Tk >> 6;
    for (int kt = 0; kt < nt; kt++) {
        const int s = kt & 1;
        if (kt + 1 < nt) {
            issueKV(s ^ 1, (kt + 1) << 6);
            asm volatile("cp.async.wait_group 1;");
        } else {
            asm volatile("cp.async.wait_group 0;");
        }
        __syncthreads();

        const float* Ks = Kraw + s * FKV_STAGE;
        const float* Vs = Vraw + s * FKV_STAGE;

        // ---- S = (scale*Q) @ K^T ----
        float sfr[8][4];
        #pragma unroll
        for (int ni = 0; ni < 8; ni++)
            #pragma unroll
            for (int c = 0; c < 4; c++) sfr[ni][c] = 0.f;
        #pragma unroll
        for (int ks = 0; ks < 64; ks += 8) {
            uint32_t af[4];
            af[0] = Qs[(mr + g    ) * FQ_STRIDE + ks + tig    ];
            af[1] = Qs[(mr + g + 8) * FQ_STRIDE + ks + tig    ];
            af[2] = Qs[(mr + g    ) * FQ_STRIDE + ks + tig + 4];
            af[3] = Qs[(mr + g + 8) * FQ_STRIDE + ks + tig + 4];
            #pragma unroll
            for (int ni = 0; ni < 8; ni++) {
                uint32_t b0 = f2tf32(Ks[(ni * 8 + g) * FQ_STRIDE + ks + tig    ]);
                uint32_t b1 = f2tf32(Ks[(ni * 8 + g) * FQ_STRIDE + ks + tig + 4]);
                mma8(sfr[ni], af, b0, b1);
            }
        }

        // ---- online softmax; P stays in registers as tf32 bits ----
        float tmax0 = -1e30f, tmax1 = -1e30f;
        #pragma unroll
        for (int ni = 0; ni < 8; ni++) {
            tmax0 = fmaxf(tmax0, fmaxf(sfr[ni][0], sfr[ni][1]));
            tmax1 = fmaxf(tmax1, fmaxf(sfr[ni][2], sfr[ni][3]));
        }
        #pragma unroll
        for (int off = 1; off <= 2; off <<= 1) {
            tmax0 = fmaxf(tmax0, __shfl_xor_sync(0xffffffffu, tmax0, off));
            tmax1 = fmaxf(tmax1, __shfl_xor_sync(0xffffffffu, tmax1, off));
        }
        const float mn0 = fmaxf(m0, tmax0), mn1 = fmaxf(m1, tmax1);
        const float a0 = __expf(m0 - mn0), a1 = __expf(m1 - mn1);
        float rs0 = 0.f, rs1 = 0.f;
        uint32_t pf[8][4];
        #pragma unroll
        for (int ni = 0; ni < 8; ni++) {
            float p0 = __expf(sfr[ni][0] - mn0);
            float p1 = __expf(sfr[ni][1] - mn0);
            float p2 = __expf(sfr[ni][2] - mn1);
            float p3 = __expf(sfr[ni][3] - mn1);
            rs0 += p0 + p1; rs1 += p2 + p3;
            pf[ni][0] = f2tf32(p0); pf[ni][1] = f2tf32(p1);
            pf[ni][2] = f2tf32(p2); pf[ni][3] = f2tf32(p3);
        }
        #pragma unroll
        for (int off = 1; off <= 2; off <<= 1) {
            rs0 += __shfl_xor_sync(0xffffffffu, rs0, off);
            rs1 += __shfl_xor_sync(0xffffffffu, rs1, off);
        }
        l0 = l0 * a0 + rs0; l1 = l1 * a1 + rs1;
        m0 = mn0; m1 = mn1;
        #pragma unroll
        for (int ni = 0; ni < 8; ni++) {
            o[ni][0] *= a0; o[ni][1] *= a0;
            o[ni][2] *= a1; o[ni][3] *= a1;
        }

        // ---- O += P @ V, P redistributed c-frag -> a-frag via quad shuffles ----
        // a-frag for k-step j: rows {g, g+8}, cols {tig, tig+4} of P tile j.
        // c-frag holder of col c: quad lane c>>1, slot (c&1).
        #pragma unroll
        for (int j = 0; j < 8; j++) {
            uint32_t r0a = __shfl_sync(0xffffffffu, pf[j][0], srcA);
            uint32_t r1a = __shfl_sync(0xffffffffu, pf[j][1], srcA);
            uint32_t r2a = __shfl_sync(0xffffffffu, pf[j][2], srcA);
            uint32_t r3a = __shfl_sync(0xffffffffu, pf[j][3], srcA);
            uint32_t r0b = __shfl_sync(0xffffffffu, pf[j][0], srcB);
            uint32_t r1b = __shfl_sync(0xffffffffu, pf[j][1], srcB);
            uint32_t r2b = __shfl_sync(0xffffffffu, pf[j][2], srcB);
            uint32_t r3b = __shfl_sync(0xffffffffu, pf[j][3], srcB);
            uint32_t af[4];
            af[0] = odd ? r1a : r0a;   // P[g,     8j+tig  ]
            af[1] = odd ? r3a : r2a;   // P[g+8,   8j+tig  ]
            af[2] = odd ? r1b : r0b;   // P[g,     8j+tig+4]
            af[3] = odd ? r3b : r2b;   // P[g+8,   8j+tig+4]
            const int ks = j * 8;
            #pragma unroll
            for (int ni = 0; ni < 8; ni++) {
                uint32_t b0 = f2tf32(Vs[(ks + tig    ) * FQ_STRIDE + ni * 8 + g]);
                uint32_t b1 = f2tf32(Vs[(ks + tig + 4) * FQ_STRIDE + ni * 8 + g]);
                mma8(o[ni], af, b0, b1);
            }
        }
        __syncthreads();
    }

    // ---- epilogue: normalize + store (float2) ----
    const float i0 = 1.f / l0, i1 = 1.f / l1;
    #pragma unroll
    for (int ni = 0; ni < 8; ni++) {
        int col = h * DHEAD + ni * 8 + 2 * tig;
        int r0 = q0 + mr + g, r1 = r0 + 8;
        if (r0 < Tq)
            *(float2*)(Og + (size_t)(b * Tq + r0) * DMODEL + col) =
                make_float2(o[ni][0] * i0, o[ni][1] * i0);
        if (r1 < Tq)
            *(float2*)(Og + (size_t)(b * Tq + r1) * DMODEL + col) =
                make_float2(o[ni][2] * i1, o[ni][3] * i1);
    }
}

// ================= fused decoder self-attention (exact fp32) =================
// One CTA per (b,h). Q/K/V (100x64) + S (100x100) in smem. Full-row softmax
// first, THEN causal fill of -1e10 (faithful to reference), then P@V.
#define DS_STRIDE 68
#define DS_SSTRIDE 104
#define DEC_SMEM ((3 * T_DEC * DS_STRIDE + T_DEC * DS_SSTRIDE) * 4)

__global__ __launch_bounds__(256)
void dec_self_attn(const float* __restrict__ Qg, const float* __restrict__ Kg,
                   const float* __restrict__ Vg, float* __restrict__ Og)
{
    extern __shared__ float dsm[];
    float* Qd = dsm;
    float* Kd = Qd + T_DEC * DS_STRIDE;
    float* Vd = Kd + T_DEC * DS_STRIDE;
    float* Sd = Vd + T_DEC * DS_STRIDE;

    const int bh = blockIdx.x;
    const int b = bh >> 3, h = bh & 7;
    const int tid = threadIdx.x;
    const int wid = tid >> 5, lane = tid & 31;

    const float* qp = Qg + (size_t)b * T_DEC * DMODEL + h * DHEAD;
    const float* kp = Kg + (size_t)b * T_DEC * DMODEL + h * DHEAD;
    const float* vp = Vg + (size_t)b * T_DEC * DMODEL + h * DHEAD;

    for (int idx = tid; idx < T_DEC * 16; idx += 256) {
        int r = idx >> 4, d4 = (idx & 15) << 2;
        *(float4*)&Qd[r * DS_STRIDE + d4] = *(const float4*)(qp + (size_t)r * DMODEL + d4);
        *(float4*)&Kd[r * DS_STRIDE + d4] = *(const float4*)(kp + (size_t)r * DMODEL + d4);
        *(float4*)&Vd[r * DS_STRIDE + d4] = *(const float4*)(vp + (size_t)r * DMODEL + d4);
    }
    __syncthreads();

    for (int e = tid; e < T_DEC * T_DEC; e += 256) {
        int q = e / T_DEC, kk = e - q * T_DEC;
        const float* qr = &Qd[q * DS_STRIDE];
        const float* kr = &Kd[kk * DS_STRIDE];
        float acc = 0.f;
        #pragma unroll
        for (int d = 0; d < 64; d++) acc += qr[d] * kr[d];
        Sd[q * DS_SSTRIDE + kk] = acc * 0.125f;
    }
    __syncthreads();

    for (int q = wid; q < T_DEC; q += 8) {
        float* row = &Sd[q * DS_SSTRIDE];
        float r0 = (lane      < T_DEC) ? row[lane]      : -1e30f;
        float r1 = (lane + 32 < T_DEC) ? row[lane + 32] : -1e30f;
        float r2 = (lane + 64 < T_DEC) ? row[lane + 64] : -1e30f;
        float r3 = (lane + 96 < T_DEC) ? row[lane + 96] : -1e30f;
        float m = fmaxf(fmaxf(r0, r1), fmaxf(r2, r3));
        #pragma unroll
        for (int off = 16; off; off >>= 1) m = fmaxf(m, __shfl_xor_sync(0xffffffffu, m, off));
        float e0 = expf(r0 - m), e1 = expf(r1 - m), e2 = expf(r2 - m), e3 = expf(r3 - m);
        if (lane      >= T_DEC) e0 = 0.f;
        if (lane + 32 >= T_DEC) e1 = 0.f;
        if (lane + 64 >= T_DEC) e2 = 0.f;
        if (lane + 96 >= T_DEC) e3 = 0.f;
        float s = e0 + e1 + e2 + e3;
        #pragma unroll
        for (int off = 16; off; off >>= 1) s += __shfl_xor_sync(0xffffffffu, s, off);
        const float inv = 1.f / s;
        if (lane      < T_DEC) row[lane]      = (lane      > q) ? -1e10f : e0 * inv;
        if (lane + 32 < T_DEC) row[lane + 32] = (lane + 32 > q) ? -1e10f : e1 * inv;
        if (lane + 64 < T_DEC) row[lane + 64] = (lane + 64 > q) ? -1e10f : e2 * inv;
        if (lane + 96 < T_DEC) row[lane + 96] = (lane + 96 > q) ? -1e10f : e3 * inv;
    }
    __syncthreads();

    for (int e = tid; e < T_DEC * 64; e += 256) {
        int q = e >> 6, d = e & 63;
        const float* pr = &Sd[q * DS_SSTRIDE];
        float acc = 0.f;
        #pragma unroll 4
        for (int kk = 0; kk < T_DEC; kk++) acc += pr[kk] * Vd[kk * DS_STRIDE + d];
        Og[(size_t)(b * T_DEC + q) * DMODEL + h * DHEAD + d] = acc;
    }
}

// ---------------- fused residual + LayerNorm over D=512 ----------------
__global__ void ln_res_kernel(const float* __restrict__ A, const float* __restrict__ Bv,
                              const float* __restrict__ g, const float* __restrict__ be,
                              float* __restrict__ O) {
    const int row = blockIdx.x;
    const float* a = A + (size_t)row * DMODEL;
    const float* b = Bv + (size_t)row * DMODEL;
    __shared__ float red[256];
    const int tid = threadIdx.x;

    float v0 = a[tid] + b[tid];
    float v1 = a[tid + 256] + b[tid + 256];

    red[tid] = v0 + v1; __syncthreads();
    for (int s = 128; s > 0; s >>= 1) { if (tid < s) red[tid] += red[tid + s]; __syncthreads(); }
    const float mean = red[0] * (1.f / DMODEL); __syncthreads();

    float d0 = v0 - mean, d1 = v1 - mean;
    red[tid] = d0 * d0 + d1 * d1; __syncthreads();
    for (int s = 128; s > 0; s >>= 1) { if (tid < s) red[tid] += red[tid + s]; __syncthreads(); }
    const float inv = rsqrtf(red[0] * (1.f / DMODEL) + 1e-5f);

    O[(size_t)row * DMODEL + tid]       = d0 * inv * g[tid]       + be[tid];
    O[(size_t)row * DMODEL + tid + 256] = d1 * inv * g[tid + 256] + be[tid + 256];
}

// ---------------- host orchestration ----------------
static inline void mgemm(const float* A, const float* B, const float* bias, float* C,
                         int M, int N, int K, int relu) {
    dim3 grid(N / 128, (M + 127) / 128);
    if (relu)
        mma_gemm<1><<<grid, 256, GEMM_SMEM>>>(A, B, bias, C, M, N, K);
    else
        mma_gemm<0><<<grid, 256, GEMM_SMEM>>>(A, B, bias, C, M, N, K);
}

template <typename T>
static inline float* sym(T& s) {
    void* p = nullptr;
    cudaGetSymbolAddress(&p, s);
    return (float*)p;
}

extern "C" void kernel_launch(void* const* d_in, const int* in_sizes, int n_in,
                              void* d_out, int out_size) {
    (void)in_sizes; (void)n_in; (void)out_size;

    cudaFuncSetAttribute(mma_gemm<0>, cudaFuncAttributeMaxDynamicSharedMemorySize, GEMM_SMEM);
    cudaFuncSetAttribute(mma_gemm<1>, cudaFuncAttributeMaxDynamicSharedMemorySize, GEMM_SMEM);
    cudaFuncSetAttribute(flash_attn, cudaFuncAttributeMaxDynamicSharedMemorySize, FLASH_SMEM);
    cudaFuncSetAttribute(dec_self_attn, cudaFuncAttributeMaxDynamicSharedMemorySize, DEC_SMEM);

    const float* x_in      = (const float*)d_in[0];
    const float* y_in      = (const float*)d_in[1];
    const float* enc_Wq    = (const float*)d_in[2];
    const float* enc_Wk    = (const float*)d_in[3];
    const float* enc_Wv    = (const float*)d_in[4];
    const float* enc_ff_w1 = (const float*)d_in[5];
    const float* enc_ff_b1 = (const float*)d_in[6];
    const float* enc_ff_w2 = (const float*)d_in[7];
    const float* enc_ff_b2 = (const float*)d_in[8];
    const float* enc_ln1_g = (const float*)d_in[9];
    const float* enc_ln1_b = (const float*)d_in[10];
    const float* enc_ln2_g = (const float*)d_in[11];
    const float* enc_ln2_b = (const float*)d_in[12];
    const float* dec_Wq1   = (const float*)d_in[13];
    const float* dec_Wk1   = (const float*)d_in[14];
    const float* dec_Wv1   = (const float*)d_in[15];
    const float* dec_Wq2   = (const float*)d_in[16];
    const float* dec_Wk2   = (const float*)d_in[17];
    const float* dec_Wv2   = (const float*)d_in[18];
    const float* dec_ff_w1 = (const float*)d_in[19];
    const float* dec_ff_b1 = (const float*)d_in[20];
    const float* dec_ff_w2 = (const float*)d_in[21];
    const float* dec_ff_b2 = (const float*)d_in[22];
    const float* dec_ln1_g = (const float*)d_in[23];
    const float* dec_ln1_b = (const float*)d_in[24];
    const float* dec_ln2_g = (const float*)d_in[25];
    const float* dec_ln2_b = (const float*)d_in[26];
    const float* dec_ln3_g = (const float*)d_in[27];
    const float* dec_ln3_b = (const float*)d_in[28];

    float* q   = sym(g_q);
    float* k   = sym(g_k);
    float* v   = sym(g_v);
    float* att = sym(g_att);
    float* x1  = sym(g_x1);
    float* gx  = sym(g_x);
    float* h   = sym(g_h);
    float* y1  = sym(g_y1);
    float* y2  = sym(g_y2);
    float* gy  = sym(g_y);

    const float scale = 0.125f;  // 1/sqrt(64), exact power of 2
    const long long WO = DMODEL * DMODEL;
    const long long FO1 = DMODEL * DFF;
    const long long FO2 = DFF * DMODEL;

    // -------- encoder --------
    const float* xc = x_in;
    for (int i = 0; i < 2; i++) {
        mgemm(xc, enc_Wq + i * WO, nullptr, q, M_ENC, DMODEL, DMODEL, 0);
        mgemm(xc, enc_Wk + i * WO, nullptr, k, M_ENC, DMODEL, DMODEL, 0);
        mgemm(xc, enc_Wv + i * WO, nullptr, v, M_ENC, DMODEL, DMODEL, 0);
        flash_attn<<<dim3(T_ENC / 128, BHT), 256, FLASH_SMEM>>>(q, k, v, att, T_ENC, T_ENC, scale);
        ln_res_kernel<<<M_ENC, 256>>>(xc, att, enc_ln1_g + i * DMODEL, enc_ln1_b + i * DMODEL, x1);
        mgemm(x1, enc_ff_w1 + i * FO1, enc_ff_b1 + i * DFF, h, M_ENC, DFF, DMODEL, 1);
        mgemm(h, enc_ff_w2 + i * FO2, enc_ff_b2 + i * DMODEL, att, M_ENC, DMODEL, DFF, 0);
        ln_res_kernel<<<M_ENC, 256>>>(x1, att, enc_ln2_g + i * DMODEL, enc_ln2_b + i * DMODEL, gx);
        xc = gx;
    }

    // -------- decoder --------
    const float* yc = y_in;
    for (int i = 0; i < 2; i++) {
        // masked self-attention: exact fp32 fused path (post-softmax -1e10 fill)
        mgemm(yc, dec_Wq1 + i * WO, nullptr, q, M_DEC, DMODEL, DMODEL, 0);
        mgemm(yc, dec_Wk1 + i * WO, nullptr, k, M_DEC, DMODEL, DMODEL, 0);
        mgemm(yc, dec_Wv1 + i * WO, nullptr, v, M_DEC, DMODEL, DMODEL, 0);
        dec_self_attn<<<BHT, 256, DEC_SMEM>>>(q, k, v, att);
        ln_res_kernel<<<M_DEC, 256>>>(yc, att, dec_ln1_g + i * DMODEL, dec_ln1_b + i * DMODEL, y1);

        // cross-attention (non-causal -> flash)
        mgemm(y1, dec_Wq2 + i * WO, nullptr, q, M_DEC, DMODEL, DMODEL, 0);
        mgemm(xc, dec_Wk2 + i * WO, nullptr, k, M_ENC, DMODEL, DMODEL, 0);
        mgemm(xc, dec_Wv2 + i * WO, nullptr, v, M_ENC, DMODEL, DMODEL, 0);
        flash_attn<<<dim3(1, BHT), 256, FLASH_SMEM>>>(q, k, v, att, T_DEC, T_ENC, scale);
        ln_res_kernel<<<M_DEC, 256>>>(y1, att, dec_ln2_g + i * DMODEL, dec_ln2_b + i * DMODEL, y2);

        // feed-forward
        mgemm(y2, dec_ff_w1 + i * FO1, dec_ff_b1 + i * DFF, h, M_DEC, DFF, DMODEL, 1);
        mgemm(h, dec_ff_w2 + i * FO2, dec_ff_b2 + i * DMODEL, att, M_DEC, DMODEL, DFF, 0);
        float* outp = (i == 1) ? (float*)d_out : gy;
        ln_res_kernel<<<M_DEC, 256>>>(y2, att, dec_ln3_g + i * DMODEL, dec_ln3_b + i * DMODEL, outp);
        yc = gy;
    }
}

// round 6
// speedup vs baseline: 1.1691x; 1.0289x over previous
#include <cuda_runtime.h>
#include <cstdint>
#include <cstddef>

// ---------------- problem constants ----------------
#define BATCH   8
#define T_ENC   1024
#define T_DEC   100
#define DMODEL  512
#define NHEAD   8
#define DHEAD   64
#define DFF     2048
#define M_ENC   (BATCH * T_ENC)   // 8192
#define M_DEC   (BATCH * T_DEC)   // 800
#define BHT     (BATCH * NHEAD)   // 64

// ---------------- weight tf32 cache offsets (elements) ----------------
#define OFF_EWQ   0LL
#define OFF_EWK   524288LL
#define OFF_EWV   1048576LL
#define OFF_EW1   1572864LL
#define OFF_EW2   3670016LL
#define OFF_DWQ1  5767168LL
#define OFF_DWK1  6291456LL
#define OFF_DWV1  6815744LL
#define OFF_DWQ2  7340032LL
#define OFF_DWK2  7864320LL
#define OFF_DWV2  8388608LL
#define OFF_DW1   8912896LL
#define OFF_DW2   11010048LL
#define WTF_TOTAL 13107200LL

// ---------------- scratch (device globals; no allocation allowed) ----------------
__device__ uint32_t g_wtf [WTF_TOTAL];          // tf32 weights
__device__ uint32_t g_q   [M_ENC * DMODEL];     // tf32 (scale pre-folded)
__device__ uint32_t g_k   [M_ENC * DMODEL];     // tf32
__device__ uint32_t g_v   [M_ENC * DMODEL];     // tf32
__device__ uint32_t g_h   [M_ENC * DFF];        // tf32 FFN intermediate
__device__ uint32_t g_xtf [M_ENC * DMODEL];     // tf32 copy of enc activations
__device__ uint32_t g_x1tf[M_ENC * DMODEL];
__device__ uint32_t g_ytf [M_DEC * DMODEL];     // tf32 copy of dec activations
__device__ uint32_t g_y1tf[M_DEC * DMODEL];
__device__ uint32_t g_y2tf[M_DEC * DMODEL];
__device__ float g_att [M_ENC * DMODEL];
__device__ float g_x1  [M_ENC * DMODEL];
__device__ float g_x   [M_ENC * DMODEL];
__device__ float g_y1  [M_DEC * DMODEL];
__device__ float g_y2  [M_DEC * DMODEL];
__device__ float g_y   [M_DEC * DMODEL];
__device__ float g_qd  [M_DEC * DMODEL];        // fp32 dec-self Q/K/V
__device__ float g_kd  [M_DEC * DMODEL];
__device__ float g_vd  [M_DEC * DMODEL];

__device__ __forceinline__ uint32_t f2tf32(float x) {
    uint32_t t;
    asm("cvt.rna.tf32.f32 %0, %1;" : "=r"(t) : "f"(x));
    return t;
}

__device__ __forceinline__ void mma8(float* c, const uint32_t* a, uint32_t b0, uint32_t b1) {
    asm volatile(
        "mma.sync.aligned.m16n8k8.row.col.f32.tf32.tf32.f32 "
        "{%0,%1,%2,%3}, {%4,%5,%6,%7}, {%8,%9}, {%0,%1,%2,%3};"
        : "+f"(c[0]), "+f"(c[1]), "+f"(c[2]), "+f"(c[3])
        : "r"(a[0]), "r"(a[1]), "r"(a[2]), "r"(a[3]), "r"(b0), "r"(b1));
}

__device__ __forceinline__ void cpasync16(uint32_t smem_dst, const void* gsrc, int bytes) {
    asm volatile("cp.async.ca.shared.global [%0], [%1], 16, %2;"
                 :: "r"(smem_dst), "l"(gsrc), "r"(bytes));
}

// ---------------- fp32 -> tf32 bit conversion (grid-stride, float4) ----------------
__global__ void cvt_tf32_kernel(const float4* __restrict__ in, uint4* __restrict__ out, int n4) {
    for (int i = blockIdx.x * blockDim.x + threadIdx.x; i < n4; i += gridDim.x * blockDim.x) {
        float4 v = in[i];
        out[i] = make_uint4(f2tf32(v.x), f2tf32(v.y), f2tf32(v.z), f2tf32(v.w));
    }
}

// ================= 2-stage cp.async tf32 GEMM (zero cvt in mainloop) =================
// C = alpha * A(MxK) @ B(KxN) (+bias) (+relu). A,B are tf32 bits. BM=BN=128, BK=32.
#define GA_STRIDE 36
#define GB_STRIDE 132
#define GA_STAGE  (128 * GA_STRIDE)
#define GB_STAGE  (32 * GB_STRIDE)
#define GEMM_SMEM ((2 * GA_STAGE + 2 * GB_STAGE) * 4)

template<int RELU, int TF32OUT>
__global__ __launch_bounds__(256)
void mma_gemm(const uint32_t* __restrict__ A, const uint32_t* __restrict__ B,
              const float* __restrict__ bias, void* __restrict__ Cv,
              int M, int N, int K, float alpha)
{
    extern __shared__ uint32_t gsm[];
    uint32_t* Asf = gsm;
    uint32_t* Bsf = gsm + 2 * GA_STAGE;

    const int tid  = threadIdx.x;
    const int wid  = tid >> 5, lane = tid & 31;
    const int wm   = wid & 1, wn = wid >> 1;
    const int g    = lane >> 2, tig = lane & 3;
    const int m0   = blockIdx.y * 128, n0 = blockIdx.x * 128;

    const uint32_t aBase = (uint32_t)__cvta_generic_to_shared(Asf);
    const uint32_t bBase = (uint32_t)__cvta_generic_to_shared(Bsf);

    float acc[4][4][4];
    #pragma unroll
    for (int i = 0; i < 4; i++)
        #pragma unroll
        for (int j = 0; j < 4; j++)
            #pragma unroll
            for (int c = 0; c < 4; c++) acc[i][j][c] = 0.f;

    auto issue = [&](int s, int k0) {
        #pragma unroll
        for (int i = 0; i < 4; i++) {
            int idx = tid + (i << 8);
            int r = idx >> 3, kk4 = (idx & 7) << 2;
            int m = m0 + r;
            const uint32_t* src = A + (size_t)(m < M ? m : 0) * K + k0 + kk4;
            cpasync16(aBase + (s * GA_STAGE + r * GA_STRIDE + kk4) * 4, src, (m < M) ? 16 : 0);
        }
        #pragma unroll
        for (int i = 0; i < 4; i++) {
            int idx = tid + (i << 8);
            int kk = idx >> 5, n4 = (idx & 31) << 2;
            const uint32_t* src = B + (size_t)(k0 + kk) * N + n0 + n4;
            cpasync16(bBase + (s * GB_STAGE + kk * GB_STRIDE + n4) * 4, src, 16);
        }
        asm volatile("cp.async.commit_group;");
    };

    const int nk = K >> 5;
    issue(0, 0);

    for (int kt = 0; kt < nk; kt++) {
        const int s = kt & 1;
        if (kt + 1 < nk) {
            issue(s ^ 1, (kt + 1) << 5);
            asm volatile("cp.async.wait_group 1;");
        } else {
            asm volatile("cp.async.wait_group 0;");
        }
        __syncthreads();

        const uint32_t* As = Asf + s * GA_STAGE;
        const uint32_t* Bs = Bsf + s * GB_STAGE;
        #pragma unroll
        for (int ks = 0; ks < 32; ks += 8) {
            uint32_t af[4][4];
            #pragma unroll
            for (int mi = 0; mi < 4; mi++) {
                int mr = wm * 64 + mi * 16;
                af[mi][0] = As[(mr + g    ) * GA_STRIDE + ks + tig    ];
                af[mi][1] = As[(mr + g + 8) * GA_STRIDE + ks + tig    ];
                af[mi][2] = As[(mr + g    ) * GA_STRIDE + ks + tig + 4];
                af[mi][3] = As[(mr + g + 8) * GA_STRIDE + ks + tig + 4];
            }
            uint32_t bf[4][2];
            #pragma unroll
            for (int ni = 0; ni < 4; ni++) {
                int nc = wn * 32 + ni * 8 + g;
                bf[ni][0] = Bs[(ks + tig    ) * GB_STRIDE + nc];
                bf[ni][1] = Bs[(ks + tig + 4) * GB_STRIDE + nc];
            }
            #pragma unroll
            for (int mi = 0; mi < 4; mi++)
                #pragma unroll
                for (int ni = 0; ni < 4; ni++)
                    mma8(acc[mi][ni], af[mi], bf[ni][0], bf[ni][1]);
        }
        __syncthreads();
    }

    #pragma unroll
    for (int mi = 0; mi < 4; mi++) {
        int mb = m0 + wm * 64 + mi * 16;
        #pragma unroll
        for (int ni = 0; ni < 4; ni++) {
            int nb = n0 + wn * 32 + ni * 8 + 2 * tig;
            #pragma unroll
            for (int half = 0; half < 2; half++) {
                int m = mb + g + half * 8;
                if (m < M) {
                    float v0 = acc[mi][ni][half * 2    ] * alpha;
                    float v1 = acc[mi][ni][half * 2 + 1] * alpha;
                    if (bias) { v0 += bias[nb]; v1 += bias[nb + 1]; }
                    if (RELU) { v0 = fmaxf(v0, 0.f); v1 = fmaxf(v1, 0.f); }
                    if (TF32OUT) {
                        *(uint2*)((uint32_t*)Cv + (size_t)m * N + nb) =
                            make_uint2(f2tf32(v0), f2tf32(v1));
                    } else {
                        *(float2*)((float*)Cv + (size_t)m * N + nb) = make_float2(v0, v1);
                    }
                }
            }
        }
    }
}

// ================= fused flash attention (non-causal, exact) =================
// Q/K/V arrive as tf32 bits (Q pre-scaled). Zero cvt in S / PV loops; only P
// (post-exp) is converted. cp.async double-buffered KV, P in registers moved
// c-frag -> a-frag via quad shuffles. Tk % 64 == 0.
#define FQ_STRIDE 68
#define FKV_STAGE (64 * FQ_STRIDE)
#define FLASH_SMEM ((128 * FQ_STRIDE + 4 * FKV_STAGE) * 4)

__global__ __launch_bounds__(256, 2)
void flash_attn(const uint32_t* __restrict__ Qg, const uint32_t* __restrict__ Kg,
                const uint32_t* __restrict__ Vg, float* __restrict__ Og,
                int Tq, int Tk)
{
    extern __shared__ uint32_t fsm[];
    uint32_t* Qs   = fsm;                        // [128][68]
    uint32_t* Kraw = fsm + 128 * FQ_STRIDE;      // 2 x [64][68]
    uint32_t* Vraw = Kraw + 2 * FKV_STAGE;       // 2 x [64][68]

    const int bh = blockIdx.y;
    const int b = bh >> 3, h = bh & 7;
    const int q0 = blockIdx.x * 128;
    const int tid = threadIdx.x;
    const int wid = tid >> 5, lane = tid & 31;
    const int g = lane >> 2, tig = lane & 3;
    const int mr = wid * 16;

    const uint32_t* qp = Qg + (size_t)b * Tq * DMODEL + h * DHEAD;
    const uint32_t* kp = Kg + (size_t)b * Tk * DMODEL + h * DHEAD;
    const uint32_t* vp = Vg + (size_t)b * Tk * DMODEL + h * DHEAD;

    const uint32_t qBase = (uint32_t)__cvta_generic_to_shared(Qs);
    const uint32_t kBase = (uint32_t)__cvta_generic_to_shared(Kraw);
    const uint32_t vBase = (uint32_t)__cvta_generic_to_shared(Vraw);

    auto issueKV = [&](int s, int kt) {
        #pragma unroll
        for (int i = 0; i < 4; i++) {
            int idx = tid + (i << 8);
            int r = idx >> 4, d4 = (idx & 15) << 2;
            cpasync16(kBase + (s * FKV_STAGE + r * FQ_STRIDE + d4) * 4,
                      kp + (size_t)(kt + r) * DMODEL + d4, 16);
            cpasync16(vBase + (s * FKV_STAGE + r * FQ_STRIDE + d4) * 4,
                      vp + (size_t)(kt + r) * DMODEL + d4, 16);
        }
        asm volatile("cp.async.commit_group;");
    };

    // group 0: KV tile 0; group 1: Q (both complete before first compute)
    issueKV(0, 0);
    #pragma unroll
    for (int i = 0; i < 8; i++) {
        int idx = tid + (i << 8);
        int r = idx >> 4, d4 = (idx & 15) << 2;
        int q = q0 + r;
        cpasync16(qBase + (r * FQ_STRIDE + d4) * 4,
                  qp + (size_t)(q < Tq ? q : 0) * DMODEL + d4, (q < Tq) ? 16 : 0);
    }
    asm volatile("cp.async.commit_group;");

    float o[8][4];
    #pragma unroll
    for (int ni = 0; ni < 8; ni++)
        #pragma unroll
        for (int c = 0; c < 4; c++) o[ni][c] = 0.f;
    float m0 = -1e30f, m1 = -1e30f, l0 = 0.f, l1 = 0.f;

    const int srcA = (lane & ~3) | (tig >> 1);
    const int srcB = srcA + 2;
    const bool odd = tig & 1;

    const int nt = Tk >> 6;
    for (int kt = 0; kt < nt; kt++) {
        const int s = kt & 1;
        if (kt + 1 < nt) {
            issueKV(s ^ 1, (kt + 1) << 6);
            asm volatile("cp.async.wait_group 1;");
        } else {
            asm volatile("cp.async.wait_group 0;");
        }
        __syncthreads();

        const uint32_t* Ks = Kraw + s * FKV_STAGE;
        const uint32_t* Vs = Vraw + s * FKV_STAGE;

        // ---- S = Q @ K^T (Q pre-scaled tf32) ----
        float sfr[8][4];
        #pragma unroll
        for (int ni = 0; ni < 8; ni++)
            #pragma unroll
            for (int c = 0; c < 4; c++) sfr[ni][c] = 0.f;
        #pragma unroll
        for (int ks = 0; ks < 64; ks += 8) {
            uint32_t af[4];
            af[0] = Qs[(mr + g    ) * FQ_STRIDE + ks + tig    ];
            af[1] = Qs[(mr + g + 8) * FQ_STRIDE + ks + tig    ];
            af[2] = Qs[(mr + g    ) * FQ_STRIDE + ks + tig + 4];
            af[3] = Qs[(mr + g + 8) * FQ_STRIDE + ks + tig + 4];
            #pragma unroll
            for (int ni = 0; ni < 8; ni++) {
                uint32_t b0 = Ks[(ni * 8 + g) * FQ_STRIDE + ks + tig    ];
                uint32_t b1 = Ks[(ni * 8 + g) * FQ_STRIDE + ks + tig + 4];
                mma8(sfr[ni], af, b0, b1);
            }
        }

        // ---- online softmax; P stays in registers ----
        float tmax0 = -1e30f, tmax1 = -1e30f;
        #pragma unroll
        for (int ni = 0; ni < 8; ni++) {
            tmax0 = fmaxf(tmax0, fmaxf(sfr[ni][0], sfr[ni][1]));
            tmax1 = fmaxf(tmax1, fmaxf(sfr[ni][2], sfr[ni][3]));
        }
        #pragma unroll
        for (int off = 1; off <= 2; off <<= 1) {
            tmax0 = fmaxf(tmax0, __shfl_xor_sync(0xffffffffu, tmax0, off));
            tmax1 = fmaxf(tmax1, __shfl_xor_sync(0xffffffffu, tmax1, off));
        }
        const float mn0 = fmaxf(m0, tmax0), mn1 = fmaxf(m1, tmax1);
        const float a0 = __expf(m0 - mn0), a1 = __expf(m1 - mn1);
        float rs0 = 0.f, rs1 = 0.f;
        uint32_t pf[8][4];
        #pragma unroll
        for (int ni = 0; ni < 8; ni++) {
            float p0 = __expf(sfr[ni][0] - mn0);
            float p1 = __expf(sfr[ni][1] - mn0);
            float p2 = __expf(sfr[ni][2] - mn1);
            float p3 = __expf(sfr[ni][3] - mn1);
            rs0 += p0 + p1; rs1 += p2 + p3;
            pf[ni][0] = f2tf32(p0); pf[ni][1] = f2tf32(p1);
            pf[ni][2] = f2tf32(p2); pf[ni][3] = f2tf32(p3);
        }
        #pragma unroll
        for (int off = 1; off <= 2; off <<= 1) {
            rs0 += __shfl_xor_sync(0xffffffffu, rs0, off);
            rs1 += __shfl_xor_sync(0xffffffffu, rs1, off);
        }
        l0 = l0 * a0 + rs0; l1 = l1 * a1 + rs1;
        m0 = mn0; m1 = mn1;
        #pragma unroll
        for (int ni = 0; ni < 8; ni++) {
            o[ni][0] *= a0; o[ni][1] *= a0;
            o[ni][2] *= a1; o[ni][3] *= a1;
        }

        // ---- O += P @ V, P redistributed c-frag -> a-frag via quad shuffles ----
        #pragma unroll
        for (int j = 0; j < 8; j++) {
            uint32_t r0a = __shfl_sync(0xffffffffu, pf[j][0], srcA);
            uint32_t r1a = __shfl_sync(0xffffffffu, pf[j][1], srcA);
            uint32_t r2a = __shfl_sync(0xffffffffu, pf[j][2], srcA);
            uint32_t r3a = __shfl_sync(0xffffffffu, pf[j][3], srcA);
            uint32_t r0b = __shfl_sync(0xffffffffu, pf[j][0], srcB);
            uint32_t r1b = __shfl_sync(0xffffffffu, pf[j][1], srcB);
            uint32_t r2b = __shfl_sync(0xffffffffu, pf[j][2], srcB);
            uint32_t r3b = __shfl_sync(0xffffffffu, pf[j][3], srcB);
            uint32_t af[4];
            af[0] = odd ? r1a : r0a;
            af[1] = odd ? r3a : r2a;
            af[2] = odd ? r1b : r0b;
            af[3] = odd ? r3b : r2b;
            const int ks = j * 8;
            #pragma unroll
            for (int ni = 0; ni < 8; ni++) {
                uint32_t b0 = Vs[(ks + tig    ) * FQ_STRIDE + ni * 8 + g];
                uint32_t b1 = Vs[(ks + tig + 4) * FQ_STRIDE + ni * 8 + g];
                mma8(o[ni], af, b0, b1);
            }
        }
        __syncthreads();
    }

    // ---- epilogue: normalize + store (float2) ----
    const float i0 = 1.f / l0, i1 = 1.f / l1;
    #pragma unroll
    for (int ni = 0; ni < 8; ni++) {
        int col = h * DHEAD + ni * 8 + 2 * tig;
        int r0 = q0 + mr + g, r1 = r0 + 8;
        if (r0 < Tq)
            *(float2*)(Og + (size_t)(b * Tq + r0) * DMODEL + col) =
                make_float2(o[ni][0] * i0, o[ni][1] * i0);
        if (r1 < Tq)
            *(float2*)(Og + (size_t)(b * Tq + r1) * DMODEL + col) =
                make_float2(o[ni][2] * i1, o[ni][3] * i1);
    }
}

// ================= fused decoder self-attention (exact fp32) =================
#define DS_STRIDE 68
#define DS_SSTRIDE 104
#define DEC_SMEM ((3 * T_DEC * DS_STRIDE + T_DEC * DS_SSTRIDE) * 4)

__global__ __launch_bounds__(256)
void dec_self_attn(const float* __restrict__ Qg, const float* __restrict__ Kg,
                   const float* __restrict__ Vg, float* __restrict__ Og)
{
    extern __shared__ float dsm[];
    float* Qd = dsm;
    float* Kd = Qd + T_DEC * DS_STRIDE;
    float* Vd = Kd + T_DEC * DS_STRIDE;
    float* Sd = Vd + T_DEC * DS_STRIDE;

    const int bh = blockIdx.x;
    const int b = bh >> 3, h = bh & 7;
    const int tid = threadIdx.x;
    const int wid = tid >> 5, lane = tid & 31;

    const float* qp = Qg + (size_t)b * T_DEC * DMODEL + h * DHEAD;
    const float* kp = Kg + (size_t)b * T_DEC * DMODEL + h * DHEAD;
    const float* vp = Vg + (size_t)b * T_DEC * DMODEL + h * DHEAD;

    for (int idx = tid; idx < T_DEC * 16; idx += 256) {
        int r = idx >> 4, d4 = (idx & 15) << 2;
        *(float4*)&Qd[r * DS_STRIDE + d4] = *(const float4*)(qp + (size_t)r * DMODEL + d4);
        *(float4*)&Kd[r * DS_STRIDE + d4] = *(const float4*)(kp + (size_t)r * DMODEL + d4);
        *(float4*)&Vd[r * DS_STRIDE + d4] = *(const float4*)(vp + (size_t)r * DMODEL + d4);
    }
    __syncthreads();

    for (int e = tid; e < T_DEC * T_DEC; e += 256) {
        int q = e / T_DEC, kk = e - q * T_DEC;
        const float* qr = &Qd[q * DS_STRIDE];
        const float* kr = &Kd[kk * DS_STRIDE];
        float acc = 0.f;
        #pragma unroll
        for (int d = 0; d < 64; d++) acc += qr[d] * kr[d];
        Sd[q * DS_SSTRIDE + kk] = acc * 0.125f;
    }
    __syncthreads();

    for (int q = wid; q < T_DEC; q += 8) {
        float* row = &Sd[q * DS_SSTRIDE];
        float r0 = (lane      < T_DEC) ? row[lane]      : -1e30f;
        float r1 = (lane + 32 < T_DEC) ? row[lane + 32] : -1e30f;
        float r2 = (lane + 64 < T_DEC) ? row[lane + 64] : -1e30f;
        float r3 = (lane + 96 < T_DEC) ? row[lane + 96] : -1e30f;
        float m = fmaxf(fmaxf(r0, r1), fmaxf(r2, r3));
        #pragma unroll
        for (int off = 16; off; off >>= 1) m = fmaxf(m, __shfl_xor_sync(0xffffffffu, m, off));
        float e0 = expf(r0 - m), e1 = expf(r1 - m), e2 = expf(r2 - m), e3 = expf(r3 - m);
        if (lane      >= T_DEC) e0 = 0.f;
        if (lane + 32 >= T_DEC) e1 = 0.f;
        if (lane + 64 >= T_DEC) e2 = 0.f;
        if (lane + 96 >= T_DEC) e3 = 0.f;
        float s = e0 + e1 + e2 + e3;
        #pragma unroll
        for (int off = 16; off; off >>= 1) s += __shfl_xor_sync(0xffffffffu, s, off);
        const float inv = 1.f / s;
        if (lane      < T_DEC) row[lane]      = (lane      > q) ? -1e10f : e0 * inv;
        if (lane + 32 < T_DEC) row[lane + 32] = (lane + 32 > q) ? -1e10f : e1 * inv;
        if (lane + 64 < T_DEC) row[lane + 64] = (lane + 64 > q) ? -1e10f : e2 * inv;
        if (lane + 96 < T_DEC) row[lane + 96] = (lane + 96 > q) ? -1e10f : e3 * inv;
    }
    __syncthreads();

    for (int e = tid; e < T_DEC * 64; e += 256) {
        int q = e >> 6, d = e & 63;
        const float* pr = &Sd[q * DS_SSTRIDE];
        float acc = 0.f;
        #pragma unroll 4
        for (int kk = 0; kk < T_DEC; kk++) acc += pr[kk] * Vd[kk * DS_STRIDE + d];
        Og[(size_t)(b * T_DEC + q) * DMODEL + h * DHEAD + d] = acc;
    }
}

// ---------------- fused residual + LayerNorm (fp32 out + optional tf32 out) ----------------
__global__ void ln_res_kernel(const float* __restrict__ A, const float* __restrict__ Bv,
                              const float* __restrict__ g, const float* __restrict__ be,
                              float* __restrict__ O, uint32_t* __restrict__ Otf) {
    const int row = blockIdx.x;
    const float* a = A + (size_t)row * DMODEL;
    const float* b = Bv + (size_t)row * DMODEL;
    __shared__ float red[256];
    const int tid = threadIdx.x;

    float v0 = a[tid] + b[tid];
    float v1 = a[tid + 256] + b[tid + 256];

    red[tid] = v0 + v1; __syncthreads();
    for (int s = 128; s > 0; s >>= 1) { if (tid < s) red[tid] += red[tid + s]; __syncthreads(); }
    const float mean = red[0] * (1.f / DMODEL); __syncthreads();

    float d0 = v0 - mean, d1 = v1 - mean;
    red[tid] = d0 * d0 + d1 * d1; __syncthreads();
    for (int s = 128; s > 0; s >>= 1) { if (tid < s) red[tid] += red[tid + s]; __syncthreads(); }
    const float inv = rsqrtf(red[0] * (1.f / DMODEL) + 1e-5f);

    const float o0 = d0 * inv * g[tid]       + be[tid];
    const float o1 = d1 * inv * g[tid + 256] + be[tid + 256];
    O[(size_t)row * DMODEL + tid]       = o0;
    O[(size_t)row * DMODEL + tid + 256] = o1;
    if (Otf) {
        Otf[(size_t)row * DMODEL + tid]       = f2tf32(o0);
        Otf[(size_t)row * DMODEL + tid + 256] = f2tf32(o1);
    }
}

// ---------------- host orchestration ----------------
static inline void mgemm(const uint32_t* A, const uint32_t* B, const float* bias, void* C,
                         int M, int N, int K, int relu, int tf32out, float alpha) {
    dim3 grid(N / 128, (M + 127) / 128);
    if (relu && tf32out)
        mma_gemm<1, 1><<<grid, 256, GEMM_SMEM>>>(A, B, bias, C, M, N, K, alpha);
    else if (tf32out)
        mma_gemm<0, 1><<<grid, 256, GEMM_SMEM>>>(A, B, bias, C, M, N, K, alpha);
    else
        mma_gemm<0, 0><<<grid, 256, GEMM_SMEM>>>(A, B, bias, C, M, N, K, alpha);
}

template <typename T>
static inline void* symv(T& s) {
    void* p = nullptr;
    cudaGetSymbolAddress(&p, s);
    return p;
}

extern "C" void kernel_launch(void* const* d_in, const int* in_sizes, int n_in,
                              void* d_out, int out_size) {
    (void)in_sizes; (void)n_in; (void)out_size;

    cudaFuncSetAttribute((const void*)mma_gemm<0,0>, cudaFuncAttributeMaxDynamicSharedMemorySize, GEMM_SMEM);
    cudaFuncSetAttribute((const void*)mma_gemm<0,1>, cudaFuncAttributeMaxDynamicSharedMemorySize, GEMM_SMEM);
    cudaFuncSetAttribute((const void*)mma_gemm<1,1>, cudaFuncAttributeMaxDynamicSharedMemorySize, GEMM_SMEM);
    cudaFuncSetAttribute((const void*)flash_attn,    cudaFuncAttributeMaxDynamicSharedMemorySize, FLASH_SMEM);
    cudaFuncSetAttribute((const void*)dec_self_attn, cudaFuncAttributeMaxDynamicSharedMemorySize, DEC_SMEM);

    const float* x_in      = (const float*)d_in[0];
    const float* y_in      = (const float*)d_in[1];
    const float* enc_Wq    = (const float*)d_in[2];
    const float* enc_Wk    = (const float*)d_in[3];
    const float* enc_Wv    = (const float*)d_in[4];
    const float* enc_ff_w1 = (const float*)d_in[5];
    const float* enc_ff_b1 = (const float*)d_in[6];
    const float* enc_ff_w2 = (const float*)d_in[7];
    const float* enc_ff_b2 = (const float*)d_in[8];
    const float* enc_ln1_g = (const float*)d_in[9];
    const float* enc_ln1_b = (const float*)d_in[10];
    const float* enc_ln2_g = (const float*)d_in[11];
    const float* enc_ln2_b = (const float*)d_in[12];
    const float* dec_Wq1   = (const float*)d_in[13];
    const float* dec_Wk1   = (const float*)d_in[14];
    const float* dec_Wv1   = (const float*)d_in[15];
    const float* dec_Wq2   = (const float*)d_in[16];
    const float* dec_Wk2   = (const float*)d_in[17];
    const float* dec_Wv2   = (const float*)d_in[18];
    const float* dec_ff_w1 = (const float*)d_in[19];
    const float* dec_ff_b1 = (const float*)d_in[20];
    const float* dec_ff_w2 = (const float*)d_in[21];
    const float* dec_ff_b2 = (const float*)d_in[22];
    const float* dec_ln1_g = (const float*)d_in[23];
    const float* dec_ln1_b = (const float*)d_in[24];
    const float* dec_ln2_g = (const float*)d_in[25];
    const float* dec_ln2_b = (const float*)d_in[26];
    const float* dec_ln3_g = (const float*)d_in[27];
    const float* dec_ln3_b = (const float*)d_in[28];

    uint32_t* wtf  = (uint32_t*)symv(g_wtf);
    uint32_t* q    = (uint32_t*)symv(g_q);
    uint32_t* k    = (uint32_t*)symv(g_k);
    uint32_t* v    = (uint32_t*)symv(g_v);
    uint32_t* h    = (uint32_t*)symv(g_h);
    uint32_t* xtf  = (uint32_t*)symv(g_xtf);
    uint32_t* x1tf = (uint32_t*)symv(g_x1tf);
    uint32_t* ytf  = (uint32_t*)symv(g_ytf);
    uint32_t* y1tf = (uint32_t*)symv(g_y1tf);
    uint32_t* y2tf = (uint32_t*)symv(g_y2tf);
    float* att = (float*)symv(g_att);
    float* x1  = (float*)symv(g_x1);
    float* gx  = (float*)symv(g_x);
    float* y1  = (float*)symv(g_y1);
    float* y2  = (float*)symv(g_y2);
    float* gy  = (float*)symv(g_y);
    float* qd  = (float*)symv(g_qd);
    float* kd  = (float*)symv(g_kd);
    float* vd  = (float*)symv(g_vd);

    // ---- pre-convert weights + inputs to tf32 bits (same rounding point as before) ----
    auto conv = [&](const float* src, uint32_t* dst, long long n) {
        int n4 = (int)(n >> 2);
        int blocks = (n4 + 255) / 256; if (blocks > 4096) blocks = 4096;
        cvt_tf32_kernel<<<blocks, 256>>>((const float4*)src, (uint4*)dst, n4);
    };
    conv(enc_Wq,    wtf + OFF_EWQ,  2LL*512*512);
    conv(enc_Wk,    wtf + OFF_EWK,  2LL*512*512);
    conv(enc_Wv,    wtf + OFF_EWV,  2LL*512*512);
    conv(enc_ff_w1, wtf + OFF_EW1,  2LL*512*2048);
    conv(enc_ff_w2, wtf + OFF_EW2,  2LL*2048*512);
    conv(dec_Wq1,   wtf + OFF_DWQ1, 2LL*512*512);
    conv(dec_Wk1,   wtf + OFF_DWK1, 2LL*512*512);
    conv(dec_Wv1,   wtf + OFF_DWV1, 2LL*512*512);
    conv(dec_Wq2,   wtf + OFF_DWQ2, 2LL*512*512);
    conv(dec_Wk2,   wtf + OFF_DWK2, 2LL*512*512);
    conv(dec_Wv2,   wtf + OFF_DWV2, 2LL*512*512);
    conv(dec_ff_w1, wtf + OFF_DW1,  2LL*512*2048);
    conv(dec_ff_w2, wtf + OFF_DW2,  2LL*2048*512);
    conv(x_in, xtf, (long long)M_ENC * DMODEL);
    conv(y_in, ytf, (long long)M_DEC * DMODEL);

    const long long WO = DMODEL * DMODEL;
    const long long FO1 = DMODEL * DFF;
    const long long FO2 = DFF * DMODEL;

    // -------- encoder --------
    const float* xc = x_in;   // fp32 view (residual); xtf = tf32 view (GEMM A)
    for (int i = 0; i < 2; i++) {
        mgemm(xtf, wtf + OFF_EWQ + i * WO, nullptr, q, M_ENC, DMODEL, DMODEL, 0, 1, 0.125f);
        mgemm(xtf, wtf + OFF_EWK + i * WO, nullptr, k, M_ENC, DMODEL, DMODEL, 0, 1, 1.f);
        mgemm(xtf, wtf + OFF_EWV + i * WO, nullptr, v, M_ENC, DMODEL, DMODEL, 0, 1, 1.f);
        flash_attn<<<dim3(T_ENC / 128, BHT), 256, FLASH_SMEM>>>(q, k, v, att, T_ENC, T_ENC);
        ln_res_kernel<<<M_ENC, 256>>>(xc, att, enc_ln1_g + i * DMODEL, enc_ln1_b + i * DMODEL, x1, x1tf);
        mgemm(x1tf, wtf + OFF_EW1 + i * FO1, enc_ff_b1 + i * DFF, h, M_ENC, DFF, DMODEL, 1, 1, 1.f);
        mgemm(h, wtf + OFF_EW2 + i * FO2, enc_ff_b2 + i * DMODEL, att, M_ENC, DMODEL, DFF, 0, 0, 1.f);
        ln_res_kernel<<<M_ENC, 256>>>(x1, att, enc_ln2_g + i * DMODEL, enc_ln2_b + i * DMODEL, gx, xtf);
        xc = gx;
    }

    // -------- decoder --------
    const float* yc = y_in;   // fp32 view; ytf = tf32 view
    for (int i = 0; i < 2; i++) {
        // masked self-attention: exact fp32 fused path (post-softmax -1e10 fill)
        mgemm(ytf, wtf + OFF_DWQ1 + i * WO, nullptr, qd, M_DEC, DMODEL, DMODEL, 0, 0, 1.f);
        mgemm(ytf, wtf + OFF_DWK1 + i * WO, nullptr, kd, M_DEC, DMODEL, DMODEL, 0, 0, 1.f);
        mgemm(ytf, wtf + OFF_DWV1 + i * WO, nullptr, vd, M_DEC, DMODEL, DMODEL, 0, 0, 1.f);
        dec_self_attn<<<BHT, 256, DEC_SMEM>>>(qd, kd, vd, att);
        ln_res_kernel<<<M_DEC, 256>>>(yc, att, dec_ln1_g + i * DMODEL, dec_ln1_b + i * DMODEL, y1, y1tf);

        // cross-attention (non-causal -> flash, all-tf32 operands)
        mgemm(y1tf, wtf + OFF_DWQ2 + i * WO, nullptr, q, M_DEC, DMODEL, DMODEL, 0, 1, 0.125f);
        mgemm(xtf, wtf + OFF_DWK2 + i * WO, nullptr, k, M_ENC, DMODEL, DMODEL, 0, 1, 1.f);
        mgemm(xtf, wtf + OFF_DWV2 + i * WO, nullptr, v, M_ENC, DMODEL, DMODEL, 0, 1, 1.f);
        flash_attn<<<dim3(1, BHT), 256, FLASH_SMEM>>>(q, k, v, att, T_DEC, T_ENC);
        ln_res_kernel<<<M_DEC, 256>>>(y1, att, dec_ln2_g + i * DMODEL, dec_ln2_b + i * DMODEL, y2, y2tf);

        // feed-forward
        mgemm(y2tf, wtf + OFF_DW1 + i * FO1, dec_ff_b1 + i * DFF, h, M_DEC, DFF, DMODEL, 1, 1, 1.f);
        mgemm(h, wtf + OFF_DW2 + i * FO2, dec_ff_b2 + i * DMODEL, att, M_DEC, DMODEL, DFF, 0, 0, 1.f);
        float* outp = (i == 1) ? (float*)d_out : gy;
        ln_res_kernel<<<M_DEC, 256>>>(y2, att, dec_ln3_g + i * DMODEL, dec_ln3_b + i * DMODEL,
                                      outp, (i == 1) ? nullptr : ytf);
        yc = gy;
    }
}

// round 7
// speedup vs baseline: 1.2308x; 1.0528x over previous
#include <cuda_runtime.h>
#include <cstdint>
#include <cstddef>

// ---------------- problem constants ----------------
#define BATCH   8
#define T_ENC   1024
#define T_DEC   100
#define DMODEL  512
#define NHEAD   8
#define DHEAD   64
#define DFF     2048
#define M_ENC   (BATCH * T_ENC)   // 8192
#define M_DEC   (BATCH * T_DEC)   // 800
#define BHT     (BATCH * NHEAD)   // 64
#define NQKV    1536
#define NKV     1024

// ---------------- fused tf32 weights ----------------
__device__ uint32_t w_eqkv[2 * DMODEL * NQKV];   // enc Wq(x0.125)|Wk|Wv
__device__ uint32_t w_ew1 [2 * DMODEL * DFF];
__device__ uint32_t w_ew2 [2 * DFF * DMODEL];
__device__ uint32_t w_dqkv1[2 * DMODEL * NQKV];  // dec self Wq|Wk|Wv (unscaled)
__device__ uint32_t w_dq2 [2 * DMODEL * DMODEL]; // dec cross Wq (x0.125)
__device__ uint32_t w_dkv2[2 * DMODEL * NKV];    // dec cross Wk|Wv
__device__ uint32_t w_dw1 [2 * DMODEL * DFF];
__device__ uint32_t w_dw2 [2 * DFF * DMODEL];

// ---------------- activations / scratch ----------------
__device__ uint32_t g_qkv [M_ENC * NQKV];        // enc fused QKV (tf32, q pre-scaled)
__device__ float    g_qkvd[M_DEC * NQKV];        // dec self QKV (fp32 exact)
__device__ uint32_t g_kv  [M_ENC * NKV];         // dec cross K|V (tf32)
__device__ uint32_t g_qx  [M_DEC * DMODEL];      // dec cross Q (tf32, pre-scaled)
__device__ uint32_t g_h   [M_ENC * DFF];         // FFN intermediate (tf32)
__device__ uint32_t g_xtf [M_ENC * DMODEL];
__device__ uint32_t g_x1tf[M_ENC * DMODEL];
__device__ uint32_t g_ytf [M_DEC * DMODEL];
__device__ uint32_t g_y1tf[M_DEC * DMODEL];
__device__ uint32_t g_y2tf[M_DEC * DMODEL];
__device__ float g_att [M_ENC * DMODEL];
__device__ float g_x1  [M_ENC * DMODEL];
__device__ float g_x   [M_ENC * DMODEL];
__device__ float g_y1  [M_DEC * DMODEL];
__device__ float g_y2  [M_DEC * DMODEL];
__device__ float g_y   [M_DEC * DMODEL];

__device__ __forceinline__ uint32_t f2tf32(float x) {
    uint32_t t;
    asm("cvt.rna.tf32.f32 %0, %1;" : "=r"(t) : "f"(x));
    return t;
}

__device__ __forceinline__ void mma8(float* c, const uint32_t* a, uint32_t b0, uint32_t b1) {
    asm volatile(
        "mma.sync.aligned.m16n8k8.row.col.f32.tf32.tf32.f32 "
        "{%0,%1,%2,%3}, {%4,%5,%6,%7}, {%8,%9}, {%0,%1,%2,%3};"
        : "+f"(c[0]), "+f"(c[1]), "+f"(c[2]), "+f"(c[3])
        : "r"(a[0]), "r"(a[1]), "r"(a[2]), "r"(a[3]), "r"(b0), "r"(b1));
}

__device__ __forceinline__ void cpasync16(uint32_t smem_dst, const void* gsrc, int bytes) {
    asm volatile("cp.async.ca.shared.global [%0], [%1], 16, %2;"
                 :: "r"(smem_dst), "l"(gsrc), "r"(bytes));
}

__device__ __forceinline__ uint4 cvt4(float4 v) {
    return make_uint4(f2tf32(v.x), f2tf32(v.y), f2tf32(v.z), f2tf32(v.w));
}

// ---------------- conversion / packing kernels (one-time per launch) ----------------
__global__ void cvt_tf32_kernel(const float4* __restrict__ in, uint4* __restrict__ out,
                                int n4, float scale) {
    for (int i = blockIdx.x * blockDim.x + threadIdx.x; i < n4; i += gridDim.x * blockDim.x) {
        float4 v = in[i];
        v.x *= scale; v.y *= scale; v.z *= scale; v.w *= scale;
        out[i] = cvt4(v);
    }
}

// pack 3x [K][512] -> [K][1536], scale0 applied to src0 (exact pow2)
__global__ void pack3_kernel(const float4* __restrict__ s0, const float4* __restrict__ s1,
                             const float4* __restrict__ s2, uint4* __restrict__ dst,
                             int K, float scale0) {
    int total = K * 384;
    for (int i = blockIdx.x * blockDim.x + threadIdx.x; i < total; i += gridDim.x * blockDim.x) {
        int k = i / 384, n4 = i - k * 384;
        float4 v;
        if (n4 < 128) {
            v = s0[k * 128 + n4];
            v.x *= scale0; v.y *= scale0; v.z *= scale0; v.w *= scale0;
        } else if (n4 < 256) {
            v = s1[k * 128 + n4 - 128];
        } else {
            v = s2[k * 128 + n4 - 256];
        }
        dst[i] = cvt4(v);
    }
}

// pack 2x [K][512] -> [K][1024]
__global__ void pack2_kernel(const float4* __restrict__ s0, const float4* __restrict__ s1,
                             uint4* __restrict__ dst, int K) {
    int total = K * 256;
    for (int i = blockIdx.x * blockDim.x + threadIdx.x; i < total; i += gridDim.x * blockDim.x) {
        int k = i / 256, n4 = i - k * 256;
        float4 v = (n4 < 128) ? s0[k * 128 + n4] : s1[k * 128 + n4 - 128];
        dst[i] = cvt4(v);
    }
}

// ================= 2-stage cp.async tf32 GEMM (zero cvt in mainloop) =================
#define GA_STRIDE 36
#define GB_STRIDE 132
#define GA_STAGE  (128 * GA_STRIDE)
#define GB_STAGE  (32 * GB_STRIDE)
#define GEMM_SMEM ((2 * GA_STAGE + 2 * GB_STAGE) * 4)

template<int RELU, int TF32OUT>
__global__ __launch_bounds__(256)
void mma_gemm(const uint32_t* __restrict__ A, const uint32_t* __restrict__ B,
              const float* __restrict__ bias, void* __restrict__ Cv,
              int M, int N, int K)
{
    extern __shared__ uint32_t gsm[];
    uint32_t* Asf = gsm;
    uint32_t* Bsf = gsm + 2 * GA_STAGE;

    const int tid  = threadIdx.x;
    const int wid  = tid >> 5, lane = tid & 31;
    const int wm   = wid & 1, wn = wid >> 1;
    const int g    = lane >> 2, tig = lane & 3;
    const int m0   = blockIdx.y * 128, n0 = blockIdx.x * 128;

    const uint32_t aBase = (uint32_t)__cvta_generic_to_shared(Asf);
    const uint32_t bBase = (uint32_t)__cvta_generic_to_shared(Bsf);

    float acc[4][4][4];
    #pragma unroll
    for (int i = 0; i < 4; i++)
        #pragma unroll
        for (int j = 0; j < 4; j++)
            #pragma unroll
            for (int c = 0; c < 4; c++) acc[i][j][c] = 0.f;

    auto issue = [&](int s, int k0) {
        #pragma unroll
        for (int i = 0; i < 4; i++) {
            int idx = tid + (i << 8);
            int r = idx >> 3, kk4 = (idx & 7) << 2;
            int m = m0 + r;
            const uint32_t* src = A + (size_t)(m < M ? m : 0) * K + k0 + kk4;
            cpasync16(aBase + (s * GA_STAGE + r * GA_STRIDE + kk4) * 4, src, (m < M) ? 16 : 0);
        }
        #pragma unroll
        for (int i = 0; i < 4; i++) {
            int idx = tid + (i << 8);
            int kk = idx >> 5, n4 = (idx & 31) << 2;
            const uint32_t* src = B + (size_t)(k0 + kk) * N + n0 + n4;
            cpasync16(bBase + (s * GB_STAGE + kk * GB_STRIDE + n4) * 4, src, 16);
        }
        asm volatile("cp.async.commit_group;");
    };

    const int nk = K >> 5;
    issue(0, 0);

    for (int kt = 0; kt < nk; kt++) {
        const int s = kt & 1;
        if (kt + 1 < nk) {
            issue(s ^ 1, (kt + 1) << 5);
            asm volatile("cp.async.wait_group 1;");
        } else {
            asm volatile("cp.async.wait_group 0;");
        }
        __syncthreads();

        const uint32_t* As = Asf + s * GA_STAGE;
        const uint32_t* Bs = Bsf + s * GB_STAGE;
        #pragma unroll
        for (int ks = 0; ks < 32; ks += 8) {
            uint32_t af[4][4];
            #pragma unroll
            for (int mi = 0; mi < 4; mi++) {
                int mr = wm * 64 + mi * 16;
                af[mi][0] = As[(mr + g    ) * GA_STRIDE + ks + tig    ];
                af[mi][1] = As[(mr + g + 8) * GA_STRIDE + ks + tig    ];
                af[mi][2] = As[(mr + g    ) * GA_STRIDE + ks + tig + 4];
                af[mi][3] = As[(mr + g + 8) * GA_STRIDE + ks + tig + 4];
            }
            uint32_t bf[4][2];
            #pragma unroll
            for (int ni = 0; ni < 4; ni++) {
                int nc = wn * 32 + ni * 8 + g;
                bf[ni][0] = Bs[(ks + tig    ) * GB_STRIDE + nc];
                bf[ni][1] = Bs[(ks + tig + 4) * GB_STRIDE + nc];
            }
            #pragma unroll
            for (int mi = 0; mi < 4; mi++)
                #pragma unroll
                for (int ni = 0; ni < 4; ni++)
                    mma8(acc[mi][ni], af[mi], bf[ni][0], bf[ni][1]);
        }
        __syncthreads();
    }

    #pragma unroll
    for (int mi = 0; mi < 4; mi++) {
        int mb = m0 + wm * 64 + mi * 16;
        #pragma unroll
        for (int ni = 0; ni < 4; ni++) {
            int nb = n0 + wn * 32 + ni * 8 + 2 * tig;
            #pragma unroll
            for (int half = 0; half < 2; half++) {
                int m = mb + g + half * 8;
                if (m < M) {
                    float v0 = acc[mi][ni][half * 2    ];
                    float v1 = acc[mi][ni][half * 2 + 1];
                    if (bias) { v0 += bias[nb]; v1 += bias[nb + 1]; }
                    if (RELU) { v0 = fmaxf(v0, 0.f); v1 = fmaxf(v1, 0.f); }
                    if (TF32OUT) {
                        *(uint2*)((uint32_t*)Cv + (size_t)m * N + nb) =
                            make_uint2(f2tf32(v0), f2tf32(v1));
                    } else {
                        *(float2*)((float*)Cv + (size_t)m * N + nb) = make_float2(v0, v1);
                    }
                }
            }
        }
    }
}

// ================= fused flash attention (non-causal, exact) =================
// Q/K/V are tf32 bits with row strides ldq/ldkv (fused QKV buffers). Q pre-scaled.
#define FQ_STRIDE 68
#define FKV_STAGE (64 * FQ_STRIDE)
#define FLASH_SMEM ((128 * FQ_STRIDE + 4 * FKV_STAGE) * 4)

__global__ __launch_bounds__(256, 2)
void flash_attn(const uint32_t* __restrict__ Qg, int ldq,
                const uint32_t* __restrict__ Kg, const uint32_t* __restrict__ Vg, int ldkv,
                float* __restrict__ Og, int Tq, int Tk)
{
    extern __shared__ uint32_t fsm[];
    uint32_t* Qs   = fsm;
    uint32_t* Kraw = fsm + 128 * FQ_STRIDE;
    uint32_t* Vraw = Kraw + 2 * FKV_STAGE;

    const int bh = blockIdx.y;
    const int b = bh >> 3, h = bh & 7;
    const int q0 = blockIdx.x * 128;
    const int tid = threadIdx.x;
    const int wid = tid >> 5, lane = tid & 31;
    const int g = lane >> 2, tig = lane & 3;
    const int mr = wid * 16;

    const uint32_t* qp = Qg + (size_t)b * Tq * ldq + h * DHEAD;
    const uint32_t* kp = Kg + (size_t)b * Tk * ldkv + h * DHEAD;
    const uint32_t* vp = Vg + (size_t)b * Tk * ldkv + h * DHEAD;

    const uint32_t qBase = (uint32_t)__cvta_generic_to_shared(Qs);
    const uint32_t kBase = (uint32_t)__cvta_generic_to_shared(Kraw);
    const uint32_t vBase = (uint32_t)__cvta_generic_to_shared(Vraw);

    auto issueKV = [&](int s, int kt) {
        #pragma unroll
        for (int i = 0; i < 4; i++) {
            int idx = tid + (i << 8);
            int r = idx >> 4, d4 = (idx & 15) << 2;
            cpasync16(kBase + (s * FKV_STAGE + r * FQ_STRIDE + d4) * 4,
                      kp + (size_t)(kt + r) * ldkv + d4, 16);
            cpasync16(vBase + (s * FKV_STAGE + r * FQ_STRIDE + d4) * 4,
                      vp + (size_t)(kt + r) * ldkv + d4, 16);
        }
        asm volatile("cp.async.commit_group;");
    };

    issueKV(0, 0);
    #pragma unroll
    for (int i = 0; i < 8; i++) {
        int idx = tid + (i << 8);
        int r = idx >> 4, d4 = (idx & 15) << 2;
        int q = q0 + r;
        cpasync16(qBase + (r * FQ_STRIDE + d4) * 4,
                  qp + (size_t)(q < Tq ? q : 0) * ldq + d4, (q < Tq) ? 16 : 0);
    }
    asm volatile("cp.async.commit_group;");

    float o[8][4];
    #pragma unroll
    for (int ni = 0; ni < 8; ni++)
        #pragma unroll
        for (int c = 0; c < 4; c++) o[ni][c] = 0.f;
    float m0 = -1e30f, m1 = -1e30f, l0 = 0.f, l1 = 0.f;

    const int srcA = (lane & ~3) | (tig >> 1);
    const int srcB = srcA + 2;
    const bool odd = tig & 1;

    const int nt = Tk >> 6;
    for (int kt = 0; kt < nt; kt++) {
        const int s = kt & 1;
        if (kt + 1 < nt) {
            issueKV(s ^ 1, (kt + 1) << 6);
            asm volatile("cp.async.wait_group 1;");
        } else {
            asm volatile("cp.async.wait_group 0;");
        }
        __syncthreads();

        const uint32_t* Ks = Kraw + s * FKV_STAGE;
        const uint32_t* Vs = Vraw + s * FKV_STAGE;

        float sfr[8][4];
        #pragma unroll
        for (int ni = 0; ni < 8; ni++)
            #pragma unroll
            for (int c = 0; c < 4; c++) sfr[ni][c] = 0.f;
        #pragma unroll
        for (int ks = 0; ks < 64; ks += 8) {
            uint32_t af[4];
            af[0] = Qs[(mr + g    ) * FQ_STRIDE + ks + tig    ];
            af[1] = Qs[(mr + g + 8) * FQ_STRIDE + ks + tig    ];
            af[2] = Qs[(mr + g    ) * FQ_STRIDE + ks + tig + 4];
            af[3] = Qs[(mr + g + 8) * FQ_STRIDE + ks + tig + 4];
            #pragma unroll
            for (int ni = 0; ni < 8; ni++) {
                uint32_t b0 = Ks[(ni * 8 + g) * FQ_STRIDE + ks + tig    ];
                uint32_t b1 = Ks[(ni * 8 + g) * FQ_STRIDE + ks + tig + 4];
                mma8(sfr[ni], af, b0, b1);
            }
        }

        float tmax0 = -1e30f, tmax1 = -1e30f;
        #pragma unroll
        for (int ni = 0; ni < 8; ni++) {
            tmax0 = fmaxf(tmax0, fmaxf(sfr[ni][0], sfr[ni][1]));
            tmax1 = fmaxf(tmax1, fmaxf(sfr[ni][2], sfr[ni][3]));
        }
        #pragma unroll
        for (int off = 1; off <= 2; off <<= 1) {
            tmax0 = fmaxf(tmax0, __shfl_xor_sync(0xffffffffu, tmax0, off));
            tmax1 = fmaxf(tmax1, __shfl_xor_sync(0xffffffffu, tmax1, off));
        }
        const float mn0 = fmaxf(m0, tmax0), mn1 = fmaxf(m1, tmax1);
        const float a0 = __expf(m0 - mn0), a1 = __expf(m1 - mn1);
        float rs0 = 0.f, rs1 = 0.f;
        uint32_t pf[8][4];
        #pragma unroll
        for (int ni = 0; ni < 8; ni++) {
            float p0 = __expf(sfr[ni][0] - mn0);
            float p1 = __expf(sfr[ni][1] - mn0);
            float p2 = __expf(sfr[ni][2] - mn1);
            float p3 = __expf(sfr[ni][3] - mn1);
            rs0 += p0 + p1; rs1 += p2 + p3;
            pf[ni][0] = f2tf32(p0); pf[ni][1] = f2tf32(p1);
            pf[ni][2] = f2tf32(p2); pf[ni][3] = f2tf32(p3);
        }
        #pragma unroll
        for (int off = 1; off <= 2; off <<= 1) {
            rs0 += __shfl_xor_sync(0xffffffffu, rs0, off);
            rs1 += __shfl_xor_sync(0xffffffffu, rs1, off);
        }
        l0 = l0 * a0 + rs0; l1 = l1 * a1 + rs1;
        m0 = mn0; m1 = mn1;
        #pragma unroll
        for (int ni = 0; ni < 8; ni++) {
            o[ni][0] *= a0; o[ni][1] *= a0;
            o[ni][2] *= a1; o[ni][3] *= a1;
        }

        #pragma unroll
        for (int j = 0; j < 8; j++) {
            uint32_t r0a = __shfl_sync(0xffffffffu, pf[j][0], srcA);
            uint32_t r1a = __shfl_sync(0xffffffffu, pf[j][1], srcA);
            uint32_t r2a = __shfl_sync(0xffffffffu, pf[j][2], srcA);
            uint32_t r3a = __shfl_sync(0xffffffffu, pf[j][3], srcA);
            uint32_t r0b = __shfl_sync(0xffffffffu, pf[j][0], srcB);
            uint32_t r1b = __shfl_sync(0xffffffffu, pf[j][1], srcB);
            uint32_t r2b = __shfl_sync(0xffffffffu, pf[j][2], srcB);
            uint32_t r3b = __shfl_sync(0xffffffffu, pf[j][3], srcB);
            uint32_t af[4];
            af[0] = odd ? r1a : r0a;
            af[1] = odd ? r3a : r2a;
            af[2] = odd ? r1b : r0b;
            af[3] = odd ? r3b : r2b;
            const int ks = j * 8;
            #pragma unroll
            for (int ni = 0; ni < 8; ni++) {
                uint32_t b0 = Vs[(ks + tig    ) * FQ_STRIDE + ni * 8 + g];
                uint32_t b1 = Vs[(ks + tig + 4) * FQ_STRIDE + ni * 8 + g];
                mma8(o[ni], af, b0, b1);
            }
        }
        __syncthreads();
    }

    const float i0 = 1.f / l0, i1 = 1.f / l1;
    #pragma unroll
    for (int ni = 0; ni < 8; ni++) {
        int col = h * DHEAD + ni * 8 + 2 * tig;
        int r0 = q0 + mr + g, r1 = r0 + 8;
        if (r0 < Tq)
            *(float2*)(Og + (size_t)(b * Tq + r0) * DMODEL + col) =
                make_float2(o[ni][0] * i0, o[ni][1] * i0);
        if (r1 < Tq)
            *(float2*)(Og + (size_t)(b * Tq + r1) * DMODEL + col) =
                make_float2(o[ni][2] * i1, o[ni][3] * i1);
    }
}

// ================= fused decoder self-attention (exact fp32) =================
// Reads fused QKV buffer [M_DEC][1536] fp32 (q|k|v at col 0|512|1024).
#define DS_STRIDE 68
#define DS_SSTRIDE 104
#define DEC_SMEM ((3 * T_DEC * DS_STRIDE + T_DEC * DS_SSTRIDE) * 4)

__global__ __launch_bounds__(256)
void dec_self_attn(const float* __restrict__ QKV, float* __restrict__ Og)
{
    extern __shared__ float dsm[];
    float* Qd = dsm;
    float* Kd = Qd + T_DEC * DS_STRIDE;
    float* Vd = Kd + T_DEC * DS_STRIDE;
    float* Sd = Vd + T_DEC * DS_STRIDE;

    const int bh = blockIdx.x;
    const int b = bh >> 3, h = bh & 7;
    const int tid = threadIdx.x;
    const int wid = tid >> 5, lane = tid & 31;

    const float* qp = QKV + (size_t)b * T_DEC * NQKV + h * DHEAD;
    const float* kp = qp + 512;
    const float* vp = qp + 1024;

    for (int idx = tid; idx < T_DEC * 16; idx += 256) {
        int r = idx >> 4, d4 = (idx & 15) << 2;
        *(float4*)&Qd[r * DS_STRIDE + d4] = *(const float4*)(qp + (size_t)r * NQKV + d4);
        *(float4*)&Kd[r * DS_STRIDE + d4] = *(const float4*)(kp + (size_t)r * NQKV + d4);
        *(float4*)&Vd[r * DS_STRIDE + d4] = *(const float4*)(vp + (size_t)r * NQKV + d4);
    }
    __syncthreads();

    for (int e = tid; e < T_DEC * T_DEC; e += 256) {
        int q = e / T_DEC, kk = e - q * T_DEC;
        const float* qr = &Qd[q * DS_STRIDE];
        const float* kr = &Kd[kk * DS_STRIDE];
        float acc = 0.f;
        #pragma unroll
        for (int d = 0; d < 64; d++) acc += qr[d] * kr[d];
        Sd[q * DS_SSTRIDE + kk] = acc * 0.125f;
    }
    __syncthreads();

    for (int q = wid; q < T_DEC; q += 8) {
        float* row = &Sd[q * DS_SSTRIDE];
        float r0 = (lane      < T_DEC) ? row[lane]      : -1e30f;
        float r1 = (lane + 32 < T_DEC) ? row[lane + 32] : -1e30f;
        float r2 = (lane + 64 < T_DEC) ? row[lane + 64] : -1e30f;
        float r3 = (lane + 96 < T_DEC) ? row[lane + 96] : -1e30f;
        float m = fmaxf(fmaxf(r0, r1), fmaxf(r2, r3));
        #pragma unroll
        for (int off = 16; off; off >>= 1) m = fmaxf(m, __shfl_xor_sync(0xffffffffu, m, off));
        float e0 = expf(r0 - m), e1 = expf(r1 - m), e2 = expf(r2 - m), e3 = expf(r3 - m);
        if (lane      >= T_DEC) e0 = 0.f;
        if (lane + 32 >= T_DEC) e1 = 0.f;
        if (lane + 64 >= T_DEC) e2 = 0.f;
        if (lane + 96 >= T_DEC) e3 = 0.f;
        float s = e0 + e1 + e2 + e3;
        #pragma unroll
        for (int off = 16; off; off >>= 1) s += __shfl_xor_sync(0xffffffffu, s, off);
        const float inv = 1.f / s;
        if (lane      < T_DEC) row[lane]      = (lane      > q) ? -1e10f : e0 * inv;
        if (lane + 32 < T_DEC) row[lane + 32] = (lane + 32 > q) ? -1e10f : e1 * inv;
        if (lane + 64 < T_DEC) row[lane + 64] = (lane + 64 > q) ? -1e10f : e2 * inv;
        if (lane + 96 < T_DEC) row[lane + 96] = (lane + 96 > q) ? -1e10f : e3 * inv;
    }
    __syncthreads();

    for (int e = tid; e < T_DEC * 64; e += 256) {
        int q = e >> 6, d = e & 63;
        const float* pr = &Sd[q * DS_SSTRIDE];
        float acc = 0.f;
        #pragma unroll 4
        for (int kk = 0; kk < T_DEC; kk++) acc += pr[kk] * Vd[kk * DS_STRIDE + d];
        Og[(size_t)(b * T_DEC + q) * DMODEL + h * DHEAD + d] = acc;
    }
}

// ---------------- fused residual + LayerNorm (fp32 out + optional tf32 out) ----------------
__global__ void ln_res_kernel(const float* __restrict__ A, const float* __restrict__ Bv,
                              const float* __restrict__ g, const float* __restrict__ be,
                              float* __restrict__ O, uint32_t* __restrict__ Otf) {
    const int row = blockIdx.x;
    const float* a = A + (size_t)row * DMODEL;
    const float* b = Bv + (size_t)row * DMODEL;
    __shared__ float red[256];
    const int tid = threadIdx.x;

    float v0 = a[tid] + b[tid];
    float v1 = a[tid + 256] + b[tid + 256];

    red[tid] = v0 + v1; __syncthreads();
    for (int s = 128; s > 0; s >>= 1) { if (tid < s) red[tid] += red[tid + s]; __syncthreads(); }
    const float mean = red[0] * (1.f / DMODEL); __syncthreads();

    float d0 = v0 - mean, d1 = v1 - mean;
    red[tid] = d0 * d0 + d1 * d1; __syncthreads();
    for (int s = 128; s > 0; s >>= 1) { if (tid < s) red[tid] += red[tid + s]; __syncthreads(); }
    const float inv = rsqrtf(red[0] * (1.f / DMODEL) + 1e-5f);

    const float o0 = d0 * inv * g[tid]       + be[tid];
    const float o1 = d1 * inv * g[tid + 256] + be[tid + 256];
    O[(size_t)row * DMODEL + tid]       = o0;
    O[(size_t)row * DMODEL + tid + 256] = o1;
    if (Otf) {
        Otf[(size_t)row * DMODEL + tid]       = f2tf32(o0);
        Otf[(size_t)row * DMODEL + tid + 256] = f2tf32(o1);
    }
}

// ---------------- host orchestration ----------------
static inline void mgemm(const uint32_t* A, const uint32_t* B, const float* bias, void* C,
                         int M, int N, int K, int relu, int tf32out) {
    dim3 grid(N / 128, (M + 127) / 128);
    if (relu && tf32out)
        mma_gemm<1, 1><<<grid, 256, GEMM_SMEM>>>(A, B, bias, C, M, N, K);
    else if (tf32out)
        mma_gemm<0, 1><<<grid, 256, GEMM_SMEM>>>(A, B, bias, C, M, N, K);
    else
        mma_gemm<0, 0><<<grid, 256, GEMM_SMEM>>>(A, B, bias, C, M, N, K);
}

template <typename T>
static inline void* symv(T& s) {
    void* p = nullptr;
    cudaGetSymbolAddress(&p, s);
    return p;
}

extern "C" void kernel_launch(void* const* d_in, const int* in_sizes, int n_in,
                              void* d_out, int out_size) {
    (void)in_sizes; (void)n_in; (void)out_size;

    cudaFuncSetAttribute((const void*)mma_gemm<0,0>, cudaFuncAttributeMaxDynamicSharedMemorySize, GEMM_SMEM);
    cudaFuncSetAttribute((const void*)mma_gemm<0,1>, cudaFuncAttributeMaxDynamicSharedMemorySize, GEMM_SMEM);
    cudaFuncSetAttribute((const void*)mma_gemm<1,1>, cudaFuncAttributeMaxDynamicSharedMemorySize, GEMM_SMEM);
    cudaFuncSetAttribute((const void*)flash_attn,    cudaFuncAttributeMaxDynamicSharedMemorySize, FLASH_SMEM);
    cudaFuncSetAttribute((const void*)dec_self_attn, cudaFuncAttributeMaxDynamicSharedMemorySize, DEC_SMEM);

    const float* x_in      = (const float*)d_in[0];
    const float* y_in      = (const float*)d_in[1];
    const float* enc_Wq    = (const float*)d_in[2];
    const float* enc_Wk    = (const float*)d_in[3];
    const float* enc_Wv    = (const float*)d_in[4];
    const float* enc_ff_w1 = (const float*)d_in[5];
    const float* enc_ff_b1 = (const float*)d_in[6];
    const float* enc_ff_w2 = (const float*)d_in[7];
    const float* enc_ff_b2 = (const float*)d_in[8];
    const float* enc_ln1_g = (const float*)d_in[9];
    const float* enc_ln1_b = (const float*)d_in[10];
    const float* enc_ln2_g = (const float*)d_in[11];
    const float* enc_ln2_b = (const float*)d_in[12];
    const float* dec_Wq1   = (const float*)d_in[13];
    const float* dec_Wk1   = (const float*)d_in[14];
    const float* dec_Wv1   = (const float*)d_in[15];
    const float* dec_Wq2   = (const float*)d_in[16];
    const float* dec_Wk2   = (const float*)d_in[17];
    const float* dec_Wv2   = (const float*)d_in[18];
    const float* dec_ff_w1 = (const float*)d_in[19];
    const float* dec_ff_b1 = (const float*)d_in[20];
    const float* dec_ff_w2 = (const float*)d_in[21];
    const float* dec_ff_b2 = (const float*)d_in[22];
    const float* dec_ln1_g = (const float*)d_in[23];
    const float* dec_ln1_b = (const float*)d_in[24];
    const float* dec_ln2_g = (const float*)d_in[25];
    const float* dec_ln2_b = (const float*)d_in[26];
    const float* dec_ln3_g = (const float*)d_in[27];
    const float* dec_ln3_b = (const float*)d_in[28];

    uint32_t* eqkvW = (uint32_t*)symv(w_eqkv);
    uint32_t* ew1   = (uint32_t*)symv(w_ew1);
    uint32_t* ew2   = (uint32_t*)symv(w_ew2);
    uint32_t* dqkv1 = (uint32_t*)symv(w_dqkv1);
    uint32_t* dq2   = (uint32_t*)symv(w_dq2);
    uint32_t* dkv2  = (uint32_t*)symv(w_dkv2);
    uint32_t* dw1   = (uint32_t*)symv(w_dw1);
    uint32_t* dw2   = (uint32_t*)symv(w_dw2);

    uint32_t* qkv  = (uint32_t*)symv(g_qkv);
    float*    qkvd = (float*)symv(g_qkvd);
    uint32_t* kv   = (uint32_t*)symv(g_kv);
    uint32_t* qx   = (uint32_t*)symv(g_qx);
    uint32_t* h    = (uint32_t*)symv(g_h);
    uint32_t* xtf  = (uint32_t*)symv(g_xtf);
    uint32_t* x1tf = (uint32_t*)symv(g_x1tf);
    uint32_t* ytf  = (uint32_t*)symv(g_ytf);
    uint32_t* y1tf = (uint32_t*)symv(g_y1tf);
    uint32_t* y2tf = (uint32_t*)symv(g_y2tf);
    float* att = (float*)symv(g_att);
    float* x1  = (float*)symv(g_x1);
    float* gx  = (float*)symv(g_x);
    float* y1  = (float*)symv(g_y1);
    float* y2  = (float*)symv(g_y2);
    float* gy  = (float*)symv(g_y);

    // ---- weight packing / conversion (rounding points identical to R6) ----
    const long long WO = DMODEL * DMODEL;
    const long long FO1 = DMODEL * DFF;
    const long long FO2 = DFF * DMODEL;
    auto conv = [&](const float* src, uint32_t* dst, long long n, float sc) {
        int n4 = (int)(n >> 2);
        int blocks = (n4 + 255) / 256; if (blocks > 2048) blocks = 2048;
        cvt_tf32_kernel<<<blocks, 256>>>((const float4*)src, (uint4*)dst, n4, sc);
    };
    for (int i = 0; i < 2; i++) {
        pack3_kernel<<<768, 256>>>((const float4*)(enc_Wq + i * WO), (const float4*)(enc_Wk + i * WO),
                                   (const float4*)(enc_Wv + i * WO),
                                   (uint4*)(eqkvW + (size_t)i * DMODEL * NQKV), DMODEL, 0.125f);
        pack3_kernel<<<768, 256>>>((const float4*)(dec_Wq1 + i * WO), (const float4*)(dec_Wk1 + i * WO),
                                   (const float4*)(dec_Wv1 + i * WO),
                                   (uint4*)(dqkv1 + (size_t)i * DMODEL * NQKV), DMODEL, 1.f);
        pack2_kernel<<<512, 256>>>((const float4*)(dec_Wk2 + i * WO), (const float4*)(dec_Wv2 + i * WO),
                                   (uint4*)(dkv2 + (size_t)i * DMODEL * NKV), DMODEL);
        conv(dec_Wq2 + i * WO, dq2 + i * WO, WO, 0.125f);
    }
    conv(enc_ff_w1, ew1, 2 * FO1, 1.f);
    conv(enc_ff_w2, ew2, 2 * FO2, 1.f);
    conv(dec_ff_w1, dw1, 2 * FO1, 1.f);
    conv(dec_ff_w2, dw2, 2 * FO2, 1.f);
    conv(x_in, xtf, (long long)M_ENC * DMODEL, 1.f);
    conv(y_in, ytf, (long long)M_DEC * DMODEL, 1.f);

    // -------- encoder --------
    const float* xc = x_in;
    for (int i = 0; i < 2; i++) {
        mgemm(xtf, eqkvW + (size_t)i * DMODEL * NQKV, nullptr, qkv, M_ENC, NQKV, DMODEL, 0, 1);
        flash_attn<<<dim3(T_ENC / 128, BHT), 256, FLASH_SMEM>>>(
            qkv, NQKV, qkv + 512, qkv + 1024, NQKV, att, T_ENC, T_ENC);
        ln_res_kernel<<<M_ENC, 256>>>(xc, att, enc_ln1_g + i * DMODEL, enc_ln1_b + i * DMODEL, x1, x1tf);
        mgemm(x1tf, ew1 + (size_t)i * FO1, enc_ff_b1 + i * DFF, h, M_ENC, DFF, DMODEL, 1, 1);
        mgemm(h, ew2 + (size_t)i * FO2, enc_ff_b2 + i * DMODEL, att, M_ENC, DMODEL, DFF, 0, 0);
        ln_res_kernel<<<M_ENC, 256>>>(x1, att, enc_ln2_g + i * DMODEL, enc_ln2_b + i * DMODEL, gx, xtf);
        xc = gx;
    }

    // -------- decoder --------
    const float* yc = y_in;
    for (int i = 0; i < 2; i++) {
        // masked self-attention: exact fp32 fused path (post-softmax -1e10 fill)
        mgemm(ytf, dqkv1 + (size_t)i * DMODEL * NQKV, nullptr, qkvd, M_DEC, NQKV, DMODEL, 0, 0);
        dec_self_attn<<<BHT, 256, DEC_SMEM>>>(qkvd, att);
        ln_res_kernel<<<M_DEC, 256>>>(yc, att, dec_ln1_g + i * DMODEL, dec_ln1_b + i * DMODEL, y1, y1tf);

        // cross-attention (non-causal -> flash)
        mgemm(y1tf, dq2 + i * WO, nullptr, qx, M_DEC, DMODEL, DMODEL, 0, 1);
        mgemm(xtf, dkv2 + (size_t)i * DMODEL * NKV, nullptr, kv, M_ENC, NKV, DMODEL, 0, 1);
        flash_attn<<<dim3(1, BHT), 256, FLASH_SMEM>>>(
            qx, DMODEL, kv, kv + 512, NKV, att, T_DEC, T_ENC);
        ln_res_kernel<<<M_DEC, 256>>>(y1, att, dec_ln2_g + i * DMODEL, dec_ln2_b + i * DMODEL, y2, y2tf);

        // feed-forward
        mgemm(y2tf, dw1 + (size_t)i * FO1, dec_ff_b1 + i * DFF, h, M_DEC, DFF, DMODEL, 1, 1);
        mgemm(h, dw2 + (size_t)i * FO2, dec_ff_b2 + i * DMODEL, att, M_DEC, DMODEL, DFF, 0, 0);
        float* outp = (i == 1) ? (float*)d_out : gy;
        ln_res_kernel<<<M_DEC, 256>>>(y2, att, dec_ln3_g + i * DMODEL, dec_ln3_b + i * DMODEL,
                                      outp, (i == 1) ? nullptr : ytf);
        yc = gy;
    }
}

// round 8
// speedup vs baseline: 1.2705x; 1.0323x over previous
#include <cuda_runtime.h>
#include <cstdint>
#include <cstddef>

// ---------------- problem constants ----------------
#define BATCH   8
#define T_ENC   1024
#define T_DEC   100
#define DMODEL  512
#define NHEAD   8
#define DHEAD   64
#define DFF     2048
#define M_ENC   (BATCH * T_ENC)   // 8192
#define M_DEC   (BATCH * T_DEC)   // 800
#define BHT     (BATCH * NHEAD)   // 64
#define NQKV    1536
#define NKV2    2048              // both decoder layers' K|V fused along N

// ---------------- fused tf32 weights ----------------
__device__ uint32_t w_eqkv[2 * DMODEL * NQKV];   // enc Wq(x0.125)|Wk|Wv per layer
__device__ uint32_t w_ew1 [2 * DMODEL * DFF];
__device__ uint32_t w_ew2 [2 * DFF * DMODEL];
__device__ uint32_t w_dqkv1[2 * DMODEL * NQKV];  // dec self Wq|Wk|Wv (unscaled)
__device__ uint32_t w_dq2 [2 * DMODEL * DMODEL]; // dec cross Wq (x0.125)
__device__ uint32_t w_dkv2[DMODEL * NKV2];       // dec cross K0|V0|K1|V1
__device__ uint32_t w_dw1 [2 * DMODEL * DFF];
__device__ uint32_t w_dw2 [2 * DFF * DMODEL];

// ---------------- activations / scratch ----------------
__device__ uint32_t g_qkv [M_ENC * NQKV];        // enc fused QKV (tf32, q pre-scaled)
__device__ float    g_qkvd[M_DEC * NQKV];        // dec self QKV (fp32 exact)
__device__ uint32_t g_kv  [M_ENC * NKV2];        // dec cross K|V both layers (tf32)
__device__ uint32_t g_qx  [M_DEC * DMODEL];      // dec cross Q (tf32, pre-scaled)
__device__ uint32_t g_h   [M_ENC * DFF];         // FFN intermediate (tf32)
__device__ uint32_t g_xtf [M_ENC * DMODEL];
__device__ uint32_t g_x1tf[M_ENC * DMODEL];
__device__ uint32_t g_ytf [M_DEC * DMODEL];
__device__ uint32_t g_y1tf[M_DEC * DMODEL];
__device__ uint32_t g_y2tf[M_DEC * DMODEL];
__device__ float g_att [M_ENC * DMODEL];
__device__ float g_x1  [M_ENC * DMODEL];
__device__ float g_x   [M_ENC * DMODEL];
__device__ float g_y1  [M_DEC * DMODEL];
__device__ float g_y2  [M_DEC * DMODEL];
__device__ float g_y   [M_DEC * DMODEL];

__device__ __forceinline__ uint32_t f2tf32(float x) {
    uint32_t t;
    asm("cvt.rna.tf32.f32 %0, %1;" : "=r"(t) : "f"(x));
    return t;
}

__device__ __forceinline__ void mma8(float* c, const uint32_t* a, uint32_t b0, uint32_t b1) {
    asm volatile(
        "mma.sync.aligned.m16n8k8.row.col.f32.tf32.tf32.f32 "
        "{%0,%1,%2,%3}, {%4,%5,%6,%7}, {%8,%9}, {%0,%1,%2,%3};"
        : "+f"(c[0]), "+f"(c[1]), "+f"(c[2]), "+f"(c[3])
        : "r"(a[0]), "r"(a[1]), "r"(a[2]), "r"(a[3]), "r"(b0), "r"(b1));
}

// ldmatrix x4 on 8x(4xb32) tiles (16B rows; type-agnostic)
__device__ __forceinline__ void ldsm4(uint32_t& r0, uint32_t& r1, uint32_t& r2, uint32_t& r3,
                                      uint32_t addr) {
    asm volatile("ldmatrix.sync.aligned.m8n8.x4.shared.b16 {%0,%1,%2,%3}, [%4];"
                 : "=r"(r0), "=r"(r1), "=r"(r2), "=r"(r3) : "r"(addr));
}

__device__ __forceinline__ void cpasync16(uint32_t smem_dst, const void* gsrc, int bytes) {
    asm volatile("cp.async.ca.shared.global [%0], [%1], 16, %2;"
                 :: "r"(smem_dst), "l"(gsrc), "r"(bytes));
}

__device__ __forceinline__ uint4 cvt4(float4 v) {
    return make_uint4(f2tf32(v.x), f2tf32(v.y), f2tf32(v.z), f2tf32(v.w));
}

// ---------------- conversion / packing (4 launches total) ----------------
struct ConvJob { const float4* src; uint4* dst; int n4; float scale; };
struct ConvJobs { ConvJob j[8]; };

__global__ void conv_multi_kernel(ConvJobs jobs, int njobs) {
    int seg = blockIdx.y;
    if (seg >= njobs) return;
    ConvJob jb = jobs.j[seg];
    for (int i = blockIdx.x * blockDim.x + threadIdx.x; i < jb.n4; i += gridDim.x * blockDim.x) {
        float4 v = jb.src[i];
        v.x *= jb.scale; v.y *= jb.scale; v.z *= jb.scale; v.w *= jb.scale;
        jb.dst[i] = cvt4(v);
    }
}

// pack 3x [K][512] -> [K][1536], scale0 on src0 (exact pow2). K spans both layers.
__global__ void pack3_kernel(const float4* __restrict__ s0, const float4* __restrict__ s1,
                             const float4* __restrict__ s2, uint4* __restrict__ dst,
                             int K, float scale0) {
    int total = K * 384;
    for (int i = blockIdx.x * blockDim.x + threadIdx.x; i < total; i += gridDim.x * blockDim.x) {
        int k = i / 384, n4 = i - k * 384;
        float4 v;
        if (n4 < 128) {
            v = s0[k * 128 + n4];
            v.x *= scale0; v.y *= scale0; v.z *= scale0; v.w *= scale0;
        } else if (n4 < 256) {
            v = s1[k * 128 + n4 - 128];
        } else {
            v = s2[k * 128 + n4 - 256];
        }
        dst[i] = cvt4(v);
    }
}

// pack 4x [512][512] -> [512][2048] (dec cross K0|V0|K1|V1)
__global__ void pack4_kernel(const float4* __restrict__ s0, const float4* __restrict__ s1,
                             const float4* __restrict__ s2, const float4* __restrict__ s3,
                             uint4* __restrict__ dst) {
    int total = DMODEL * 512;
    for (int i = blockIdx.x * blockDim.x + threadIdx.x; i < total; i += gridDim.x * blockDim.x) {
        int k = i >> 9, n4 = i & 511;
        int sel = n4 >> 7, off = k * 128 + (n4 & 127);
        float4 v = (sel == 0) ? s0[off] : (sel == 1) ? s1[off] : (sel == 2) ? s2[off] : s3[off];
        dst[i] = cvt4(v);
    }
}

// ================= 2-stage cp.async tf32 GEMM (ldmatrix A-fragments) =================
#define GA_STRIDE 36
#define GB_STRIDE 132
#define GA_STAGE  (128 * GA_STRIDE)
#define GB_STAGE  (32 * GB_STRIDE)
#define GEMM_SMEM ((2 * GA_STAGE + 2 * GB_STAGE) * 4)

template<int RELU, int TF32OUT>
__global__ __launch_bounds__(256)
void mma_gemm(const uint32_t* __restrict__ A, const uint32_t* __restrict__ B,
              const float* __restrict__ bias, void* __restrict__ Cv,
              int M, int N, int K)
{
    extern __shared__ uint32_t gsm[];
    uint32_t* Asf = gsm;
    uint32_t* Bsf = gsm + 2 * GA_STAGE;

    const int tid  = threadIdx.x;
    const int wid  = tid >> 5, lane = tid & 31;
    const int wm   = wid & 1, wn = wid >> 1;
    const int g    = lane >> 2, tig = lane & 3;
    const int m0   = blockIdx.y * 128, n0 = blockIdx.x * 128;

    // ldmatrix per-lane tile coords for A (tiles: (mr,ks),(mr+8,ks),(mr,ks+4),(mr+8,ks+4))
    const int lt = lane >> 3, lr = lane & 7;
    const int a_row = lr + ((lt & 1) << 3);
    const int a_col = (lt >> 1) << 2;

    const uint32_t aBase = (uint32_t)__cvta_generic_to_shared(Asf);
    const uint32_t bBase = (uint32_t)__cvta_generic_to_shared(Bsf);

    float acc[4][4][4];
    #pragma unroll
    for (int i = 0; i < 4; i++)
        #pragma unroll
        for (int j = 0; j < 4; j++)
            #pragma unroll
            for (int c = 0; c < 4; c++) acc[i][j][c] = 0.f;

    auto issue = [&](int s, int k0) {
        #pragma unroll
        for (int i = 0; i < 4; i++) {
            int idx = tid + (i << 8);
            int r = idx >> 3, kk4 = (idx & 7) << 2;
            int m = m0 + r;
            const uint32_t* src = A + (size_t)(m < M ? m : 0) * K + k0 + kk4;
            cpasync16(aBase + (s * GA_STAGE + r * GA_STRIDE + kk4) * 4, src, (m < M) ? 16 : 0);
        }
        #pragma unroll
        for (int i = 0; i < 4; i++) {
            int idx = tid + (i << 8);
            int kk = idx >> 5, n4 = (idx & 31) << 2;
            const uint32_t* src = B + (size_t)(k0 + kk) * N + n0 + n4;
            cpasync16(bBase + (s * GB_STAGE + kk * GB_STRIDE + n4) * 4, src, 16);
        }
        asm volatile("cp.async.commit_group;");
    };

    const int nk = K >> 5;
    issue(0, 0);

    for (int kt = 0; kt < nk; kt++) {
        const int s = kt & 1;
        if (kt + 1 < nk) {
            issue(s ^ 1, (kt + 1) << 5);
            asm volatile("cp.async.wait_group 1;");
        } else {
            asm volatile("cp.async.wait_group 0;");
        }
        __syncthreads();

        const uint32_t aLane = aBase +
            (s * GA_STAGE + (wm * 64 + a_row) * GA_STRIDE + a_col) * 4;
        const uint32_t* Bs = Bsf + s * GB_STAGE;
        #pragma unroll
        for (int ks = 0; ks < 32; ks += 8) {
            uint32_t af[4][4];
            #pragma unroll
            for (int mi = 0; mi < 4; mi++)
                ldsm4(af[mi][0], af[mi][1], af[mi][2], af[mi][3],
                      aLane + (mi * 16 * GA_STRIDE + ks) * 4);
            uint32_t bf[4][2];
            #pragma unroll
            for (int ni = 0; ni < 4; ni++) {
                int nc = wn * 32 + ni * 8 + g;
                bf[ni][0] = Bs[(ks + tig    ) * GB_STRIDE + nc];
                bf[ni][1] = Bs[(ks + tig + 4) * GB_STRIDE + nc];
            }
            #pragma unroll
            for (int mi = 0; mi < 4; mi++)
                #pragma unroll
                for (int ni = 0; ni < 4; ni++)
                    mma8(acc[mi][ni], af[mi], bf[ni][0], bf[ni][1]);
        }
        __syncthreads();
    }

    #pragma unroll
    for (int mi = 0; mi < 4; mi++) {
        int mb = m0 + wm * 64 + mi * 16;
        #pragma unroll
        for (int ni = 0; ni < 4; ni++) {
            int nb = n0 + wn * 32 + ni * 8 + 2 * tig;
            #pragma unroll
            for (int half = 0; half < 2; half++) {
                int m = mb + g + half * 8;
                if (m < M) {
                    float v0 = acc[mi][ni][half * 2    ];
                    float v1 = acc[mi][ni][half * 2 + 1];
                    if (bias) { v0 += bias[nb]; v1 += bias[nb + 1]; }
                    if (RELU) { v0 = fmaxf(v0, 0.f); v1 = fmaxf(v1, 0.f); }
                    if (TF32OUT) {
                        *(uint2*)((uint32_t*)Cv + (size_t)m * N + nb) =
                            make_uint2(f2tf32(v0), f2tf32(v1));
                    } else {
                        *(float2*)((float*)Cv + (size_t)m * N + nb) = make_float2(v0, v1);
                    }
                }
            }
        }
    }
}

// ================= fused flash attention (non-causal, exact; ldmatrix Q/K) =================
#define FQ_STRIDE 68
#define FKV_STAGE (64 * FQ_STRIDE)
#define FLASH_SMEM ((128 * FQ_STRIDE + 4 * FKV_STAGE) * 4)

__global__ __launch_bounds__(256, 2)
void flash_attn(const uint32_t* __restrict__ Qg, int ldq,
                const uint32_t* __restrict__ Kg, const uint32_t* __restrict__ Vg, int ldkv,
                float* __restrict__ Og, int Tq, int Tk)
{
    extern __shared__ uint32_t fsm[];
    uint32_t* Qs   = fsm;
    uint32_t* Kraw = fsm + 128 * FQ_STRIDE;
    uint32_t* Vraw = Kraw + 2 * FKV_STAGE;

    const int bh = blockIdx.y;
    const int b = bh >> 3, h = bh & 7;
    const int q0 = blockIdx.x * 128;
    const int tid = threadIdx.x;
    const int wid = tid >> 5, lane = tid & 31;
    const int g = lane >> 2, tig = lane & 3;
    const int mr = wid * 16;

    // ldmatrix lane coords: A-style (Q) and B-style (K)
    const int lt = lane >> 3, lr = lane & 7;
    const int a_row = lr + ((lt & 1) << 3);     // tiles (mr,ks),(mr+8,ks),(mr,ks+4),(mr+8,ks+4)
    const int a_col = (lt >> 1) << 2;
    const int k_row = lr + ((lt >> 1) << 3);    // tiles (n0,ks),(n0,ks+4),(n0+8,ks),(n0+8,ks+4)
    const int k_col = (lt & 1) << 2;

    const uint32_t* qp = Qg + (size_t)b * Tq * ldq + h * DHEAD;
    const uint32_t* kp = Kg + (size_t)b * Tk * ldkv + h * DHEAD;
    const uint32_t* vp = Vg + (size_t)b * Tk * ldkv + h * DHEAD;

    const uint32_t qBase = (uint32_t)__cvta_generic_to_shared(Qs);
    const uint32_t kBase = (uint32_t)__cvta_generic_to_shared(Kraw);
    const uint32_t vBase = (uint32_t)__cvta_generic_to_shared(Vraw);

    auto issueKV = [&](int s, int kt) {
        #pragma unroll
        for (int i = 0; i < 4; i++) {
            int idx = tid + (i << 8);
            int r = idx >> 4, d4 = (idx & 15) << 2;
            cpasync16(kBase + (s * FKV_STAGE + r * FQ_STRIDE + d4) * 4,
                      kp + (size_t)(kt + r) * ldkv + d4, 16);
            cpasync16(vBase + (s * FKV_STAGE + r * FQ_STRIDE + d4) * 4,
                      vp + (size_t)(kt + r) * ldkv + d4, 16);
        }
        asm volatile("cp.async.commit_group;");
    };

    issueKV(0, 0);
    #pragma unroll
    for (int i = 0; i < 8; i++) {
        int idx = tid + (i << 8);
        int r = idx >> 4, d4 = (idx & 15) << 2;
        int q = q0 + r;
        cpasync16(qBase + (r * FQ_STRIDE + d4) * 4,
                  qp + (size_t)(q < Tq ? q : 0) * ldq + d4, (q < Tq) ? 16 : 0);
    }
    asm volatile("cp.async.commit_group;");

    float o[8][4];
    #pragma unroll
    for (int ni = 0; ni < 8; ni++)
        #pragma unroll
        for (int c = 0; c < 4; c++) o[ni][c] = 0.f;
    float m0 = -1e30f, m1 = -1e30f, l0 = 0.f, l1 = 0.f;

    const int srcA = (lane & ~3) | (tig >> 1);
    const int srcB = srcA + 2;
    const bool odd = tig & 1;

    const uint32_t qLane = qBase + ((mr + a_row) * FQ_STRIDE + a_col) * 4;

    const int nt = Tk >> 6;
    for (int kt = 0; kt < nt; kt++) {
        const int s = kt & 1;
        if (kt + 1 < nt) {
            issueKV(s ^ 1, (kt + 1) << 6);
            asm volatile("cp.async.wait_group 1;");
        } else {
            asm volatile("cp.async.wait_group 0;");
        }
        __syncthreads();

        const uint32_t kLane = kBase + (s * FKV_STAGE + k_row * FQ_STRIDE + k_col) * 4;
        const uint32_t* Vs = Vraw + s * FKV_STAGE;

        // ---- S = Q @ K^T ----
        float sfr[8][4];
        #pragma unroll
        for (int ni = 0; ni < 8; ni++)
            #pragma unroll
            for (int c = 0; c < 4; c++) sfr[ni][c] = 0.f;
        #pragma unroll
        for (int ks = 0; ks < 64; ks += 8) {
            uint32_t af[4];
            ldsm4(af[0], af[1], af[2], af[3], qLane + ks * 4);
            #pragma unroll
            for (int np = 0; np < 8; np += 2) {
                uint32_t b00, b01, b10, b11;
                ldsm4(b00, b01, b10, b11, kLane + (np * 8 * FQ_STRIDE + ks) * 4);
                mma8(sfr[np    ], af, b00, b01);
                mma8(sfr[np + 1], af, b10, b11);
            }
        }

        // ---- online softmax; P stays in registers ----
        float tmax0 = -1e30f, tmax1 = -1e30f;
        #pragma unroll
        for (int ni = 0; ni < 8; ni++) {
            tmax0 = fmaxf(tmax0, fmaxf(sfr[ni][0], sfr[ni][1]));
            tmax1 = fmaxf(tmax1, fmaxf(sfr[ni][2], sfr[ni][3]));
        }
        #pragma unroll
        for (int off = 1; off <= 2; off <<= 1) {
            tmax0 = fmaxf(tmax0, __shfl_xor_sync(0xffffffffu, tmax0, off));
            tmax1 = fmaxf(tmax1, __shfl_xor_sync(0xffffffffu, tmax1, off));
        }
        const float mn0 = fmaxf(m0, tmax0), mn1 = fmaxf(m1, tmax1);
        const float a0 = __expf(m0 - mn0), a1 = __expf(m1 - mn1);
        float rs0 = 0.f, rs1 = 0.f;
        uint32_t pf[8][4];
        #pragma unroll
        for (int ni = 0; ni < 8; ni++) {
            float p0 = __expf(sfr[ni][0] - mn0);
            float p1 = __expf(sfr[ni][1] - mn0);
            float p2 = __expf(sfr[ni][2] - mn1);
            float p3 = __expf(sfr[ni][3] - mn1);
            rs0 += p0 + p1; rs1 += p2 + p3;
            pf[ni][0] = f2tf32(p0); pf[ni][1] = f2tf32(p1);
            pf[ni][2] = f2tf32(p2); pf[ni][3] = f2tf32(p3);
        }
        #pragma unroll
        for (int off = 1; off <= 2; off <<= 1) {
            rs0 += __shfl_xor_sync(0xffffffffu, rs0, off);
            rs1 += __shfl_xor_sync(0xffffffffu, rs1, off);
        }
        l0 = l0 * a0 + rs0; l1 = l1 * a1 + rs1;
        m0 = mn0; m1 = mn1;
        #pragma unroll
        for (int ni = 0; ni < 8; ni++) {
            o[ni][0] *= a0; o[ni][1] *= a0;
            o[ni][2] *= a1; o[ni][3] *= a1;
        }

        // ---- O += P @ V, P redistributed c-frag -> a-frag via quad shuffles ----
        #pragma unroll
        for (int j = 0; j < 8; j++) {
            uint32_t r0a = __shfl_sync(0xffffffffu, pf[j][0], srcA);
            uint32_t r1a = __shfl_sync(0xffffffffu, pf[j][1], srcA);
            uint32_t r2a = __shfl_sync(0xffffffffu, pf[j][2], srcA);
            uint32_t r3a = __shfl_sync(0xffffffffu, pf[j][3], srcA);
            uint32_t r0b = __shfl_sync(0xffffffffu, pf[j][0], srcB);
            uint32_t r1b = __shfl_sync(0xffffffffu, pf[j][1], srcB);
            uint32_t r2b = __shfl_sync(0xffffffffu, pf[j][2], srcB);
            uint32_t r3b = __shfl_sync(0xffffffffu, pf[j][3], srcB);
            uint32_t af[4];
            af[0] = odd ? r1a : r0a;
            af[1] = odd ? r3a : r2a;
            af[2] = odd ? r1b : r0b;
            af[3] = odd ? r3b : r2b;
            const int ks = j * 8;
            #pragma unroll
            for (int ni = 0; ni < 8; ni++) {
                uint32_t b0 = Vs[(ks + tig    ) * FQ_STRIDE + ni * 8 + g];
                uint32_t b1 = Vs[(ks + tig + 4) * FQ_STRIDE + ni * 8 + g];
                mma8(o[ni], af, b0, b1);
            }
        }
        __syncthreads();
    }

    const float i0 = 1.f / l0, i1 = 1.f / l1;
    #pragma unroll
    for (int ni = 0; ni < 8; ni++) {
        int col = h * DHEAD + ni * 8 + 2 * tig;
        int r0 = q0 + mr + g, r1 = r0 + 8;
        if (r0 < Tq)
            *(float2*)(Og + (size_t)(b * Tq + r0) * DMODEL + col) =
                make_float2(o[ni][0] * i0, o[ni][1] * i0);
        if (r1 < Tq)
            *(float2*)(Og + (size_t)(b * Tq + r1) * DMODEL + col) =
                make_float2(o[ni][2] * i1, o[ni][3] * i1);
    }
}

// ================= fused decoder self-attention (exact fp32) =================
#define DS_STRIDE 68
#define DS_SSTRIDE 104
#define DEC_SMEM ((3 * T_DEC * DS_STRIDE + T_DEC * DS_SSTRIDE) * 4)

__global__ __launch_bounds__(256)
void dec_self_attn(const float* __restrict__ QKV, float* __restrict__ Og)
{
    extern __shared__ float dsm[];
    float* Qd = dsm;
    float* Kd = Qd + T_DEC * DS_STRIDE;
    float* Vd = Kd + T_DEC * DS_STRIDE;
    float* Sd = Vd + T_DEC * DS_STRIDE;

    const int bh = blockIdx.x;
    const int b = bh >> 3, h = bh & 7;
    const int tid = threadIdx.x;
    const int wid = tid >> 5, lane = tid & 31;

    const float* qp = QKV + (size_t)b * T_DEC * NQKV + h * DHEAD;
    const float* kp = qp + 512;
    const float* vp = qp + 1024;

    for (int idx = tid; idx < T_DEC * 16; idx += 256) {
        int r = idx >> 4, d4 = (idx & 15) << 2;
        *(float4*)&Qd[r * DS_STRIDE + d4] = *(const float4*)(qp + (size_t)r * NQKV + d4);
        *(float4*)&Kd[r * DS_STRIDE + d4] = *(const float4*)(kp + (size_t)r * NQKV + d4);
        *(float4*)&Vd[r * DS_STRIDE + d4] = *(const float4*)(vp + (size_t)r * NQKV + d4);
    }
    __syncthreads();

    for (int e = tid; e < T_DEC * T_DEC; e += 256) {
        int q = e / T_DEC, kk = e - q * T_DEC;
        const float* qr = &Qd[q * DS_STRIDE];
        const float* kr = &Kd[kk * DS_STRIDE];
        float acc = 0.f;
        #pragma unroll
        for (int d = 0; d < 64; d++) acc += qr[d] * kr[d];
        Sd[q * DS_SSTRIDE + kk] = acc * 0.125f;
    }
    __syncthreads();

    for (int q = wid; q < T_DEC; q += 8) {
        float* row = &Sd[q * DS_SSTRIDE];
        float r0 = (lane      < T_DEC) ? row[lane]      : -1e30f;
        float r1 = (lane + 32 < T_DEC) ? row[lane + 32] : -1e30f;
        float r2 = (lane + 64 < T_DEC) ? row[lane + 64] : -1e30f;
        float r3 = (lane + 96 < T_DEC) ? row[lane + 96] : -1e30f;
        float m = fmaxf(fmaxf(r0, r1), fmaxf(r2, r3));
        #pragma unroll
        for (int off = 16; off; off >>= 1) m = fmaxf(m, __shfl_xor_sync(0xffffffffu, m, off));
        float e0 = expf(r0 - m), e1 = expf(r1 - m), e2 = expf(r2 - m), e3 = expf(r3 - m);
        if (lane      >= T_DEC) e0 = 0.f;
        if (lane + 32 >= T_DEC) e1 = 0.f;
        if (lane + 64 >= T_DEC) e2 = 0.f;
        if (lane + 96 >= T_DEC) e3 = 0.f;
        float s = e0 + e1 + e2 + e3;
        #pragma unroll
        for (int off = 16; off; off >>= 1) s += __shfl_xor_sync(0xffffffffu, s, off);
        const float inv = 1.f / s;
        if (lane      < T_DEC) row[lane]      = (lane      > q) ? -1e10f : e0 * inv;
        if (lane + 32 < T_DEC) row[lane + 32] = (lane + 32 > q) ? -1e10f : e1 * inv;
        if (lane + 64 < T_DEC) row[lane + 64] = (lane + 64 > q) ? -1e10f : e2 * inv;
        if (lane + 96 < T_DEC) row[lane + 96] = (lane + 96 > q) ? -1e10f : e3 * inv;
    }
    __syncthreads();

    for (int e = tid; e < T_DEC * 64; e += 256) {
        int q = e >> 6, d = e & 63;
        const float* pr = &Sd[q * DS_SSTRIDE];
        float acc = 0.f;
        #pragma unroll 4
        for (int kk = 0; kk < T_DEC; kk++) acc += pr[kk] * Vd[kk * DS_STRIDE + d];
        Og[(size_t)(b * T_DEC + q) * DMODEL + h * DHEAD + d] = acc;
    }
}

// ---------------- fused residual + LayerNorm (fp32 out + optional tf32 out) ----------------
__global__ void ln_res_kernel(const float* __restrict__ A, const float* __restrict__ Bv,
                              const float* __restrict__ g, const float* __restrict__ be,
                              float* __restrict__ O, uint32_t* __restrict__ Otf) {
    const int row = blockIdx.x;
    const float* a = A + (size_t)row * DMODEL;
    const float* b = Bv + (size_t)row * DMODEL;
    __shared__ float red[256];
    const int tid = threadIdx.x;

    float v0 = a[tid] + b[tid];
    float v1 = a[tid + 256] + b[tid + 256];

    red[tid] = v0 + v1; __syncthreads();
    for (int s = 128; s > 0; s >>= 1) { if (tid < s) red[tid] += red[tid + s]; __syncthreads(); }
    const float mean = red[0] * (1.f / DMODEL); __syncthreads();

    float d0 = v0 - mean, d1 = v1 - mean;
    red[tid] = d0 * d0 + d1 * d1; __syncthreads();
    for (int s = 128; s > 0; s >>= 1) { if (tid < s) red[tid] += red[tid + s]; __syncthreads(); }
    const float inv = rsqrtf(red[0] * (1.f / DMODEL) + 1e-5f);

    const float o0 = d0 * inv * g[tid]       + be[tid];
    const float o1 = d1 * inv * g[tid + 256] + be[tid + 256];
    O[(size_t)row * DMODEL + tid]       = o0;
    O[(size_t)row * DMODEL + tid + 256] = o1;
    if (Otf) {
        Otf[(size_t)row * DMODEL + tid]       = f2tf32(o0);
        Otf[(size_t)row * DMODEL + tid + 256] = f2tf32(o1);
    }
}

// ---------------- host orchestration ----------------
static inline void mgemm(const uint32_t* A, const uint32_t* B, const float* bias, void* C,
                         int M, int N, int K, int relu, int tf32out) {
    dim3 grid(N / 128, (M + 127) / 128);
    if (relu && tf32out)
        mma_gemm<1, 1><<<grid, 256, GEMM_SMEM>>>(A, B, bias, C, M, N, K);
    else if (tf32out)
        mma_gemm<0, 1><<<grid, 256, GEMM_SMEM>>>(A, B, bias, C, M, N, K);
    else
        mma_gemm<0, 0><<<grid, 256, GEMM_SMEM>>>(A, B, bias, C, M, N, K);
}

template <typename T>
static inline void* symv(T& s) {
    void* p = nullptr;
    cudaGetSymbolAddress(&p, s);
    return p;
}

extern "C" void kernel_launch(void* const* d_in, const int* in_sizes, int n_in,
                              void* d_out, int out_size) {
    (void)in_sizes; (void)n_in; (void)out_size;

    cudaFuncSetAttribute((const void*)mma_gemm<0,0>, cudaFuncAttributeMaxDynamicSharedMemorySize, GEMM_SMEM);
    cudaFuncSetAttribute((const void*)mma_gemm<0,1>, cudaFuncAttributeMaxDynamicSharedMemorySize, GEMM_SMEM);
    cudaFuncSetAttribute((const void*)mma_gemm<1,1>, cudaFuncAttributeMaxDynamicSharedMemorySize, GEMM_SMEM);
    cudaFuncSetAttribute((const void*)flash_attn,    cudaFuncAttributeMaxDynamicSharedMemorySize, FLASH_SMEM);
    cudaFuncSetAttribute((const void*)dec_self_attn, cudaFuncAttributeMaxDynamicSharedMemorySize, DEC_SMEM);

    const float* x_in      = (const float*)d_in[0];
    const float* y_in      = (const float*)d_in[1];
    const float* enc_Wq    = (const float*)d_in[2];
    const float* enc_Wk    = (const float*)d_in[3];
    const float* enc_Wv    = (const float*)d_in[4];
    const float* enc_ff_w1 = (const float*)d_in[5];
    const float* enc_ff_b1 = (const float*)d_in[6];
    const float* enc_ff_w2 = (const float*)d_in[7];
    const float* enc_ff_b2 = (const float*)d_in[8];
    const float* enc_ln1_g = (const float*)d_in[9];
    const float* enc_ln1_b = (const float*)d_in[10];
    const float* enc_ln2_g = (const float*)d_in[11];
    const float* enc_ln2_b = (const float*)d_in[12];
    const float* dec_Wq1   = (const float*)d_in[13];
    const float* dec_Wk1   = (const float*)d_in[14];
    const float* dec_Wv1   = (const float*)d_in[15];
    const float* dec_Wq2   = (const float*)d_in[16];
    const float* dec_Wk2   = (const float*)d_in[17];
    const float* dec_Wv2   = (const float*)d_in[18];
    const float* dec_ff_w1 = (const float*)d_in[19];
    const float* dec_ff_b1 = (const float*)d_in[20];
    const float* dec_ff_w2 = (const float*)d_in[21];
    const float* dec_ff_b2 = (const float*)d_in[22];
    const float* dec_ln1_g = (const float*)d_in[23];
    const float* dec_ln1_b = (const float*)d_in[24];
    const float* dec_ln2_g = (const float*)d_in[25];
    const float* dec_ln2_b = (const float*)d_in[26];
    const float* dec_ln3_g = (const float*)d_in[27];
    const float* dec_ln3_b = (const float*)d_in[28];

    uint32_t* eqkvW = (uint32_t*)symv(w_eqkv);
    uint32_t* ew1   = (uint32_t*)symv(w_ew1);
    uint32_t* ew2   = (uint32_t*)symv(w_ew2);
    uint32_t* dqkv1 = (uint32_t*)symv(w_dqkv1);
    uint32_t* dq2   = (uint32_t*)symv(w_dq2);
    uint32_t* dkv2  = (uint32_t*)symv(w_dkv2);
    uint32_t* dw1   = (uint32_t*)symv(w_dw1);
    uint32_t* dw2   = (uint32_t*)symv(w_dw2);

    uint32_t* qkv  = (uint32_t*)symv(g_qkv);
    float*    qkvd = (float*)symv(g_qkvd);
    uint32_t* kv   = (uint32_t*)symv(g_kv);
    uint32_t* qx   = (uint32_t*)symv(g_qx);
    uint32_t* h    = (uint32_t*)symv(g_h);
    uint32_t* xtf  = (uint32_t*)symv(g_xtf);
    uint32_t* x1tf = (uint32_t*)symv(g_x1tf);
    uint32_t* ytf  = (uint32_t*)symv(g_ytf);
    uint32_t* y1tf = (uint32_t*)symv(g_y1tf);
    uint32_t* y2tf = (uint32_t*)symv(g_y2tf);
    float* att = (float*)symv(g_att);
    float* x1  = (float*)symv(g_x1);
    float* gx  = (float*)symv(g_x);
    float* y1  = (float*)symv(g_y1);
    float* y2  = (float*)symv(g_y2);
    float* gy  = (float*)symv(g_y);

    const long long WO = DMODEL * DMODEL;
    const long long FO1 = DMODEL * DFF;
    const long long FO2 = DFF * DMODEL;

    // ---- weight packing / conversion: 4 launches (rounding points unchanged) ----
    pack3_kernel<<<1024, 256>>>((const float4*)enc_Wq, (const float4*)enc_Wk,
                                (const float4*)enc_Wv, (uint4*)eqkvW, 2 * DMODEL, 0.125f);
    pack3_kernel<<<1024, 256>>>((const float4*)dec_Wq1, (const float4*)dec_Wk1,
                                (const float4*)dec_Wv1, (uint4*)dqkv1, 2 * DMODEL, 1.f);
    pack4_kernel<<<512, 256>>>((const float4*)dec_Wk2, (const float4*)dec_Wv2,
                               (const float4*)(dec_Wk2 + WO), (const float4*)(dec_Wv2 + WO),
                               (uint4*)dkv2);
    {
        ConvJobs jobs;
        jobs.j[0] = { (const float4*)dec_Wq2,   (uint4*)dq2, (int)(2 * WO  / 4), 0.125f };
        jobs.j[1] = { (const float4*)enc_ff_w1, (uint4*)ew1, (int)(2 * FO1 / 4), 1.f };
        jobs.j[2] = { (const float4*)enc_ff_w2, (uint4*)ew2, (int)(2 * FO2 / 4), 1.f };
        jobs.j[3] = { (const float4*)dec_ff_w1, (uint4*)dw1, (int)(2 * FO1 / 4), 1.f };
        jobs.j[4] = { (const float4*)dec_ff_w2, (uint4*)dw2, (int)(2 * FO2 / 4), 1.f };
        jobs.j[5] = { (const float4*)x_in,      (uint4*)xtf, (M_ENC * DMODEL) / 4, 1.f };
        jobs.j[6] = { (const float4*)y_in,      (uint4*)ytf, (M_DEC * DMODEL) / 4, 1.f };
        jobs.j[7] = { nullptr, nullptr, 0, 1.f };
        conv_multi_kernel<<<dim3(160, 7), 256>>>(jobs, 7);
    }

    // -------- encoder --------
    const float* xc = x_in;
    for (int i = 0; i < 2; i++) {
        mgemm(xtf, eqkvW + (size_t)i * DMODEL * NQKV, nullptr, qkv, M_ENC, NQKV, DMODEL, 0, 1);
        flash_attn<<<dim3(T_ENC / 128, BHT), 256, FLASH_SMEM>>>(
            qkv, NQKV, qkv + 512, qkv + 1024, NQKV, att, T_ENC, T_ENC);
        ln_res_kernel<<<M_ENC, 256>>>(xc, att, enc_ln1_g + i * DMODEL, enc_ln1_b + i * DMODEL, x1, x1tf);
        mgemm(x1tf, ew1 + (size_t)i * FO1, enc_ff_b1 + i * DFF, h, M_ENC, DFF, DMODEL, 1, 1);
        mgemm(h, ew2 + (size_t)i * FO2, enc_ff_b2 + i * DMODEL, att, M_ENC, DMODEL, DFF, 0, 0);
        ln_res_kernel<<<M_ENC, 256>>>(x1, att, enc_ln2_g + i * DMODEL, enc_ln2_b + i * DMODEL, gx, xtf);
        xc = gx;
    }

    // -------- decoder cross K/V for BOTH layers (one full-wave GEMM) --------
    mgemm(xtf, dkv2, nullptr, kv, M_ENC, NKV2, DMODEL, 0, 1);

    // -------- decoder --------
    const float* yc = y_in;
    for (int i = 0; i < 2; i++) {
        // masked self-attention: exact fp32 fused path (post-softmax -1e10 fill)
        mgemm(ytf, dqkv1 + (size_t)i * DMODEL * NQKV, nullptr, qkvd, M_DEC, NQKV, DMODEL, 0, 0);
        dec_self_attn<<<BHT, 256, DEC_SMEM>>>(qkvd, att);
        ln_res_kernel<<<M_DEC, 256>>>(yc, att, dec_ln1_g + i * DMODEL, dec_ln1_b + i * DMODEL, y1, y1tf);

        // cross-attention (non-causal -> flash; K/V precomputed)
        mgemm(y1tf, dq2 + i * WO, nullptr, qx, M_DEC, DMODEL, DMODEL, 0, 1);
        flash_attn<<<dim3(1, BHT), 256, FLASH_SMEM>>>(
            qx, DMODEL, kv + (size_t)i * 1024, kv + (size_t)i * 1024 + 512, NKV2,
            att, T_DEC, T_ENC);
        ln_res_kernel<<<M_DEC, 256>>>(y1, att, dec_ln2_g + i * DMODEL, dec_ln2_b + i * DMODEL, y2, y2tf);

        // feed-forward
        mgemm(y2tf, dw1 + (size_t)i * FO1, dec_ff_b1 + i * DFF, h, M_DEC, DFF, DMODEL, 1, 1);
        mgemm(h, dw2 + (size_t)i * FO2, dec_ff_b2 + i * DMODEL, att, M_DEC, DMODEL, DFF, 0, 0);
        float* outp = (i == 1) ? (float*)d_out : gy;
        ln_res_kernel<<<M_DEC, 256>>>(y2, att, dec_ln3_g + i * DMODEL, dec_ln3_b + i * DMODEL,
                                      outp, (i == 1) ? nullptr : ytf);
        yc = gy;
    }
}

// round 9
// speedup vs baseline: 1.3209x; 1.0397x over previous
#include <cuda_runtime.h>
#include <cstdint>
#include <cstddef>

// ---------------- problem constants ----------------
#define BATCH   8
#define T_ENC   1024
#define T_DEC   100
#define DMODEL  512
#define NHEAD   8
#define DHEAD   64
#define DFF     2048
#define M_ENC   (BATCH * T_ENC)   // 8192
#define M_DEC   (BATCH * T_DEC)   // 800
#define BHT     (BATCH * NHEAD)   // 64
#define NQKV    1536
#define NKV2    2048              // both decoder layers' K|V fused along N

// ---------------- fused tf32 weights, TRANSPOSED [N][K] ----------------
__device__ uint32_t w_eqkv[2 * NQKV * DMODEL];   // enc [1536][512] per layer (q rows x0.125)
__device__ uint32_t w_ew1 [2 * DFF * DMODEL];    // [2048][512]
__device__ uint32_t w_ew2 [2 * DMODEL * DFF];    // [512][2048]
__device__ uint32_t w_dqkv1[2 * NQKV * DMODEL];
__device__ uint32_t w_dq2 [2 * DMODEL * DMODEL];
__device__ uint32_t w_dkv2[NKV2 * DMODEL];       // [2048][512]  K0|V0|K1|V1
__device__ uint32_t w_dw1 [2 * DFF * DMODEL];
__device__ uint32_t w_dw2 [2 * DMODEL * DFF];

// ---------------- activations / scratch ----------------
__device__ uint32_t g_qkv [M_ENC * NQKV];        // enc fused QKV (tf32, q pre-scaled)
__device__ float    g_qkvd[M_DEC * NQKV];        // dec self QKV (fp32 exact)
__device__ uint32_t g_kv  [M_ENC * NKV2];        // dec cross K|V both layers (tf32)
__device__ uint32_t g_qx  [M_DEC * DMODEL];      // dec cross Q (tf32, pre-scaled)
__device__ uint32_t g_h   [M_ENC * DFF];         // FFN intermediate (tf32)
__device__ uint32_t g_xtf [M_ENC * DMODEL];
__device__ uint32_t g_x1tf[M_ENC * DMODEL];
__device__ uint32_t g_ytf [M_DEC * DMODEL];
__device__ uint32_t g_y1tf[M_DEC * DMODEL];
__device__ uint32_t g_y2tf[M_DEC * DMODEL];
__device__ float g_att [M_ENC * DMODEL];
__device__ float g_x1  [M_ENC * DMODEL];
__device__ float g_x   [M_ENC * DMODEL];
__device__ float g_y1  [M_DEC * DMODEL];
__device__ float g_y2  [M_DEC * DMODEL];
__device__ float g_y   [M_DEC * DMODEL];

__device__ __forceinline__ uint32_t f2tf32(float x) {
    uint32_t t;
    asm("cvt.rna.tf32.f32 %0, %1;" : "=r"(t) : "f"(x));
    return t;
}

__device__ __forceinline__ void mma8(float* c, const uint32_t* a, uint32_t b0, uint32_t b1) {
    asm volatile(
        "mma.sync.aligned.m16n8k8.row.col.f32.tf32.tf32.f32 "
        "{%0,%1,%2,%3}, {%4,%5,%6,%7}, {%8,%9}, {%0,%1,%2,%3};"
        : "+f"(c[0]), "+f"(c[1]), "+f"(c[2]), "+f"(c[3])
        : "r"(a[0]), "r"(a[1]), "r"(a[2]), "r"(a[3]), "r"(b0), "r"(b1));
}

__device__ __forceinline__ void ldsm4(uint32_t& r0, uint32_t& r1, uint32_t& r2, uint32_t& r3,
                                      uint32_t addr) {
    asm volatile("ldmatrix.sync.aligned.m8n8.x4.shared.b16 {%0,%1,%2,%3}, [%4];"
                 : "=r"(r0), "=r"(r1), "=r"(r2), "=r"(r3) : "r"(addr));
}

__device__ __forceinline__ void cpasync16(uint32_t smem_dst, const void* gsrc, int bytes) {
    asm volatile("cp.async.ca.shared.global [%0], [%1], 16, %2;"
                 :: "r"(smem_dst), "l"(gsrc), "r"(bytes));
}

__device__ __forceinline__ uint4 cvt4(float4 v) {
    return make_uint4(f2tf32(v.x), f2tf32(v.y), f2tf32(v.z), f2tf32(v.w));
}

// ---------------- transpose-convert packing: src [K][N] fp32 -> dst [N][K] tf32 ----------------
struct TJob { const float* src; uint32_t* dst; int K; int N; float scale; };
struct TJobs { TJob j[26]; };

__global__ void tpack_kernel(TJobs jobs, int njobs) {
    const int job = blockIdx.z;
    if (job >= njobs) return;
    const TJob jb = jobs.j[job];
    const int nt = blockIdx.x << 5, kt = blockIdx.y << 5;
    if (nt >= jb.N || kt >= jb.K) return;
    __shared__ float tile[32][33];
    const int tx = threadIdx.x & 31, ty = threadIdx.x >> 5;
    #pragma unroll
    for (int i = 0; i < 4; i++) {
        int k = kt + ty + i * 8;
        tile[ty + i * 8][tx] = jb.src[(size_t)k * jb.N + nt + tx];
    }
    __syncthreads();
    #pragma unroll
    for (int i = 0; i < 4; i++) {
        int n = nt + ty + i * 8;
        jb.dst[(size_t)n * jb.K + kt + tx] = f2tf32(tile[tx][ty + i * 8] * jb.scale);
    }
}

// ---------------- plain conversion (x / y inputs) ----------------
struct ConvJob { const float4* src; uint4* dst; int n4; };
struct ConvJobs { ConvJob j[2]; };

__global__ void conv_multi_kernel(ConvJobs jobs, int njobs) {
    int seg = blockIdx.y;
    if (seg >= njobs) return;
    ConvJob jb = jobs.j[seg];
    for (int i = blockIdx.x * blockDim.x + threadIdx.x; i < jb.n4; i += gridDim.x * blockDim.x) {
        jb.dst[i] = cvt4(jb.src[i]);
    }
}

// ================= 2-stage cp.async tf32 GEMM (ldmatrix A AND B fragments) =================
// C = A(MxK) @ B^T  with B stored [N][K].  BM=BN=128, BK=32, 256 thr.
#define GA_STRIDE 36
#define GA_STAGE  (128 * GA_STRIDE)
#define GB_STAGE  (128 * GA_STRIDE)
#define GEMM_SMEM ((2 * GA_STAGE + 2 * GB_STAGE) * 4)

template<int RELU, int TF32OUT>
__global__ __launch_bounds__(256)
void mma_gemm(const uint32_t* __restrict__ A, const uint32_t* __restrict__ B,
              const float* __restrict__ bias, void* __restrict__ Cv,
              int M, int N, int K)
{
    extern __shared__ uint32_t gsm[];
    uint32_t* Asf = gsm;
    uint32_t* Bsf = gsm + 2 * GA_STAGE;

    const int tid  = threadIdx.x;
    const int wid  = tid >> 5, lane = tid & 31;
    const int wm   = wid & 1, wn = wid >> 1;
    const int g    = lane >> 2, tig = lane & 3;
    const int m0   = blockIdx.y * 128, n0 = blockIdx.x * 128;

    // ldmatrix lane coords
    const int lt = lane >> 3, lr = lane & 7;
    const int a_row = lr + ((lt & 1) << 3);   // A tiles: (mr,ks),(mr+8,ks),(mr,ks+4),(mr+8,ks+4)
    const int a_col = (lt >> 1) << 2;
    const int b_row = lr + ((lt >> 1) << 3);  // B tiles: (nb,ks),(nb,ks+4),(nb+8,ks),(nb+8,ks+4)
    const int b_col = (lt & 1) << 2;

    const uint32_t aBase = (uint32_t)__cvta_generic_to_shared(Asf);
    const uint32_t bBase = (uint32_t)__cvta_generic_to_shared(Bsf);

    float acc[4][4][4];
    #pragma unroll
    for (int i = 0; i < 4; i++)
        #pragma unroll
        for (int j = 0; j < 4; j++)
            #pragma unroll
            for (int c = 0; c < 4; c++) acc[i][j][c] = 0.f;

    auto issue = [&](int s, int k0) {
        #pragma unroll
        for (int i = 0; i < 4; i++) {
            int idx = tid + (i << 8);
            int r = idx >> 3, kk4 = (idx & 7) << 2;
            int m = m0 + r;
            const uint32_t* src = A + (size_t)(m < M ? m : 0) * K + k0 + kk4;
            cpasync16(aBase + (s * GA_STAGE + r * GA_STRIDE + kk4) * 4, src, (m < M) ? 16 : 0);
        }
        #pragma unroll
        for (int i = 0; i < 4; i++) {
            int idx = tid + (i << 8);
            int r = idx >> 3, kk4 = (idx & 7) << 2;
            const uint32_t* src = B + (size_t)(n0 + r) * K + k0 + kk4;
            cpasync16(bBase + (s * GB_STAGE + r * GA_STRIDE + kk4) * 4, src, 16);
        }
        asm volatile("cp.async.commit_group;");
    };

    const int nk = K >> 5;
    issue(0, 0);

    for (int kt = 0; kt < nk; kt++) {
        const int s = kt & 1;
        if (kt + 1 < nk) {
            issue(s ^ 1, (kt + 1) << 5);
            asm volatile("cp.async.wait_group 1;");
        } else {
            asm volatile("cp.async.wait_group 0;");
        }
        __syncthreads();

        const uint32_t aLane = aBase +
            (s * GA_STAGE + (wm * 64 + a_row) * GA_STRIDE + a_col) * 4;
        const uint32_t bLane = bBase +
            (s * GB_STAGE + (wn * 32 + b_row) * GA_STRIDE + b_col) * 4;
        #pragma unroll
        for (int ks = 0; ks < 32; ks += 8) {
            uint32_t af[4][4];
            #pragma unroll
            for (int mi = 0; mi < 4; mi++)
                ldsm4(af[mi][0], af[mi][1], af[mi][2], af[mi][3],
                      aLane + (mi * 16 * GA_STRIDE + ks) * 4);
            uint32_t bf[4][2];
            ldsm4(bf[0][0], bf[0][1], bf[1][0], bf[1][1], bLane + ks * 4);
            ldsm4(bf[2][0], bf[2][1], bf[3][0], bf[3][1],
                  bLane + (16 * GA_STRIDE + ks) * 4);
            #pragma unroll
            for (int mi = 0; mi < 4; mi++)
                #pragma unroll
                for (int ni = 0; ni < 4; ni++)
                    mma8(acc[mi][ni], af[mi], bf[ni][0], bf[ni][1]);
        }
        __syncthreads();
    }

    #pragma unroll
    for (int mi = 0; mi < 4; mi++) {
        int mb = m0 + wm * 64 + mi * 16;
        #pragma unroll
        for (int ni = 0; ni < 4; ni++) {
            int nb = n0 + wn * 32 + ni * 8 + 2 * tig;
            #pragma unroll
            for (int half = 0; half < 2; half++) {
                int m = mb + g + half * 8;
                if (m < M) {
                    float v0 = acc[mi][ni][half * 2    ];
                    float v1 = acc[mi][ni][half * 2 + 1];
                    if (bias) { v0 += bias[nb]; v1 += bias[nb + 1]; }
                    if (RELU) { v0 = fmaxf(v0, 0.f); v1 = fmaxf(v1, 0.f); }
                    if (TF32OUT) {
                        *(uint2*)((uint32_t*)Cv + (size_t)m * N + nb) =
                            make_uint2(f2tf32(v0), f2tf32(v1));
                    } else {
                        *(float2*)((float*)Cv + (size_t)m * N + nb) = make_float2(v0, v1);
                    }
                }
            }
        }
    }
}

// ================= fused flash attention (non-causal, exact; ldmatrix Q/K) =================
#define FQ_STRIDE 68
#define FKV_STAGE (64 * FQ_STRIDE)
#define FLASH_SMEM ((128 * FQ_STRIDE + 4 * FKV_STAGE) * 4)

__global__ __launch_bounds__(256, 2)
void flash_attn(const uint32_t* __restrict__ Qg, int ldq,
                const uint32_t* __restrict__ Kg, const uint32_t* __restrict__ Vg, int ldkv,
                float* __restrict__ Og, int Tq, int Tk)
{
    extern __shared__ uint32_t fsm[];
    uint32_t* Qs   = fsm;
    uint32_t* Kraw = fsm + 128 * FQ_STRIDE;
    uint32_t* Vraw = Kraw + 2 * FKV_STAGE;

    const int bh = blockIdx.y;
    const int b = bh >> 3, h = bh & 7;
    const int q0 = blockIdx.x * 128;
    const int tid = threadIdx.x;
    const int wid = tid >> 5, lane = tid & 31;
    const int g = lane >> 2, tig = lane & 3;
    const int mr = wid * 16;

    const int lt = lane >> 3, lr = lane & 7;
    const int a_row = lr + ((lt & 1) << 3);
    const int a_col = (lt >> 1) << 2;
    const int k_row = lr + ((lt >> 1) << 3);
    const int k_col = (lt & 1) << 2;

    const uint32_t* qp = Qg + (size_t)b * Tq * ldq + h * DHEAD;
    const uint32_t* kp = Kg + (size_t)b * Tk * ldkv + h * DHEAD;
    const uint32_t* vp = Vg + (size_t)b * Tk * ldkv + h * DHEAD;

    const uint32_t qBase = (uint32_t)__cvta_generic_to_shared(Qs);
    const uint32_t kBase = (uint32_t)__cvta_generic_to_shared(Kraw);
    const uint32_t vBase = (uint32_t)__cvta_generic_to_shared(Vraw);

    auto issueKV = [&](int s, int kt) {
        #pragma unroll
        for (int i = 0; i < 4; i++) {
            int idx = tid + (i << 8);
            int r = idx >> 4, d4 = (idx & 15) << 2;
            cpasync16(kBase + (s * FKV_STAGE + r * FQ_STRIDE + d4) * 4,
                      kp + (size_t)(kt + r) * ldkv + d4, 16);
            cpasync16(vBase + (s * FKV_STAGE + r * FQ_STRIDE + d4) * 4,
                      vp + (size_t)(kt + r) * ldkv + d4, 16);
        }
        asm volatile("cp.async.commit_group;");
    };

    issueKV(0, 0);
    #pragma unroll
    for (int i = 0; i < 8; i++) {
        int idx = tid + (i << 8);
        int r = idx >> 4, d4 = (idx & 15) << 2;
        int q = q0 + r;
        cpasync16(qBase + (r * FQ_STRIDE + d4) * 4,
                  qp + (size_t)(q < Tq ? q : 0) * ldq + d4, (q < Tq) ? 16 : 0);
    }
    asm volatile("cp.async.commit_group;");

    float o[8][4];
    #pragma unroll
    for (int ni = 0; ni < 8; ni++)
        #pragma unroll
        for (int c = 0; c < 4; c++) o[ni][c] = 0.f;
    float m0 = -1e30f, m1 = -1e30f, l0 = 0.f, l1 = 0.f;

    const int srcA = (lane & ~3) | (tig >> 1);
    const int srcB = srcA + 2;
    const bool odd = tig & 1;

    const uint32_t qLane = qBase + ((mr + a_row) * FQ_STRIDE + a_col) * 4;

    const int nt = Tk >> 6;
    for (int kt = 0; kt < nt; kt++) {
        const int s = kt & 1;
        if (kt + 1 < nt) {
            issueKV(s ^ 1, (kt + 1) << 6);
            asm volatile("cp.async.wait_group 1;");
        } else {
            asm volatile("cp.async.wait_group 0;");
        }
        __syncthreads();

        const uint32_t kLane = kBase + (s * FKV_STAGE + k_row * FQ_STRIDE + k_col) * 4;
        const uint32_t* Vs = Vraw + s * FKV_STAGE;

        float sfr[8][4];
        #pragma unroll
        for (int ni = 0; ni < 8; ni++)
            #pragma unroll
            for (int c = 0; c < 4; c++) sfr[ni][c] = 0.f;
        #pragma unroll
        for (int ks = 0; ks < 64; ks += 8) {
            uint32_t af[4];
            ldsm4(af[0], af[1], af[2], af[3], qLane + ks * 4);
            #pragma unroll
            for (int np = 0; np < 8; np += 2) {
                uint32_t b00, b01, b10, b11;
                ldsm4(b00, b01, b10, b11, kLane + (np * 8 * FQ_STRIDE + ks) * 4);
                mma8(sfr[np    ], af, b00, b01);
                mma8(sfr[np + 1], af, b10, b11);
            }
        }

        float tmax0 = -1e30f, tmax1 = -1e30f;
        #pragma unroll
        for (int ni = 0; ni < 8; ni++) {
            tmax0 = fmaxf(tmax0, fmaxf(sfr[ni][0], sfr[ni][1]));
            tmax1 = fmaxf(tmax1, fmaxf(sfr[ni][2], sfr[ni][3]));
        }
        #pragma unroll
        for (int off = 1; off <= 2; off <<= 1) {
            tmax0 = fmaxf(tmax0, __shfl_xor_sync(0xffffffffu, tmax0, off));
            tmax1 = fmaxf(tmax1, __shfl_xor_sync(0xffffffffu, tmax1, off));
        }
        const float mn0 = fmaxf(m0, tmax0), mn1 = fmaxf(m1, tmax1);
        const float a0 = __expf(m0 - mn0), a1 = __expf(m1 - mn1);
        float rs0 = 0.f, rs1 = 0.f;
        uint32_t pf[8][4];
        #pragma unroll
        for (int ni = 0; ni < 8; ni++) {
            float p0 = __expf(sfr[ni][0] - mn0);
            float p1 = __expf(sfr[ni][1] - mn0);
            float p2 = __expf(sfr[ni][2] - mn1);
            float p3 = __expf(sfr[ni][3] - mn1);
            rs0 += p0 + p1; rs1 += p2 + p3;
            pf[ni][0] = f2tf32(p0); pf[ni][1] = f2tf32(p1);
            pf[ni][2] = f2tf32(p2); pf[ni][3] = f2tf32(p3);
        }
        #pragma unroll
        for (int off = 1; off <= 2; off <<= 1) {
            rs0 += __shfl_xor_sync(0xffffffffu, rs0, off);
            rs1 += __shfl_xor_sync(0xffffffffu, rs1, off);
        }
        l0 = l0 * a0 + rs0; l1 = l1 * a1 + rs1;
        m0 = mn0; m1 = mn1;
        #pragma unroll
        for (int ni = 0; ni < 8; ni++) {
            o[ni][0] *= a0; o[ni][1] *= a0;
            o[ni][2] *= a1; o[ni][3] *= a1;
        }

        #pragma unroll
        for (int j = 0; j < 8; j++) {
            uint32_t r0a = __shfl_sync(0xffffffffu, pf[j][0], srcA);
            uint32_t r1a = __shfl_sync(0xffffffffu, pf[j][1], srcA);
            uint32_t r2a = __shfl_sync(0xffffffffu, pf[j][2], srcA);
            uint32_t r3a = __shfl_sync(0xffffffffu, pf[j][3], srcA);
            uint32_t r0b = __shfl_sync(0xffffffffu, pf[j][0], srcB);
            uint32_t r1b = __shfl_sync(0xffffffffu, pf[j][1], srcB);
            uint32_t r2b = __shfl_sync(0xffffffffu, pf[j][2], srcB);
            uint32_t r3b = __shfl_sync(0xffffffffu, pf[j][3], srcB);
            uint32_t af[4];
            af[0] = odd ? r1a : r0a;
            af[1] = odd ? r3a : r2a;
            af[2] = odd ? r1b : r0b;
            af[3] = odd ? r3b : r2b;
            const int ks = j * 8;
            #pragma unroll
            for (int ni = 0; ni < 8; ni++) {
                uint32_t b0 = Vs[(ks + tig    ) * FQ_STRIDE + ni * 8 + g];
                uint32_t b1 = Vs[(ks + tig + 4) * FQ_STRIDE + ni * 8 + g];
                mma8(o[ni], af, b0, b1);
            }
        }
        __syncthreads();
    }

    const float i0 = 1.f / l0, i1 = 1.f / l1;
    #pragma unroll
    for (int ni = 0; ni < 8; ni++) {
        int col = h * DHEAD + ni * 8 + 2 * tig;
        int r0 = q0 + mr + g, r1 = r0 + 8;
        if (r0 < Tq)
            *(float2*)(Og + (size_t)(b * Tq + r0) * DMODEL + col) =
                make_float2(o[ni][0] * i0, o[ni][1] * i0);
        if (r1 < Tq)
            *(float2*)(Og + (size_t)(b * Tq + r1) * DMODEL + col) =
                make_float2(o[ni][2] * i1, o[ni][3] * i1);
    }
}

// ================= fused decoder self-attention (exact fp32) =================
#define DS_STRIDE 68
#define DS_SSTRIDE 104
#define DEC_SMEM ((3 * T_DEC * DS_STRIDE + T_DEC * DS_SSTRIDE) * 4)

__global__ __launch_bounds__(256)
void dec_self_attn(const float* __restrict__ QKV, float* __restrict__ Og)
{
    extern __shared__ float dsm[];
    float* Qd = dsm;
    float* Kd = Qd + T_DEC * DS_STRIDE;
    float* Vd = Kd + T_DEC * DS_STRIDE;
    float* Sd = Vd + T_DEC * DS_STRIDE;

    const int bh = blockIdx.x;
    const int b = bh >> 3, h = bh & 7;
    const int tid = threadIdx.x;
    const int wid = tid >> 5, lane = tid & 31;

    const float* qp = QKV + (size_t)b * T_DEC * NQKV + h * DHEAD;
    const float* kp = qp + 512;
    const float* vp = qp + 1024;

    for (int idx = tid; idx < T_DEC * 16; idx += 256) {
        int r = idx >> 4, d4 = (idx & 15) << 2;
        *(float4*)&Qd[r * DS_STRIDE + d4] = *(const float4*)(qp + (size_t)r * NQKV + d4);
        *(float4*)&Kd[r * DS_STRIDE + d4] = *(const float4*)(kp + (size_t)r * NQKV + d4);
        *(float4*)&Vd[r * DS_STRIDE + d4] = *(const float4*)(vp + (size_t)r * NQKV + d4);
    }
    __syncthreads();

    for (int e = tid; e < T_DEC * T_DEC; e += 256) {
        int q = e / T_DEC, kk = e - q * T_DEC;
        const float* qr = &Qd[q * DS_STRIDE];
        const float* kr = &Kd[kk * DS_STRIDE];
        float acc = 0.f;
        #pragma unroll
        for (int d = 0; d < 64; d++) acc += qr[d] * kr[d];
        Sd[q * DS_SSTRIDE + kk] = acc * 0.125f;
    }
    __syncthreads();

    for (int q = wid; q < T_DEC; q += 8) {
        float* row = &Sd[q * DS_SSTRIDE];
        float r0 = (lane      < T_DEC) ? row[lane]      : -1e30f;
        float r1 = (lane + 32 < T_DEC) ? row[lane + 32] : -1e30f;
        float r2 = (lane + 64 < T_DEC) ? row[lane + 64] : -1e30f;
        float r3 = (lane + 96 < T_DEC) ? row[lane + 96] : -1e30f;
        float m = fmaxf(fmaxf(r0, r1), fmaxf(r2, r3));
        #pragma unroll
        for (int off = 16; off; off >>= 1) m = fmaxf(m, __shfl_xor_sync(0xffffffffu, m, off));
        float e0 = expf(r0 - m), e1 = expf(r1 - m), e2 = expf(r2 - m), e3 = expf(r3 - m);
        if (lane      >= T_DEC) e0 = 0.f;
        if (lane + 32 >= T_DEC) e1 = 0.f;
        if (lane + 64 >= T_DEC) e2 = 0.f;
        if (lane + 96 >= T_DEC) e3 = 0.f;
        float s = e0 + e1 + e2 + e3;
        #pragma unroll
        for (int off = 16; off; off >>= 1) s += __shfl_xor_sync(0xffffffffu, s, off);
        const float inv = 1.f / s;
        if (lane      < T_DEC) row[lane]      = (lane      > q) ? -1e10f : e0 * inv;
        if (lane + 32 < T_DEC) row[lane + 32] = (lane + 32 > q) ? -1e10f : e1 * inv;
        if (lane + 64 < T_DEC) row[lane + 64] = (lane + 64 > q) ? -1e10f : e2 * inv;
        if (lane + 96 < T_DEC) row[lane + 96] = (lane + 96 > q) ? -1e10f : e3 * inv;
    }
    __syncthreads();

    for (int e = tid; e < T_DEC * 64; e += 256) {
        int q = e >> 6, d = e & 63;
        const float* pr = &Sd[q * DS_SSTRIDE];
        float acc = 0.f;
        #pragma unroll 4
        for (int kk = 0; kk < T_DEC; kk++) acc += pr[kk] * Vd[kk * DS_STRIDE + d];
        Og[(size_t)(b * T_DEC + q) * DMODEL + h * DHEAD + d] = acc;
    }
}

// ---------------- fused residual + LayerNorm (fp32 out + optional tf32 out) ----------------
__global__ void ln_res_kernel(const float* __restrict__ A, const float* __restrict__ Bv,
                              const float* __restrict__ g, const float* __restrict__ be,
                              float* __restrict__ O, uint32_t* __restrict__ Otf) {
    const int row = blockIdx.x;
    const float* a = A + (size_t)row * DMODEL;
    const float* b = Bv + (size_t)row * DMODEL;
    __shared__ float red[256];
    const int tid = threadIdx.x;

    float v0 = a[tid] + b[tid];
    float v1 = a[tid + 256] + b[tid + 256];

    red[tid] = v0 + v1; __syncthreads();
    for (int s = 128; s > 0; s >>= 1) { if (tid < s) red[tid] += red[tid + s]; __syncthreads(); }
    const float mean = red[0] * (1.f / DMODEL); __syncthreads();

    float d0 = v0 - mean, d1 = v1 - mean;
    red[tid] = d0 * d0 + d1 * d1; __syncthreads();
    for (int s = 128; s > 0; s >>= 1) { if (tid < s) red[tid] += red[tid + s]; __syncthreads(); }
    const float inv = rsqrtf(red[0] * (1.f / DMODEL) + 1e-5f);

    const float o0 = d0 * inv * g[tid]       + be[tid];
    const float o1 = d1 * inv * g[tid + 256] + be[tid + 256];
    O[(size_t)row * DMODEL + tid]       = o0;
    O[(size_t)row * DMODEL + tid + 256] = o1;
    if (Otf) {
        Otf[(size_t)row * DMODEL + tid]       = f2tf32(o0);
        Otf[(size_t)row * DMODEL + tid + 256] = f2tf32(o1);
    }
}

// ---------------- host orchestration ----------------
static inline void mgemm(const uint32_t* A, const uint32_t* B, const float* bias, void* C,
                         int M, int N, int K, int relu, int tf32out) {
    dim3 grid(N / 128, (M + 127) / 128);
    if (relu && tf32out)
        mma_gemm<1, 1><<<grid, 256, GEMM_SMEM>>>(A, B, bias, C, M, N, K);
    else if (tf32out)
        mma_gemm<0, 1><<<grid, 256, GEMM_SMEM>>>(A, B, bias, C, M, N, K);
    else
        mma_gemm<0, 0><<<grid, 256, GEMM_SMEM>>>(A, B, bias, C, M, N, K);
}

template <typename T>
static inline void* symv(T& s) {
    void* p = nullptr;
    cudaGetSymbolAddress(&p, s);
    return p;
}

extern "C" void kernel_launch(void* const* d_in, const int* in_sizes, int n_in,
                              void* d_out, int out_size) {
    (void)in_sizes; (void)n_in; (void)out_size;

    cudaFuncSetAttribute((const void*)mma_gemm<0,0>, cudaFuncAttributeMaxDynamicSharedMemorySize, GEMM_SMEM);
    cudaFuncSetAttribute((const void*)mma_gemm<0,1>, cudaFuncAttributeMaxDynamicSharedMemorySize, GEMM_SMEM);
    cudaFuncSetAttribute((const void*)mma_gemm<1,1>, cudaFuncAttributeMaxDynamicSharedMemorySize, GEMM_SMEM);
    cudaFuncSetAttribute((const void*)flash_attn,    cudaFuncAttributeMaxDynamicSharedMemorySize, FLASH_SMEM);
    cudaFuncSetAttribute((const void*)dec_self_attn, cudaFuncAttributeMaxDynamicSharedMemorySize, DEC_SMEM);

    const float* x_in      = (const float*)d_in[0];
    const float* y_in      = (const float*)d_in[1];
    const float* enc_Wq    = (const float*)d_in[2];
    const float* enc_Wk    = (const float*)d_in[3];
    const float* enc_Wv    = (const float*)d_in[4];
    const float* enc_ff_w1 = (const float*)d_in[5];
    const float* enc_ff_b1 = (const float*)d_in[6];
    const float* enc_ff_w2 = (const float*)d_in[7];
    const float* enc_ff_b2 = (const float*)d_in[8];
    const float* enc_ln1_g = (const float*)d_in[9];
    const float* enc_ln1_b = (const float*)d_in[10];
    const float* enc_ln2_g = (const float*)d_in[11];
    const float* enc_ln2_b = (const float*)d_in[12];
    const float* dec_Wq1   = (const float*)d_in[13];
    const float* dec_Wk1   = (const float*)d_in[14];
    const float* dec_Wv1   = (const float*)d_in[15];
    const float* dec_Wq2   = (const float*)d_in[16];
    const float* dec_Wk2   = (const float*)d_in[17];
    const float* dec_Wv2   = (const float*)d_in[18];
    const float* dec_ff_w1 = (const float*)d_in[19];
    const float* dec_ff_b1 = (const float*)d_in[20];
    const float* dec_ff_w2 = (const float*)d_in[21];
    const float* dec_ff_b2 = (const float*)d_in[22];
    const float* dec_ln1_g = (const float*)d_in[23];
    const float* dec_ln1_b = (const float*)d_in[24];
    const float* dec_ln2_g = (const float*)d_in[25];
    const float* dec_ln2_b = (const float*)d_in[26];
    const float* dec_ln3_g = (const float*)d_in[27];
    const float* dec_ln3_b = (const float*)d_in[28];

    uint32_t* eqkvW = (uint32_t*)symv(w_eqkv);
    uint32_t* ew1   = (uint32_t*)symv(w_ew1);
    uint32_t* ew2   = (uint32_t*)symv(w_ew2);
    uint32_t* dqkv1 = (uint32_t*)symv(w_dqkv1);
    uint32_t* dq2   = (uint32_t*)symv(w_dq2);
    uint32_t* dkv2  = (uint32_t*)symv(w_dkv2);
    uint32_t* dw1   = (uint32_t*)symv(w_dw1);
    uint32_t* dw2   = (uint32_t*)symv(w_dw2);

    uint32_t* qkv  = (uint32_t*)symv(g_qkv);
    float*    qkvd = (float*)symv(g_qkvd);
    uint32_t* kv   = (uint32_t*)symv(g_kv);
    uint32_t* qx   = (uint32_t*)symv(g_qx);
    uint32_t* h    = (uint32_t*)symv(g_h);
    uint32_t* xtf  = (uint32_t*)symv(g_xtf);
    uint32_t* x1tf = (uint32_t*)symv(g_x1tf);
    uint32_t* ytf  = (uint32_t*)symv(g_ytf);
    uint32_t* y1tf = (uint32_t*)symv(g_y1tf);
    uint32_t* y2tf = (uint32_t*)symv(g_y2tf);
    float* att = (float*)symv(g_att);
    float* x1  = (float*)symv(g_x1);
    float* gx  = (float*)symv(g_x);
    float* y1  = (float*)symv(g_y1);
    float* y2  = (float*)symv(g_y2);
    float* gy  = (float*)symv(g_y);

    const long long WO = DMODEL * DMODEL;
    const long long FO1 = DFF * DMODEL;      // element count per layer (both orientations)
    const long long LQKV = (long long)NQKV * DMODEL;

    // ---- transpose-convert ALL weights [K][N] -> [N][K] tf32 (2 prologue launches) ----
    {
        TJobs tj;
        int n = 0;
        for (int i = 0; i < 2; i++) {
            tj.j[n++] = { enc_Wq + i * WO, eqkvW + i * LQKV +      0LL * DMODEL, DMODEL, DMODEL, 0.125f };
            tj.j[n++] = { enc_Wk + i * WO, eqkvW + i * LQKV +    512LL * DMODEL, DMODEL, DMODEL, 1.f };
            tj.j[n++] = { enc_Wv + i * WO, eqkvW + i * LQKV +   1024LL * DMODEL, DMODEL, DMODEL, 1.f };
            tj.j[n++] = { dec_Wq1 + i * WO, dqkv1 + i * LQKV +     0LL * DMODEL, DMODEL, DMODEL, 1.f };
            tj.j[n++] = { dec_Wk1 + i * WO, dqkv1 + i * LQKV +   512LL * DMODEL, DMODEL, DMODEL, 1.f };
            tj.j[n++] = { dec_Wv1 + i * WO, dqkv1 + i * LQKV +  1024LL * DMODEL, DMODEL, DMODEL, 1.f };
            tj.j[n++] = { dec_Wq2 + i * WO, dq2 + i * WO, DMODEL, DMODEL, 0.125f };
            tj.j[n++] = { dec_Wk2 + i * WO, dkv2 + (i * 1024LL      ) * DMODEL, DMODEL, DMODEL, 1.f };
            tj.j[n++] = { dec_Wv2 + i * WO, dkv2 + (i * 1024LL + 512) * DMODEL, DMODEL, DMODEL, 1.f };
            tj.j[n++] = { enc_ff_w1 + i * FO1, ew1 + i * FO1, DMODEL, DFF, 1.f };   // [512][2048]->[2048][512]
            tj.j[n++] = { enc_ff_w2 + i * FO1, ew2 + i * FO1, DFF, DMODEL, 1.f };   // [2048][512]->[512][2048]
            tj.j[n++] = { dec_ff_w1 + i * FO1, dw1 + i * FO1, DMODEL, DFF, 1.f };
            tj.j[n++] = { dec_ff_w2 + i * FO1, dw2 + i * FO1, DFF, DMODEL, 1.f };
        }
        // max tiles: N up to 2048 (64), K up to 2048 (64)
        tpack_kernel<<<dim3(64, 64, n), 256>>>(tj, n);
    }
    {
        ConvJobs jobs;
        jobs.j[0] = { (const float4*)x_in, (uint4*)xtf, (M_ENC * DMODEL) / 4 };
        jobs.j[1] = { (const float4*)y_in, (uint4*)ytf, (M_DEC * DMODEL) / 4 };
        conv_multi_kernel<<<dim3(160, 2), 256>>>(jobs, 2);
    }

    // -------- encoder --------
    const float* xc = x_in;
    for (int i = 0; i < 2; i++) {
        mgemm(xtf, eqkvW + (size_t)i * LQKV, nullptr, qkv, M_ENC, NQKV, DMODEL, 0, 1);
        flash_attn<<<dim3(T_ENC / 128, BHT), 256, FLASH_SMEM>>>(
            qkv, NQKV, qkv + 512, qkv + 1024, NQKV, att, T_ENC, T_ENC);
        ln_res_kernel<<<M_ENC, 256>>>(xc, att, enc_ln1_g + i * DMODEL, enc_ln1_b + i * DMODEL, x1, x1tf);
        mgemm(x1tf, ew1 + (size_t)i * FO1, enc_ff_b1 + i * DFF, h, M_ENC, DFF, DMODEL, 1, 1);
        mgemm(h, ew2 + (size_t)i * FO1, enc_ff_b2 + i * DMODEL, att, M_ENC, DMODEL, DFF, 0, 0);
        ln_res_kernel<<<M_ENC, 256>>>(x1, att, enc_ln2_g + i * DMODEL, enc_ln2_b + i * DMODEL, gx, xtf);
        xc = gx;
    }

    // -------- decoder cross K/V for BOTH layers (one full-wave GEMM) --------
    mgemm(xtf, dkv2, nullptr, kv, M_ENC, NKV2, DMODEL, 0, 1);

    // -------- decoder --------
    const float* yc = y_in;
    for (int i = 0; i < 2; i++) {
        // masked self-attention: exact fp32 fused path (post-softmax -1e10 fill)
        mgemm(ytf, dqkv1 + (size_t)i * LQKV, nullptr, qkvd, M_DEC, NQKV, DMODEL, 0, 0);
        dec_self_attn<<<BHT, 256, DEC_SMEM>>>(qkvd, att);
        ln_res_kernel<<<M_DEC, 256>>>(yc, att, dec_ln1_g + i * DMODEL, dec_ln1_b + i * DMODEL, y1, y1tf);

        // cross-attention (non-causal -> flash; K/V precomputed)
        mgemm(y1tf, dq2 + i * WO, nullptr, qx, M_DEC, DMODEL, DMODEL, 0, 1);
        flash_attn<<<dim3(1, BHT), 256, FLASH_SMEM>>>(
            qx, DMODEL, kv + (size_t)i * 1024, kv + (size_t)i * 1024 + 512, NKV2,
            att, T_DEC, T_ENC);
        ln_res_kernel<<<M_DEC, 256>>>(y1, att, dec_ln2_g + i * DMODEL, dec_ln2_b + i * DMODEL, y2, y2tf);

        // feed-forward
        mgemm(y2tf, dw1 + (size_t)i * FO1, dec_ff_b1 + i * DFF, h, M_DEC, DFF, DMODEL, 1, 1);
        mgemm(h, dw2 + (size_t)i * FO1, dec_ff_b2 + i * DMODEL, att, M_DEC, DMODEL, DFF, 0, 0);
        float* outp = (i == 1) ? (float*)d_out : gy;
        ln_res_kernel<<<M_DEC, 256>>>(y2, att, dec_ln3_g + i * DMODEL, dec_ln3_b + i * DMODEL,
                                      outp, (i == 1) ? nullptr : ytf);
        yc = gy;
    }
}

// round 10
// speedup vs baseline: 1.3738x; 1.0401x over previous
#include <cuda_runtime.h>
#include <cstdint>
#include <cstddef>

// ---------------- problem constants ----------------
#define BATCH   8
#define T_ENC   1024
#define T_DEC   100
#define DMODEL  512
#define NHEAD   8
#define DHEAD   64
#define DFF     2048
#define M_ENC   (BATCH * T_ENC)   // 8192
#define M_DEC   (BATCH * T_DEC)   // 800
#define BHT     (BATCH * NHEAD)   // 64
#define NQKV    1536
#define NKV2    2048              // both decoder layers' K|V fused along N

// ---------------- fused tf32 weights, TRANSPOSED [N][K] ----------------
__device__ uint32_t w_eqkv[2 * NQKV * DMODEL];
__device__ uint32_t w_ew1 [2 * DFF * DMODEL];
__device__ uint32_t w_ew2 [2 * DMODEL * DFF];
__device__ uint32_t w_dqkv1[2 * NQKV * DMODEL];
__device__ uint32_t w_dq2 [2 * DMODEL * DMODEL];
__device__ uint32_t w_dkv2[NKV2 * DMODEL];
__device__ uint32_t w_dw1 [2 * DFF * DMODEL];
__device__ uint32_t w_dw2 [2 * DMODEL * DFF];

// ---------------- activations / scratch ----------------
__device__ uint32_t g_qkv [M_ENC * NQKV];        // enc Q|K (tf32); V region unused
__device__ float    g_qkvd[M_DEC * NQKV];        // dec self QKV (fp32 exact)
__device__ uint32_t g_kv  [M_ENC * NKV2];        // dec cross K both layers; V regions unused
__device__ uint32_t g_vtE [BHT * DHEAD * T_ENC]; // enc V, d-major [bh][64][1024]
__device__ uint32_t g_vtD [2 * BHT * DHEAD * T_ENC]; // dec cross V, per layer
__device__ uint32_t g_qx  [M_DEC * DMODEL];
__device__ uint32_t g_h   [M_ENC * DFF];
__device__ uint32_t g_xtf [M_ENC * DMODEL];
__device__ uint32_t g_x1tf[M_ENC * DMODEL];
__device__ uint32_t g_ytf [M_DEC * DMODEL];
__device__ uint32_t g_y1tf[M_DEC * DMODEL];
__device__ uint32_t g_y2tf[M_DEC * DMODEL];
__device__ float g_att [M_ENC * DMODEL];
__device__ float g_x1  [M_ENC * DMODEL];
__device__ float g_x   [M_ENC * DMODEL];
__device__ float g_y1  [M_DEC * DMODEL];
__device__ float g_y2  [M_DEC * DMODEL];
__device__ float g_y   [M_DEC * DMODEL];

__device__ __forceinline__ uint32_t f2tf32(float x) {
    uint32_t t;
    asm("cvt.rna.tf32.f32 %0, %1;" : "=r"(t) : "f"(x));
    return t;
}

__device__ __forceinline__ void mma8(float* c, const uint32_t* a, uint32_t b0, uint32_t b1) {
    asm volatile(
        "mma.sync.aligned.m16n8k8.row.col.f32.tf32.tf32.f32 "
        "{%0,%1,%2,%3}, {%4,%5,%6,%7}, {%8,%9}, {%0,%1,%2,%3};"
        : "+f"(c[0]), "+f"(c[1]), "+f"(c[2]), "+f"(c[3])
        : "r"(a[0]), "r"(a[1]), "r"(a[2]), "r"(a[3]), "r"(b0), "r"(b1));
}

__device__ __forceinline__ void ldsm4(uint32_t& r0, uint32_t& r1, uint32_t& r2, uint32_t& r3,
                                      uint32_t addr) {
    asm volatile("ldmatrix.sync.aligned.m8n8.x4.shared.b16 {%0,%1,%2,%3}, [%4];"
                 : "=r"(r0), "=r"(r1), "=r"(r2), "=r"(r3) : "r"(addr));
}

__device__ __forceinline__ void cpasync16(uint32_t smem_dst, const void* gsrc, int bytes) {
    asm volatile("cp.async.ca.shared.global [%0], [%1], 16, %2;"
                 :: "r"(smem_dst), "l"(gsrc), "r"(bytes));
}

__device__ __forceinline__ uint4 cvt4(float4 v) {
    return make_uint4(f2tf32(v.x), f2tf32(v.y), f2tf32(v.z), f2tf32(v.w));
}

// ---------------- transpose-convert packing: src [K][N] fp32 -> dst [N][K] tf32 ----------------
struct TJob { const float* src; uint32_t* dst; int K; int N; float scale; };
struct TJobs { TJob j[26]; };

__global__ void tpack_kernel(TJobs jobs, int njobs) {
    const int job = blockIdx.z;
    if (job >= njobs) return;
    const TJob jb = jobs.j[job];
    const int nt = blockIdx.x << 5, kt = blockIdx.y << 5;
    if (nt >= jb.N || kt >= jb.K) return;
    __shared__ float tile[32][33];
    const int tx = threadIdx.x & 31, ty = threadIdx.x >> 5;
    #pragma unroll
    for (int i = 0; i < 4; i++) {
        int k = kt + ty + i * 8;
        tile[ty + i * 8][tx] = jb.src[(size_t)k * jb.N + nt + tx];
    }
    __syncthreads();
    #pragma unroll
    for (int i = 0; i < 4; i++) {
        int n = nt + ty + i * 8;
        jb.dst[(size_t)n * jb.K + kt + tx] = f2tf32(tile[tx][ty + i * 8] * jb.scale);
    }
}

// ---------------- plain conversion (x / y inputs) ----------------
struct ConvJob { const float4* src; uint4* dst; int n4; };
struct ConvJobs { ConvJob j[2]; };

__global__ void conv_multi_kernel(ConvJobs jobs, int njobs) {
    int seg = blockIdx.y;
    if (seg >= njobs) return;
    ConvJob jb = jobs.j[seg];
    for (int i = blockIdx.x * blockDim.x + threadIdx.x; i < jb.n4; i += gridDim.x * blockDim.x) {
        jb.dst[i] = cvt4(jb.src[i]);
    }
}

// ================= 2-stage cp.async tf32 GEMM (ldmatrix A+B; V-transpose epilogue) =================
// C = A(MxK) @ B^T with B stored [N][K].  BM=BN=128, BK=32, 256 thr.
// vmode: 0 none; 1 enc-QKV (V = cols >=1024 -> vt); 2 cross-KV (V = 512-blocks with bit9 set).
// V tiles are written d-major to vt[(row)*1024 + token] via in-smem transpose; M must be 8192.
#define GA_STRIDE 36
#define GA_STAGE  (128 * GA_STRIDE)
#define GB_STAGE  (128 * GA_STRIDE)
#define GEMM_SMEM ((2 * GA_STAGE + 2 * GB_STAGE) * 4)

template<int RELU, int TF32OUT>
__global__ __launch_bounds__(256)
void mma_gemm(const uint32_t* __restrict__ A, const uint32_t* __restrict__ B,
              const float* __restrict__ bias, void* __restrict__ Cv,
              int M, int N, int K, int vmode, uint32_t* __restrict__ vt)
{
    extern __shared__ uint32_t gsm[];
    uint32_t* Asf = gsm;
    uint32_t* Bsf = gsm + 2 * GA_STAGE;

    const int tid  = threadIdx.x;
    const int wid  = tid >> 5, lane = tid & 31;
    const int wm   = wid & 1, wn = wid >> 1;
    const int g    = lane >> 2, tig = lane & 3;
    const int m0   = blockIdx.y * 128, n0 = blockIdx.x * 128;

    const int lt = lane >> 3, lr = lane & 7;
    const int a_row = lr + ((lt & 1) << 3);
    const int a_col = (lt >> 1) << 2;
    const int b_row = lr + ((lt >> 1) << 3);
    const int b_col = (lt & 1) << 2;

    const uint32_t aBase = (uint32_t)__cvta_generic_to_shared(Asf);
    const uint32_t bBase = (uint32_t)__cvta_generic_to_shared(Bsf);

    float acc[4][4][4];
    #pragma unroll
    for (int i = 0; i < 4; i++)
        #pragma unroll
        for (int j = 0; j < 4; j++)
            #pragma unroll
            for (int c = 0; c < 4; c++) acc[i][j][c] = 0.f;

    auto issue = [&](int s, int k0) {
        #pragma unroll
        for (int i = 0; i < 4; i++) {
            int idx = tid + (i << 8);
            int r = idx >> 3, kk4 = (idx & 7) << 2;
            int m = m0 + r;
            const uint32_t* src = A + (size_t)(m < M ? m : 0) * K + k0 + kk4;
            cpasync16(aBase + (s * GA_STAGE + r * GA_STRIDE + kk4) * 4, src, (m < M) ? 16 : 0);
        }
        #pragma unroll
        for (int i = 0; i < 4; i++) {
            int idx = tid + (i << 8);
            int r = idx >> 3, kk4 = (idx & 7) << 2;
            const uint32_t* src = B + (size_t)(n0 + r) * K + k0 + kk4;
            cpasync16(bBase + (s * GB_STAGE + r * GA_STRIDE + kk4) * 4, src, 16);
        }
        asm volatile("cp.async.commit_group;");
    };

    const int nk = K >> 5;
    issue(0, 0);

    for (int kt = 0; kt < nk; kt++) {
        const int s = kt & 1;
        if (kt + 1 < nk) {
            issue(s ^ 1, (kt + 1) << 5);
            asm volatile("cp.async.wait_group 1;");
        } else {
            asm volatile("cp.async.wait_group 0;");
        }
        __syncthreads();

        const uint32_t aLane = aBase +
            (s * GA_STAGE + (wm * 64 + a_row) * GA_STRIDE + a_col) * 4;
        const uint32_t bLane = bBase +
            (s * GB_STAGE + (wn * 32 + b_row) * GA_STRIDE + b_col) * 4;
        #pragma unroll
        for (int ks = 0; ks < 32; ks += 8) {
            uint32_t af[4][4];
            #pragma unroll
            for (int mi = 0; mi < 4; mi++)
                ldsm4(af[mi][0], af[mi][1], af[mi][2], af[mi][3],
                      aLane + (mi * 16 * GA_STRIDE + ks) * 4);
            uint32_t bf[4][2];
            ldsm4(bf[0][0], bf[0][1], bf[1][0], bf[1][1], bLane + ks * 4);
            ldsm4(bf[2][0], bf[2][1], bf[3][0], bf[3][1],
                  bLane + (16 * GA_STRIDE + ks) * 4);
            #pragma unroll
            for (int mi = 0; mi < 4; mi++)
                #pragma unroll
                for (int ni = 0; ni < 4; ni++)
                    mma8(acc[mi][ni], af[mi], bf[ni][0], bf[ni][1]);
        }
        __syncthreads();
    }

    // ---- epilogue ----
    bool vtile = false;
    int vrow0 = 0;
    if (TF32OUT && vmode) {
        if (vmode == 1 && n0 >= 1024) {
            vtile = true;
            vrow0 = (m0 >> 10) * 512 + (n0 - 1024);
        } else if (vmode == 2 && (n0 & 512)) {
            vtile = true;
            vrow0 = (n0 >> 10) * 4096 + (m0 >> 10) * 512 + ((n0 & 1023) - 512);
        }
    }

    if (!vtile) {
        #pragma unroll
        for (int mi = 0; mi < 4; mi++) {
            int mb = m0 + wm * 64 + mi * 16;
            #pragma unroll
            for (int ni = 0; ni < 4; ni++) {
                int nb = n0 + wn * 32 + ni * 8 + 2 * tig;
                #pragma unroll
                for (int half = 0; half < 2; half++) {
                    int m = mb + g + half * 8;
                    if (m < M) {
                        float v0 = acc[mi][ni][half * 2    ];
                        float v1 = acc[mi][ni][half * 2 + 1];
                        if (bias) { v0 += bias[nb]; v1 += bias[nb + 1]; }
                        if (RELU) { v0 = fmaxf(v0, 0.f); v1 = fmaxf(v1, 0.f); }
                        if (TF32OUT) {
                            *(uint2*)((uint32_t*)Cv + (size_t)m * N + nb) =
                                make_uint2(f2tf32(v0), f2tf32(v1));
                        } else {
                            *(float2*)((float*)Cv + (size_t)m * N + nb) = make_float2(v0, v1);
                        }
                    }
                }
            }
        }
    } else {
        // V tile: transpose through smem, write d-major (coalesced along tokens)
        uint32_t* st = gsm;   // 128 x 132 (<= GEMM smem)
        #pragma unroll
        for (int mi = 0; mi < 4; mi++) {
            int mloc = wm * 64 + mi * 16 + g;
            #pragma unroll
            for (int ni = 0; ni < 4; ni++) {
                int nloc = wn * 32 + ni * 8 + 2 * tig;
                st[(nloc    ) * 132 + mloc    ] = f2tf32(acc[mi][ni][0]);
                st[(nloc + 1) * 132 + mloc    ] = f2tf32(acc[mi][ni][1]);
                st[(nloc    ) * 132 + mloc + 8] = f2tf32(acc[mi][ni][2]);
                st[(nloc + 1) * 132 + mloc + 8] = f2tf32(acc[mi][ni][3]);
            }
        }
        __syncthreads();
        const int tok0 = m0 & 1023;
        #pragma unroll
        for (int it = 0; it < 16; it++) {
            int idx = tid + (it << 8);
            int r = idx >> 5, ch = (idx & 31) << 2;
            uint4 v = *(uint4*)&st[r * 132 + ch];
            *(uint4*)(vt + (size_t)(vrow0 + r) * 1024 + tok0 + ch) = v;
        }
    }
}

// ================= fused flash attention (non-causal, exact; ldmatrix Q/K/V) =================
// Q [token][ldq], K [token][ldkv] (both token-major), V d-major [bh][64][Tk].
#define FQ_STRIDE 68
#define FKV_STAGE (64 * FQ_STRIDE)
#define FLASH_SMEM ((128 * FQ_STRIDE + 4 * FKV_STAGE) * 4)

__global__ __launch_bounds__(256, 2)
void flash_attn(const uint32_t* __restrict__ Qg, int ldq,
                const uint32_t* __restrict__ Kg, int ldkv,
                const uint32_t* __restrict__ Vt,
                float* __restrict__ Og, int Tq, int Tk)
{
    extern __shared__ uint32_t fsm[];
    uint32_t* Qs   = fsm;
    uint32_t* Kraw = fsm + 128 * FQ_STRIDE;
    uint32_t* Vraw = Kraw + 2 * FKV_STAGE;   // d-major tiles [64 d][68]

    const int bh = blockIdx.y;
    const int b = bh >> 3, h = bh & 7;
    const int q0 = blockIdx.x * 128;
    const int tid = threadIdx.x;
    const int wid = tid >> 5, lane = tid & 31;
    const int g = lane >> 2, tig = lane & 3;
    const int mr = wid * 16;

    const int lt = lane >> 3, lr = lane & 7;
    const int a_row = lr + ((lt & 1) << 3);
    const int a_col = (lt >> 1) << 2;
    const int k_row = lr + ((lt >> 1) << 3);
    const int k_col = (lt & 1) << 2;

    const uint32_t* qp = Qg + (size_t)b * Tq * ldq + h * DHEAD;
    const uint32_t* kp = Kg + (size_t)b * Tk * ldkv + h * DHEAD;
    const uint32_t* vp = Vt + (size_t)bh * 64 * Tk;

    const uint32_t qBase = (uint32_t)__cvta_generic_to_shared(Qs);
    const uint32_t kBase = (uint32_t)__cvta_generic_to_shared(Kraw);
    const uint32_t vBase = (uint32_t)__cvta_generic_to_shared(Vraw);

    auto issueKV = [&](int s, int kt) {
        #pragma unroll
        for (int i = 0; i < 4; i++) {
            int idx = tid + (i << 8);
            int r = idx >> 4, d4 = (idx & 15) << 2;
            cpasync16(kBase + (s * FKV_STAGE + r * FQ_STRIDE + d4) * 4,
                      kp + (size_t)(kt + r) * ldkv + d4, 16);
            // V: row r = d, cols = tokens
            cpasync16(vBase + (s * FKV_STAGE + r * FQ_STRIDE + d4) * 4,
                      vp + (size_t)r * Tk + kt + d4, 16);
        }
        asm volatile("cp.async.commit_group;");
    };

    issueKV(0, 0);
    #pragma unroll
    for (int i = 0; i < 8; i++) {
        int idx = tid + (i << 8);
        int r = idx >> 4, d4 = (idx & 15) << 2;
        int q = q0 + r;
        cpasync16(qBase + (r * FQ_STRIDE + d4) * 4,
                  qp + (size_t)(q < Tq ? q : 0) * ldq + d4, (q < Tq) ? 16 : 0);
    }
    asm volatile("cp.async.commit_group;");

    float o[8][4];
    #pragma unroll
    for (int ni = 0; ni < 8; ni++)
        #pragma unroll
        for (int c = 0; c < 4; c++) o[ni][c] = 0.f;
    float m0 = -1e30f, m1 = -1e30f, l0 = 0.f, l1 = 0.f;

    const int srcA = (lane & ~3) | (tig >> 1);
    const int srcB = srcA + 2;
    const bool odd = tig & 1;

    const uint32_t qLane = qBase + ((mr + a_row) * FQ_STRIDE + a_col) * 4;

    const int nt = Tk >> 6;
    for (int kt = 0; kt < nt; kt++) {
        const int s = kt & 1;
        if (kt + 1 < nt) {
            issueKV(s ^ 1, (kt + 1) << 6);
            asm volatile("cp.async.wait_group 1;");
        } else {
            asm volatile("cp.async.wait_group 0;");
        }
        __syncthreads();

        const uint32_t kLane = kBase + (s * FKV_STAGE + k_row * FQ_STRIDE + k_col) * 4;
        const uint32_t vLane = vBase + (s * FKV_STAGE + k_row * FQ_STRIDE + k_col) * 4;

        // ---- S = Q @ K^T ----
        float sfr[8][4];
        #pragma unroll
        for (int ni = 0; ni < 8; ni++)
            #pragma unroll
            for (int c = 0; c < 4; c++) sfr[ni][c] = 0.f;
        #pragma unroll
        for (int ks = 0; ks < 64; ks += 8) {
            uint32_t af[4];
            ldsm4(af[0], af[1], af[2], af[3], qLane + ks * 4);
            #pragma unroll
            for (int np = 0; np < 8; np += 2) {
                uint32_t b00, b01, b10, b11;
                ldsm4(b00, b01, b10, b11, kLane + (np * 8 * FQ_STRIDE + ks) * 4);
                mma8(sfr[np    ], af, b00, b01);
                mma8(sfr[np + 1], af, b10, b11);
            }
        }

        // ---- online softmax; P stays in registers ----
        float tmax0 = -1e30f, tmax1 = -1e30f;
        #pragma unroll
        for (int ni = 0; ni < 8; ni++) {
            tmax0 = fmaxf(tmax0, fmaxf(sfr[ni][0], sfr[ni][1]));
            tmax1 = fmaxf(tmax1, fmaxf(sfr[ni][2], sfr[ni][3]));
        }
        #pragma unroll
        for (int off = 1; off <= 2; off <<= 1) {
            tmax0 = fmaxf(tmax0, __shfl_xor_sync(0xffffffffu, tmax0, off));
            tmax1 = fmaxf(tmax1, __shfl_xor_sync(0xffffffffu, tmax1, off));
        }
        const float mn0 = fmaxf(m0, tmax0), mn1 = fmaxf(m1, tmax1);
        const float a0 = __expf(m0 - mn0), a1 = __expf(m1 - mn1);
        float rs0 = 0.f, rs1 = 0.f;
        uint32_t pf[8][4];
        #pragma unroll
        for (int ni = 0; ni < 8; ni++) {
            float p0 = __expf(sfr[ni][0] - mn0);
            float p1 = __expf(sfr[ni][1] - mn0);
            float p2 = __expf(sfr[ni][2] - mn1);
            float p3 = __expf(sfr[ni][3] - mn1);
            rs0 += p0 + p1; rs1 += p2 + p3;
            pf[ni][0] = f2tf32(p0); pf[ni][1] = f2tf32(p1);
            pf[ni][2] = f2tf32(p2); pf[ni][3] = f2tf32(p3);
        }
        #pragma unroll
        for (int off = 1; off <= 2; off <<= 1) {
            rs0 += __shfl_xor_sync(0xffffffffu, rs0, off);
            rs1 += __shfl_xor_sync(0xffffffffu, rs1, off);
        }
        l0 = l0 * a0 + rs0; l1 = l1 * a1 + rs1;
        m0 = mn0; m1 = mn1;
        #pragma unroll
        for (int ni = 0; ni < 8; ni++) {
            o[ni][0] *= a0; o[ni][1] *= a0;
            o[ni][2] *= a1; o[ni][3] *= a1;
        }

        // ---- O += P @ V : P c-frag -> a-frag via quad shuffles; V B-frags via ldmatrix ----
        #pragma unroll
        for (int j = 0; j < 8; j++) {
            uint32_t r0a = __shfl_sync(0xffffffffu, pf[j][0], srcA);
            uint32_t r1a = __shfl_sync(0xffffffffu, pf[j][1], srcA);
            uint32_t r2a = __shfl_sync(0xffffffffu, pf[j][2], srcA);
            uint32_t r3a = __shfl_sync(0xffffffffu, pf[j][3], srcA);
            uint32_t r0b = __shfl_sync(0xffffffffu, pf[j][0], srcB);
            uint32_t r1b = __shfl_sync(0xffffffffu, pf[j][1], srcB);
            uint32_t r2b = __shfl_sync(0xffffffffu, pf[j][2], srcB);
            uint32_t r3b = __shfl_sync(0xffffffffu, pf[j][3], srcB);
            uint32_t af[4];
            af[0] = odd ? r1a : r0a;
            af[1] = odd ? r3a : r2a;
            af[2] = odd ? r1b : r0b;
            af[3] = odd ? r3b : r2b;
            const int ks = j * 8;
            #pragma unroll
            for (int np = 0; np < 8; np += 2) {
                uint32_t b00, b01, b10, b11;
                ldsm4(b00, b01, b10, b11, vLane + (np * 8 * FQ_STRIDE + ks) * 4);
                mma8(o[np    ], af, b00, b01);
                mma8(o[np + 1], af, b10, b11);
            }
        }
        __syncthreads();
    }

    const float i0 = 1.f / l0, i1 = 1.f / l1;
    #pragma unroll
    for (int ni = 0; ni < 8; ni++) {
        int col = h * DHEAD + ni * 8 + 2 * tig;
        int r0 = q0 + mr + g, r1 = r0 + 8;
        if (r0 < Tq)
            *(float2*)(Og + (size_t)(b * Tq + r0) * DMODEL + col) =
                make_float2(o[ni][0] * i0, o[ni][1] * i0);
        if (r1 < Tq)
            *(float2*)(Og + (size_t)(b * Tq + r1) * DMODEL + col) =
                make_float2(o[ni][2] * i1, o[ni][3] * i1);
    }
}

// ================= fused decoder self-attention (exact fp32) =================
#define DS_STRIDE 68
#define DS_SSTRIDE 104
#define DEC_SMEM ((3 * T_DEC * DS_STRIDE + T_DEC * DS_SSTRIDE) * 4)

__global__ __launch_bounds__(256)
void dec_self_attn(const float* __restrict__ QKV, float* __restrict__ Og)
{
    extern __shared__ float dsm[];
    float* Qd = dsm;
    float* Kd = Qd + T_DEC * DS_STRIDE;
    float* Vd = Kd + T_DEC * DS_STRIDE;
    float* Sd = Vd + T_DEC * DS_STRIDE;

    const int bh = blockIdx.x;
    const int b = bh >> 3, h = bh & 7;
    const int tid = threadIdx.x;
    const int wid = tid >> 5, lane = tid & 31;

    const float* qp = QKV + (size_t)b * T_DEC * NQKV + h * DHEAD;
    const float* kp = qp + 512;
    const float* vp = qp + 1024;

    for (int idx = tid; idx < T_DEC * 16; idx += 256) {
        int r = idx >> 4, d4 = (idx & 15) << 2;
        *(float4*)&Qd[r * DS_STRIDE + d4] = *(const float4*)(qp + (size_t)r * NQKV + d4);
        *(float4*)&Kd[r * DS_STRIDE + d4] = *(const float4*)(kp + (size_t)r * NQKV + d4);
        *(float4*)&Vd[r * DS_STRIDE + d4] = *(const float4*)(vp + (size_t)r * NQKV + d4);
    }
    __syncthreads();

    for (int e = tid; e < T_DEC * T_DEC; e += 256) {
        int q = e / T_DEC, kk = e - q * T_DEC;
        const float* qr = &Qd[q * DS_STRIDE];
        const float* kr = &Kd[kk * DS_STRIDE];
        float acc = 0.f;
        #pragma unroll
        for (int d = 0; d < 64; d++) acc += qr[d] * kr[d];
        Sd[q * DS_SSTRIDE + kk] = acc * 0.125f;
    }
    __syncthreads();

    for (int q = wid; q < T_DEC; q += 8) {
        float* row = &Sd[q * DS_SSTRIDE];
        float r0 = (lane      < T_DEC) ? row[lane]      : -1e30f;
        float r1 = (lane + 32 < T_DEC) ? row[lane + 32] : -1e30f;
        float r2 = (lane + 64 < T_DEC) ? row[lane + 64] : -1e30f;
        float r3 = (lane + 96 < T_DEC) ? row[lane + 96] : -1e30f;
        float m = fmaxf(fmaxf(r0, r1), fmaxf(r2, r3));
        #pragma unroll
        for (int off = 16; off; off >>= 1) m = fmaxf(m, __shfl_xor_sync(0xffffffffu, m, off));
        float e0 = expf(r0 - m), e1 = expf(r1 - m), e2 = expf(r2 - m), e3 = expf(r3 - m);
        if (lane      >= T_DEC) e0 = 0.f;
        if (lane + 32 >= T_DEC) e1 = 0.f;
        if (lane + 64 >= T_DEC) e2 = 0.f;
        if (lane + 96 >= T_DEC) e3 = 0.f;
        float s = e0 + e1 + e2 + e3;
        #pragma unroll
        for (int off = 16; off; off >>= 1) s += __shfl_xor_sync(0xffffffffu, s, off);
        const float inv = 1.f / s;
        if (lane      < T_DEC) row[lane]      = (lane      > q) ? -1e10f : e0 * inv;
        if (lane + 32 < T_DEC) row[lane + 32] = (lane + 32 > q) ? -1e10f : e1 * inv;
        if (lane + 64 < T_DEC) row[lane + 64] = (lane + 64 > q) ? -1e10f : e2 * inv;
        if (lane + 96 < T_DEC) row[lane + 96] = (lane + 96 > q) ? -1e10f : e3 * inv;
    }
    __syncthreads();

    for (int e = tid; e < T_DEC * 64; e += 256) {
        int q = e >> 6, d = e & 63;
        const float* pr = &Sd[q * DS_SSTRIDE];
        float acc = 0.f;
        #pragma unroll 4
        for (int kk = 0; kk < T_DEC; kk++) acc += pr[kk] * Vd[kk * DS_STRIDE + d];
        Og[(size_t)(b * T_DEC + q) * DMODEL + h * DHEAD + d] = acc;
    }
}

// ---------------- fused residual + LayerNorm (fp32 out + optional tf32 out) ----------------
__global__ void ln_res_kernel(const float* __restrict__ A, const float* __restrict__ Bv,
                              const float* __restrict__ g, const float* __restrict__ be,
                              float* __restrict__ O, uint32_t* __restrict__ Otf) {
    const int row = blockIdx.x;
    const float* a = A + (size_t)row * DMODEL;
    const float* b = Bv + (size_t)row * DMODEL;
    __shared__ float red[256];
    const int tid = threadIdx.x;

    float v0 = a[tid] + b[tid];
    float v1 = a[tid + 256] + b[tid + 256];

    red[tid] = v0 + v1; __syncthreads();
    for (int s = 128; s > 0; s >>= 1) { if (tid < s) red[tid] += red[tid + s]; __syncthreads(); }
    const float mean = red[0] * (1.f / DMODEL); __syncthreads();

    float d0 = v0 - mean, d1 = v1 - mean;
    red[tid] = d0 * d0 + d1 * d1; __syncthreads();
    for (int s = 128; s > 0; s >>= 1) { if (tid < s) red[tid] += red[tid + s]; __syncthreads(); }
    const float inv = rsqrtf(red[0] * (1.f / DMODEL) + 1e-5f);

    const float o0 = d0 * inv * g[tid]       + be[tid];
    const float o1 = d1 * inv * g[tid + 256] + be[tid + 256];
    O[(size_t)row * DMODEL + tid]       = o0;
    O[(size_t)row * DMODEL + tid + 256] = o1;
    if (Otf) {
        Otf[(size_t)row * DMODEL + tid]       = f2tf32(o0);
        Otf[(size_t)row * DMODEL + tid + 256] = f2tf32(o1);
    }
}

// ---------------- host orchestration ----------------
static inline void mgemm(const uint32_t* A, const uint32_t* B, const float* bias, void* C,
                         int M, int N, int K, int relu, int tf32out,
                         int vmode = 0, uint32_t* vt = nullptr) {
    dim3 grid(N / 128, (M + 127) / 128);
    if (relu && tf32out)
        mma_gemm<1, 1><<<grid, 256, GEMM_SMEM>>>(A, B, bias, C, M, N, K, vmode, vt);
    else if (tf32out)
        mma_gemm<0, 1><<<grid, 256, GEMM_SMEM>>>(A, B, bias, C, M, N, K, vmode, vt);
    else
        mma_gemm<0, 0><<<grid, 256, GEMM_SMEM>>>(A, B, bias, C, M, N, K, vmode, vt);
}

template <typename T>
static inline void* symv(T& s) {
    void* p = nullptr;
    cudaGetSymbolAddress(&p, s);
    return p;
}

extern "C" void kernel_launch(void* const* d_in, const int* in_sizes, int n_in,
                              void* d_out, int out_size) {
    (void)in_sizes; (void)n_in; (void)out_size;

    cudaFuncSetAttribute((const void*)mma_gemm<0,0>, cudaFuncAttributeMaxDynamicSharedMemorySize, GEMM_SMEM);
    cudaFuncSetAttribute((const void*)mma_gemm<0,1>, cudaFuncAttributeMaxDynamicSharedMemorySize, GEMM_SMEM);
    cudaFuncSetAttribute((const void*)mma_gemm<1,1>, cudaFuncAttributeMaxDynamicSharedMemorySize, GEMM_SMEM);
    cudaFuncSetAttribute((const void*)flash_attn,    cudaFuncAttributeMaxDynamicSharedMemorySize, FLASH_SMEM);
    cudaFuncSetAttribute((const void*)dec_self_attn, cudaFuncAttributeMaxDynamicSharedMemorySize, DEC_SMEM);

    const float* x_in      = (const float*)d_in[0];
    const float* y_in      = (const float*)d_in[1];
    const float* enc_Wq    = (const float*)d_in[2];
    const float* enc_Wk    = (const float*)d_in[3];
    const float* enc_Wv    = (const float*)d_in[4];
    const float* enc_ff_w1 = (const float*)d_in[5];
    const float* enc_ff_b1 = (const float*)d_in[6];
    const float* enc_ff_w2 = (const float*)d_in[7];
    const float* enc_ff_b2 = (const float*)d_in[8];
    const float* enc_ln1_g = (const float*)d_in[9];
    const float* enc_ln1_b = (const float*)d_in[10];
    const float* enc_ln2_g = (const float*)d_in[11];
    const float* enc_ln2_b = (const float*)d_in[12];
    const float* dec_Wq1   = (const float*)d_in[13];
    const float* dec_Wk1   = (const float*)d_in[14];
    const float* dec_Wv1   = (const float*)d_in[15];
    const float* dec_Wq2   = (const float*)d_in[16];
    const float* dec_Wk2   = (const float*)d_in[17];
    const float* dec_Wv2   = (const float*)d_in[18];
    const float* dec_ff_w1 = (const float*)d_in[19];
    const float* dec_ff_b1 = (const float*)d_in[20];
    const float* dec_ff_w2 = (const float*)d_in[21];
    const float* dec_ff_b2 = (const float*)d_in[22];
    const float* dec_ln1_g = (const float*)d_in[23];
    const float* dec_ln1_b = (const float*)d_in[24];
    const float* dec_ln2_g = (const float*)d_in[25];
    const float* dec_ln2_b = (const float*)d_in[26];
    const float* dec_ln3_g = (const float*)d_in[27];
    const float* dec_ln3_b = (const float*)d_in[28];

    uint32_t* eqkvW = (uint32_t*)symv(w_eqkv);
    uint32_t* ew1   = (uint32_t*)symv(w_ew1);
    uint32_t* ew2   = (uint32_t*)symv(w_ew2);
    uint32_t* dqkv1 = (uint32_t*)symv(w_dqkv1);
    uint32_t* dq2   = (uint32_t*)symv(w_dq2);
    uint32_t* dkv2  = (uint32_t*)symv(w_dkv2);
    uint32_t* dw1   = (uint32_t*)symv(w_dw1);
    uint32_t* dw2   = (uint32_t*)symv(w_dw2);

    uint32_t* qkv  = (uint32_t*)symv(g_qkv);
    float*    qkvd = (float*)symv(g_qkvd);
    uint32_t* kv   = (uint32_t*)symv(g_kv);
    uint32_t* vtE  = (uint32_t*)symv(g_vtE);
    uint32_t* vtD  = (uint32_t*)symv(g_vtD);
    uint32_t* qx   = (uint32_t*)symv(g_qx);
    uint32_t* h    = (uint32_t*)symv(g_h);
    uint32_t* xtf  = (uint32_t*)symv(g_xtf);
    uint32_t* x1tf = (uint32_t*)symv(g_x1tf);
    uint32_t* ytf  = (uint32_t*)symv(g_ytf);
    uint32_t* y1tf = (uint32_t*)symv(g_y1tf);
    uint32_t* y2tf = (uint32_t*)symv(g_y2tf);
    float* att = (float*)symv(g_att);
    float* x1  = (float*)symv(g_x1);
    float* gx  = (float*)symv(g_x);
    float* y1  = (float*)symv(g_y1);
    float* y2  = (float*)symv(g_y2);
    float* gy  = (float*)symv(g_y);

    const long long WO = DMODEL * DMODEL;
    const long long FO1 = DFF * DMODEL;
    const long long LQKV = (long long)NQKV * DMODEL;

    // ---- transpose-convert ALL weights [K][N] -> [N][K] tf32 ----
    {
        TJobs tj;
        int n = 0;
        for (int i = 0; i < 2; i++) {
            tj.j[n++] = { enc_Wq + i * WO, eqkvW + i * LQKV +      0LL * DMODEL, DMODEL, DMODEL, 0.125f };
            tj.j[n++] = { enc_Wk + i * WO, eqkvW + i * LQKV +    512LL * DMODEL, DMODEL, DMODEL, 1.f };
            tj.j[n++] = { enc_Wv + i * WO, eqkvW + i * LQKV +   1024LL * DMODEL, DMODEL, DMODEL, 1.f };
            tj.j[n++] = { dec_Wq1 + i * WO, dqkv1 + i * LQKV +     0LL * DMODEL, DMODEL, DMODEL, 1.f };
            tj.j[n++] = { dec_Wk1 + i * WO, dqkv1 + i * LQKV +   512LL * DMODEL, DMODEL, DMODEL, 1.f };
            tj.j[n++] = { dec_Wv1 + i * WO, dqkv1 + i * LQKV +  1024LL * DMODEL, DMODEL, DMODEL, 1.f };
            tj.j[n++] = { dec_Wq2 + i * WO, dq2 + i * WO, DMODEL, DMODEL, 0.125f };
            tj.j[n++] = { dec_Wk2 + i * WO, dkv2 + (i * 1024LL      ) * DMODEL, DMODEL, DMODEL, 1.f };
            tj.j[n++] = { dec_Wv2 + i * WO, dkv2 + (i * 1024LL + 512) * DMODEL, DMODEL, DMODEL, 1.f };
            tj.j[n++] = { enc_ff_w1 + i * FO1, ew1 + i * FO1, DMODEL, DFF, 1.f };
            tj.j[n++] = { enc_ff_w2 + i * FO1, ew2 + i * FO1, DFF, DMODEL, 1.f };
            tj.j[n++] = { dec_ff_w1 + i * FO1, dw1 + i * FO1, DMODEL, DFF, 1.f };
            tj.j[n++] = { dec_ff_w2 + i * FO1, dw2 + i * FO1, DFF, DMODEL, 1.f };
        }
        tpack_kernel<<<dim3(64, 64, n), 256>>>(tj, n);
    }
    {
        ConvJobs jobs;
        jobs.j[0] = { (const float4*)x_in, (uint4*)xtf, (M_ENC * DMODEL) / 4 };
        jobs.j[1] = { (const float4*)y_in, (uint4*)ytf, (M_DEC * DMODEL) / 4 };
        conv_multi_kernel<<<dim3(160, 2), 256>>>(jobs, 2);
    }

    // -------- encoder --------
    const float* xc = x_in;
    for (int i = 0; i < 2; i++) {
        mgemm(xtf, eqkvW + (size_t)i * LQKV, nullptr, qkv, M_ENC, NQKV, DMODEL, 0, 1, 1, vtE);
        flash_attn<<<dim3(T_ENC / 128, BHT), 256, FLASH_SMEM>>>(
            qkv, NQKV, qkv + 512, NQKV, vtE, att, T_ENC, T_ENC);
        ln_res_kernel<<<M_ENC, 256>>>(xc, att, enc_ln1_g + i * DMODEL, enc_ln1_b + i * DMODEL, x1, x1tf);
        mgemm(x1tf, ew1 + (size_t)i * FO1, enc_ff_b1 + i * DFF, h, M_ENC, DFF, DMODEL, 1, 1);
        mgemm(h, ew2 + (size_t)i * FO1, enc_ff_b2 + i * DMODEL, att, M_ENC, DMODEL, DFF, 0, 0);
        ln_res_kernel<<<M_ENC, 256>>>(x1, att, enc_ln2_g + i * DMODEL, enc_ln2_b + i * DMODEL, gx, xtf);
        xc = gx;
    }

    // -------- decoder cross K/V for BOTH layers (one full-wave GEMM; V -> vtD d-major) --------
    mgemm(xtf, dkv2, nullptr, kv, M_ENC, NKV2, DMODEL, 0, 1, 2, vtD);

    // -------- decoder --------
    const float* yc = y_in;
    for (int i = 0; i < 2; i++) {
        // masked self-attention: exact fp32 fused path (post-softmax -1e10 fill)
        mgemm(ytf, dqkv1 + (size_t)i * LQKV, nullptr, qkvd, M_DEC, NQKV, DMODEL, 0, 0);
        dec_self_attn<<<BHT, 256, DEC_SMEM>>>(qkvd, att);
        ln_res_kernel<<<M_DEC, 256>>>(yc, att, dec_ln1_g + i * DMODEL, dec_ln1_b + i * DMODEL, y1, y1tf);

        // cross-attention (non-causal -> flash; K/V precomputed, V d-major)
        mgemm(y1tf, dq2 + i * WO, nullptr, qx, M_DEC, DMODEL, DMODEL, 0, 1);
        flash_attn<<<dim3(1, BHT), 256, FLASH_SMEM>>>(
            qx, DMODEL, kv + (size_t)i * 1024, NKV2,
            vtD + (size_t)i * BHT * DHEAD * T_ENC, att, T_DEC, T_ENC);
        ln_res_kernel<<<M_DEC, 256>>>(y1, att, dec_ln2_g + i * DMODEL, dec_ln2_b + i * DMODEL, y2, y2tf);

        // feed-forward
        mgemm(y2tf, dw1 + (size_t)i * FO1, dec_ff_b1 + i * DFF, h, M_DEC, DFF, DMODEL, 1, 1);
        mgemm(h, dw2 + (size_t)i * FO1, dec_ff_b2 + i * DMODEL, att, M_DEC, DMODEL, DFF, 0, 0);
        float* outp = (i == 1) ? (float*)d_out : gy;
        ln_res_kernel<<<M_DEC, 256>>>(y2, att, dec_ln3_g + i * DMODEL, dec_ln3_b + i * DMODEL,
                                      outp, (i == 1) ? nullptr : ytf);
        yc = gy;
    }
}